// round 8
// baseline (speedup 1.0000x reference)
#include <cuda_runtime.h>

typedef unsigned long long u64;

// ---------------- scratch (device globals; no allocation) ----------------
__device__ float g_pre[16*64*1024];     // conv1 out, then h (in-place)
__device__ float2 g_bstats[64*16];      // per (oc,b) partial {sum, sumsq}
__device__ float g_S[16*64*9];          // 9 shifted window sums per (b, in-ch)
__device__ float g_Q[16*4*1024*10];
__device__ float g_KV[16*4*1024*20];    // interleaved K(10) | V(10) per key
__device__ float g_pA[4*16*4*1024*10];  // unnormalized attn partials (4 key-chunks)
__device__ float g_pl[4*16*4*1024];     // softmax denominators (partial)

__device__ __forceinline__ float wred(float v) {
  #pragma unroll
  for (int o = 16; o; o >>= 1) v += __shfl_down_sync(0xffffffffu, v, o);
  return v;
}

// ---- packed f32x2 helpers (sm_100+) ----
__device__ __forceinline__ u64 ffma2(u64 a, u64 b, u64 c) {
  u64 d; asm("fma.rn.f32x2 %0, %1, %2, %3;" : "=l"(d) : "l"(a), "l"(b), "l"(c)); return d;
}
__device__ __forceinline__ u64 fmul2(u64 a, u64 b) {
  u64 d; asm("mul.rn.f32x2 %0, %1, %2;" : "=l"(d) : "l"(a), "l"(b)); return d;
}
__device__ __forceinline__ u64 pack2(float lo, float hi) {
  u64 r; asm("mov.b64 %0, {%1, %2};" : "=l"(r) : "f"(lo), "f"(hi)); return r;
}
__device__ __forceinline__ float2 unpack2(u64 v) {
  float lo, hi; asm("mov.b64 {%0, %1}, %2;" : "=f"(lo), "=f"(hi) : "l"(v));
  return make_float2(lo, hi);
}
__device__ __forceinline__ float ex2f(float x) {
  float y; asm("ex2.approx.f32 %0, %1;" : "=f"(y) : "f"(x)); return y;
}

union F4U { float4 f4; ulonglong2 u2; };
union F2U { float2 f2; u64 u; };

__device__ __forceinline__ u64 ldf2(const float* p) {
  F2U t; t.f2 = *(const float2*)p; return t.u;
}

// ---------------- K0: conv1 3x3 (3->64) SAME + per-block BN partial stats ----------------
__global__ void __launch_bounds__(256) conv1_kernel(const float* __restrict__ x,
                                                    const float* __restrict__ w,
                                                    const float* __restrict__ bias) {
  int t = threadIdx.x;
  int oc = blockIdx.x, b = blockIdx.y;
  int p0 = t * 4;
  int y = p0 >> 5, x0 = p0 & 31;
  float w_[27];
  #pragma unroll
  for (int i = 0; i < 27; i++) w_[i] = __ldg(&w[oc * 27 + i]);
  float bv = __ldg(&bias[oc]);
  float a0 = bv, a1 = bv, a2 = bv, a3 = bv;
  #pragma unroll
  for (int ic = 0; ic < 3; ic++) {
    const float* base = x + (b * 3 + ic) * 1024;
    #pragma unroll
    for (int ky = 0; ky < 3; ky++) {
      int iy = y + ky - 1;
      if (iy < 0 || iy > 31) continue;
      const float* row = base + iy * 32;
      float r[6];
      #pragma unroll
      for (int dx = 0; dx < 6; dx++) {
        int c = x0 - 1 + dx;
        r[dx] = (c >= 0 && c < 32) ? __ldg(&row[c]) : 0.f;
      }
      #pragma unroll
      for (int kx = 0; kx < 3; kx++) {
        float wv = w_[ic * 9 + ky * 3 + kx];
        a0 = fmaf(wv, r[kx],     a0);
        a1 = fmaf(wv, r[kx + 1], a1);
        a2 = fmaf(wv, r[kx + 2], a2);
        a3 = fmaf(wv, r[kx + 3], a3);
      }
    }
  }
  *(float4*)(g_pre + (b * 64 + oc) * 1024 + p0) = make_float4(a0, a1, a2, a3);

  float s  = a0 + a1 + a2 + a3;
  float sq = fmaf(a0, a0, fmaf(a1, a1, fmaf(a2, a2, a3 * a3)));
  s = wred(s); sq = wred(sq);
  __shared__ float ss[8], s2m[8];
  int warp = t >> 5, lane = t & 31;
  if (lane == 0) { ss[warp] = s; s2m[warp] = sq; }
  __syncthreads();
  if (t == 0) {
    float S = 0.f, Q = 0.f;
    #pragma unroll
    for (int i = 0; i < 8; i++) { S += ss[i]; Q += s2m[i]; }
    g_bstats[oc * 16 + b] = make_float2(S, Q);
  }
}

// ---------------- K1: BN finalize + apply + relu (in place) + 9 window sums ----------------
__global__ void bnrelu_kernel(const float* __restrict__ gamma,
                              const float* __restrict__ beta) {
  int c = blockIdx.x, b = blockIdx.y;
  int p = threadIdx.x;                  // 1024 threads
  __shared__ float scb[2];
  if (p < 16) {
    float2 v = g_bstats[c * 16 + p];
    float s = v.x, q = v.y;
    #pragma unroll
    for (int o = 8; o; o >>= 1) {
      s += __shfl_down_sync(0xffffu, s, o, 16);
      q += __shfl_down_sync(0xffffu, q, o, 16);
    }
    if (p == 0) {
      float mean = s * (1.f / 16384.f);
      float var  = q * (1.f / 16384.f) - mean * mean;
      float sc = __ldg(&gamma[c]) * rsqrtf(var + 1e-5f);
      scb[0] = sc;
      scb[1] = __ldg(&beta[c]) - mean * sc;
    }
  }
  __syncthreads();

  int y = p >> 5, xx = p & 31;
  int idx = (b * 64 + c) * 1024 + p;
  float v = fmaxf(fmaf(g_pre[idx], scb[0], scb[1]), 0.f);
  g_pre[idx] = v;

  float t = v;
  float r0  = (y == 0)  ? v : 0.f;
  float r31 = (y == 31) ? v : 0.f;
  float c0  = (xx == 0)  ? v : 0.f;
  float c31 = (xx == 31) ? v : 0.f;

  __shared__ float red[32][5];
  __shared__ float corn[4];
  if (p == 0)    corn[0] = v;
  if (p == 31)   corn[1] = v;
  if (p == 992)  corn[2] = v;
  if (p == 1023) corn[3] = v;

  t = wred(t); r0 = wred(r0); r31 = wred(r31); c0 = wred(c0); c31 = wred(c31);
  int warp = p >> 5, lane = p & 31;
  if (lane == 0) { red[warp][0]=t; red[warp][1]=r0; red[warp][2]=r31; red[warp][3]=c0; red[warp][4]=c31; }
  __syncthreads();
  if (p < 32) {
    float a0 = red[p][0], a1 = red[p][1], a2 = red[p][2], a3 = red[p][3], a4 = red[p][4];
    a0 = wred(a0); a1 = wred(a1); a2 = wred(a2); a3 = wred(a3); a4 = wred(a4);
    if (p == 0) {
      float T = a0, R0 = a1, R31 = a2, C0 = a3, C31 = a4;
      float* Sp = g_S + (b * 64 + c) * 9;
      Sp[0] = T - R31 - C31 + corn[3];
      Sp[1] = T - R31;
      Sp[2] = T - R31 - C0 + corn[2];
      Sp[3] = T - C31;
      Sp[4] = T;
      Sp[5] = T - C0;
      Sp[6] = T - R0 - C31 + corn[1];
      Sp[7] = T - R0;
      Sp[8] = T - R0 - C0 + corn[0];
    }
  }
}

// ---------------- K2: qkv 1x1 conv -> Q (scaled), KV interleaved ----------------
__global__ void __launch_bounds__(256) qkv_kernel(const float* __restrict__ w,
                                                  const float* __restrict__ bias) {
  int tid = threadIdx.x;        // 256
  int b = blockIdx.z;
  int o0 = blockIdx.y * 8;      // 15 groups of 8 output channels
  __shared__ float ws[512];
  __shared__ float bs[8];
  for (int i = tid; i < 512; i += 256) ws[i] = w[o0 * 64 + i];
  if (tid < 8) bs[tid] = bias[o0 + tid];
  __syncthreads();
  int n0 = tid * 4;
  float4 acc[8];
  #pragma unroll
  for (int u = 0; u < 8; u++) { float bv = bs[u]; acc[u] = make_float4(bv, bv, bv, bv); }
  const float* hp = g_pre + b * 64 * 1024 + n0;
  #pragma unroll 4
  for (int i = 0; i < 64; i++) {
    float4 hv = *(const float4*)(hp + i * 1024);
    #pragma unroll
    for (int u = 0; u < 8; u++) {
      float wv = ws[u * 64 + i];
      acc[u].x = fmaf(wv, hv.x, acc[u].x);
      acc[u].y = fmaf(wv, hv.y, acc[u].y);
      acc[u].z = fmaf(wv, hv.z, acc[u].z);
      acc[u].w = fmaf(wv, hv.w, acc[u].w);
    }
  }
  // Q gets dkh^-0.5 * log2(e) folded in (exp -> ex2 domain; exact)
  const float QMUL = 0.31622776601683794f * 1.4426950408889634f;
  #pragma unroll
  for (int u = 0; u < 8; u++) {
    int o = o0 + u;
    int which = o / 40;
    int r = o - which * 40;
    int head = r / 10, d = r - head * 10;
    int bh = b * 4 + head;
    if (which == 0) {
      float* pb = g_Q + (bh * 1024) * 10 + d;
      pb[(n0 + 0) * 10] = acc[u].x * QMUL;
      pb[(n0 + 1) * 10] = acc[u].y * QMUL;
      pb[(n0 + 2) * 10] = acc[u].z * QMUL;
      pb[(n0 + 3) * 10] = acc[u].w * QMUL;
    } else {
      float* pb = g_KV + (bh * 1024) * 20 + ((which == 1) ? d : 10 + d);
      pb[(n0 + 0) * 20] = acc[u].x;
      pb[(n0 + 1) * 20] = acc[u].y;
      pb[(n0 + 2) * 20] = acc[u].z;
      pb[(n0 + 3) * 20] = acc[u].w;
    }
  }
}

// ---------------- K3: attention, 2q/thread, split-K x4, rw(a,b) packed in smem ----------------
// smem: KV chunk 256*20 f32 (20480B) + RW [32][128] u64 (32768B) + Hs 630 f32 (2520B)
#define ATTN_SMEM ((5120 + 8192 + 640) * 4)

__global__ void __launch_bounds__(128, 4) attn_kernel(const float* __restrict__ krh,
                                                      const float* __restrict__ krw) {
  extern __shared__ float sm[];
  float* KVs = sm;                    // [256][20]
  u64*   RWs = (u64*)(sm + 5120);     // [xm][tid] packed {rwa, rwb}
  float* Hs  = sm + 5120 + 8192;      // key_rel_h 63*10
  int bh = blockIdx.z;
  int kc = blockIdx.y;                // key chunk 0..3 (256 keys each)
  int tid = threadIdx.x;              // 128
  int warp = tid >> 5, lane = tid & 31;

  // stage KV chunk (coalesced float4) + krh table
  {
    const float4* src = (const float4*)(g_KV + bh * 20480 + kc * 5120);
    float4* dst = (float4*)KVs;
    #pragma unroll 10
    for (int i = tid; i < 1280; i += 128) dst[i] = src[i];
    for (int i = tid; i < 630; i += 128) Hs[i] = krh[i];
  }

  int ya = blockIdx.x * 8 + warp;     // query row A (warp 0..3)
  int yb = ya + 4;                    // query row B
  int xq = lane;
  int na = ya * 32 + xq, nb = yb * 32 + xq;
  const float* qa = g_Q + (bh * 1024 + na) * 10;   // pre-scaled by dkh^-.5*log2e
  const float* qb = g_Q + (bh * 1024 + nb) * 10;
  u64 Qa01 = ldf2(qa), Qa23 = ldf2(qa + 2), Qa45 = ldf2(qa + 4),
      Qa67 = ldf2(qa + 6), Qa89 = ldf2(qa + 8);
  u64 Qb01 = ldf2(qb), Qb23 = ldf2(qb + 2), Qb45 = ldf2(qb + 4),
      Qb67 = ldf2(qb + 6), Qb89 = ldf2(qb + 8);

  // rw per query from GLOBAL krw (cached; off hot path); packed {a,b} -> smem
  #pragma unroll
  for (int xm = 0; xm < 32; xm++) {
    const float* kr = krw + (xm - xq + 31) * 10;
    u64 k01 = ldf2(kr), k23 = ldf2(kr + 2), k45 = ldf2(kr + 4),
        k67 = ldf2(kr + 6), k89 = ldf2(kr + 8);
    u64 sa = fmul2(Qa01, k01);
    sa = ffma2(Qa23, k23, sa); sa = ffma2(Qa45, k45, sa);
    sa = ffma2(Qa67, k67, sa); sa = ffma2(Qa89, k89, sa);
    u64 sb = fmul2(Qb01, k01);
    sb = ffma2(Qb23, k23, sb); sb = ffma2(Qb45, k45, sb);
    sb = ffma2(Qb67, k67, sb); sb = ffma2(Qb89, k89, sb);
    float2 fa = unpack2(sa), fb = unpack2(sb);
    RWs[xm * 128 + tid] = pack2(fa.x + fa.y, fb.x + fb.y);
  }
  __syncthreads();

  u64 Aa01 = 0, Aa23 = 0, Aa45 = 0, Aa67 = 0, Aa89 = 0;
  u64 Ab01 = 0, Ab23 = 0, Ab45 = 0, Ab67 = 0, Ab89 = 0;
  float la = 0.f, lb = 0.f;
  #pragma unroll 1
  for (int ym8 = 0; ym8 < 8; ym8++) {
    int ymg = kc * 8 + ym8;                       // global key row
    const float* kha = Hs + (ymg - ya + 31) * 10; // smem broadcast (row const per warp)
    const float* khb = Hs + (ymg - yb + 31) * 10;
    u64 ra = fmul2(Qa01, ldf2(kha));
    ra = ffma2(Qa23, ldf2(kha + 2), ra); ra = ffma2(Qa45, ldf2(kha + 4), ra);
    ra = ffma2(Qa67, ldf2(kha + 6), ra); ra = ffma2(Qa89, ldf2(kha + 8), ra);
    u64 rb = fmul2(Qb01, ldf2(khb));
    rb = ffma2(Qb23, ldf2(khb + 2), rb); rb = ffma2(Qb45, ldf2(khb + 4), rb);
    rb = ffma2(Qb67, ldf2(khb + 6), rb); rb = ffma2(Qb89, ldf2(khb + 8), rb);
    float2 fra = unpack2(ra), frb = unpack2(rb);
    float rha = fra.x + fra.y, rhb = frb.x + frb.y;

    const float4* kv = (const float4*)(KVs + ym8 * 640);
    #pragma unroll
    for (int xm = 0; xm < 32; xm++) {
      F4U c0, c1, c2, c3, c4;
      c0.f4 = kv[xm * 5];      // K0..K3
      c1.f4 = kv[xm * 5 + 1];  // K4..K7
      c2.f4 = kv[xm * 5 + 2];  // K8,K9,V0,V1
      c3.f4 = kv[xm * 5 + 3];  // V2..V5
      c4.f4 = kv[xm * 5 + 4];  // V6..V9
      float2 rw2 = unpack2(RWs[xm * 128 + tid]);  // {rwa, rwb}
      u64 sa = ffma2(Qa01, c0.u2.x, pack2(rha, rw2.x));
      sa = ffma2(Qa23, c0.u2.y, sa);
      sa = ffma2(Qa45, c1.u2.x, sa);
      sa = ffma2(Qa67, c1.u2.y, sa);
      sa = ffma2(Qa89, c2.u2.x, sa);
      u64 sb = ffma2(Qb01, c0.u2.x, pack2(rhb, rw2.y));
      sb = ffma2(Qb23, c0.u2.y, sb);
      sb = ffma2(Qb45, c1.u2.x, sb);
      sb = ffma2(Qb67, c1.u2.y, sb);
      sb = ffma2(Qb89, c2.u2.x, sb);
      float2 pa2 = unpack2(sa), pb2 = unpack2(sb);
      float pa = ex2f(pa2.x + pa2.y);   // logits tiny; no max-subtract needed
      float pb = ex2f(pb2.x + pb2.y);
      la += pa; lb += pb;
      u64 Pa = pack2(pa, pa), Pb = pack2(pb, pb);
      Aa01 = ffma2(Pa, c2.u2.y, Aa01);
      Aa23 = ffma2(Pa, c3.u2.x, Aa23);
      Aa45 = ffma2(Pa, c3.u2.y, Aa45);
      Aa67 = ffma2(Pa, c4.u2.x, Aa67);
      Aa89 = ffma2(Pa, c4.u2.y, Aa89);
      Ab01 = ffma2(Pb, c2.u2.y, Ab01);
      Ab23 = ffma2(Pb, c3.u2.x, Ab23);
      Ab45 = ffma2(Pb, c3.u2.y, Ab45);
      Ab67 = ffma2(Pb, c4.u2.x, Ab67);
      Ab89 = ffma2(Pb, c4.u2.y, Ab89);
    }
  }
  // store unnormalized partials (normalization in final_kernel)
  int base = (kc * 64 + bh) * 1024;
  u64* oa = (u64*)(g_pA + (base + na) * 10);
  oa[0] = Aa01; oa[1] = Aa23; oa[2] = Aa45; oa[3] = Aa67; oa[4] = Aa89;
  g_pl[base + na] = la;
  u64* ob = (u64*)(g_pA + (base + nb) * 10);
  ob[0] = Ab01; ob[1] = Ab23; ob[2] = Ab45; ob[3] = Ab67; ob[4] = Ab89;
  g_pl[base + nb] = lb;
}

// ---------------- K4: combine partials + poolconv + attno + fc ----------------
__global__ void final_kernel(const float* __restrict__ convo_w,
                             const float* __restrict__ convo_b,
                             const float* __restrict__ attno_w,
                             const float* __restrict__ attno_b,
                             const float* __restrict__ fc_w,
                             const float* __restrict__ fc_b,
                             float* __restrict__ out) {
  int b = blockIdx.x, tid = threadIdx.x;  // 256 threads
  int warp = tid >> 5, lane = tid & 31;
  __shared__ float Ssm[576];
  __shared__ float invl[4096];   // per (head,n) 1/(l0+l1+l2+l3)
  __shared__ float pooled[88];
  __shared__ float mean_s[40], pa[40];

  for (int i = tid; i < 576; i += 256) Ssm[i] = g_S[b * 576 + i];
  #pragma unroll 4
  for (int i = tid; i < 4096; i += 256) {
    float l = g_pl[b * 4096 + i]
            + g_pl[65536 + b * 4096 + i]
            + g_pl[131072 + b * 4096 + i]
            + g_pl[196608 + b * 4096 + i];
    invl[i] = __frcp_rn(l);
  }
  __syncthreads();

  #pragma unroll
  for (int i = 0; i < 11; i++) {
    int oc = warp * 11 + i;
    float acc = 0.f;
    const float* wp = convo_w + oc * 576;
    #pragma unroll
    for (int j = lane; j < 576; j += 32) acc = fmaf(__ldg(&wp[j]), Ssm[j], acc);
    acc = wred(acc);
    if (lane == 0) pooled[oc] = __ldg(&convo_b[oc]) + acc * (1.f / 1024.f);
  }

  // attn channel means over (n,d)-flat layout; invl index = flat/10
  #pragma unroll
  for (int cc = 0; cc < 5; cc++) {
    int c = warp * 5 + cc;
    const float* pA0 = g_pA + b * 40960 + c * 1024;
    int fbase = c * 1024;
    float s = 0.f;
    #pragma unroll 4
    for (int j = lane; j < 1024; j += 32) {
      float a = pA0[j] + pA0[655360 + j] + pA0[1310720 + j] + pA0[1966080 + j];
      s = fmaf(a, invl[(fbase + j) / 10], s);
    }
    s = wred(s);
    if (lane == 0) mean_s[c] = s * (1.f / 1024.f);
  }
  __syncthreads();
  if (tid < 40) {
    float acc = __ldg(&attno_b[tid]);
    #pragma unroll 4
    for (int c = 0; c < 40; c++) acc = fmaf(__ldg(&attno_w[tid * 40 + c]), mean_s[c], acc);
    pa[tid] = acc;
  }
  __syncthreads();
  if (tid < 100) {
    float acc = __ldg(&fc_b[tid]);
    const float* wp = fc_w + tid * 128;
    #pragma unroll 4
    for (int c = 0; c < 88; c++) acc = fmaf(__ldg(&wp[c]), pooled[c], acc);
    #pragma unroll 4
    for (int c = 0; c < 40; c++) acc = fmaf(__ldg(&wp[88 + c]), pa[c], acc);
    out[b * 100 + tid] = acc;
  }
}

// ---------------- launch ----------------
extern "C" void kernel_launch(void* const* d_in, const int* in_sizes, int n_in,
                              void* d_out, int out_size) {
  const float* x         = (const float*)d_in[0];
  const float* conv1_w   = (const float*)d_in[1];
  const float* conv1_b   = (const float*)d_in[2];
  const float* bn1_g     = (const float*)d_in[3];
  const float* bn1_b     = (const float*)d_in[4];
  const float* convo_w   = (const float*)d_in[5];
  const float* convo_b   = (const float*)d_in[6];
  const float* qkv_w     = (const float*)d_in[7];
  const float* qkv_b     = (const float*)d_in[8];
  const float* attno_w   = (const float*)d_in[9];
  const float* attno_b   = (const float*)d_in[10];
  const float* key_rel_h = (const float*)d_in[11];
  const float* key_rel_w = (const float*)d_in[12];
  const float* fc_w      = (const float*)d_in[13];
  const float* fc_b      = (const float*)d_in[14];
  float* out = (float*)d_out;

  cudaFuncSetAttribute(attn_kernel, cudaFuncAttributeMaxDynamicSharedMemorySize, ATTN_SMEM);

  conv1_kernel<<<dim3(64, 16), 256>>>(x, conv1_w, conv1_b);     // #0
  bnrelu_kernel<<<dim3(64, 16), 1024>>>(bn1_g, bn1_b);          // #1
  qkv_kernel<<<dim3(1, 15, 16), 256>>>(qkv_w, qkv_b);           // #2
  attn_kernel<<<dim3(4, 4, 64), 128, ATTN_SMEM>>>(key_rel_h, key_rel_w);  // #3 (profiled)
  final_kernel<<<16, 256>>>(convo_w, convo_b, attno_w, attno_b, fc_w, fc_b, out);
}

// round 9
// speedup vs baseline: 1.0116x; 1.0116x over previous
#include <cuda_runtime.h>

typedef unsigned long long u64;

// ---------------- scratch (device globals; no allocation) ----------------
__device__ float g_pre[16*64*1024];     // conv1 out, then h (in-place)
__device__ float2 g_bstats[64*16];      // per (oc,b) partial {sum, sumsq}
__device__ float g_S[16*64*9];          // 9 shifted window sums per (b, in-ch)
__device__ float g_Q[16*4*1024*10];
__device__ float g_KV[16*4*1024*20];    // interleaved K(10) | V(10) per key
__device__ float g_pA[4*16*4*1024*10];  // unnormalized attn partials (4 key-chunks)
__device__ float g_pl[4*16*4*1024];     // softmax denominators (partial)

__device__ __forceinline__ float wred(float v) {
  #pragma unroll
  for (int o = 16; o; o >>= 1) v += __shfl_down_sync(0xffffffffu, v, o);
  return v;
}

// ---- packed f32x2 helpers (sm_100+) ----
__device__ __forceinline__ u64 ffma2(u64 a, u64 b, u64 c) {
  u64 d; asm("fma.rn.f32x2 %0, %1, %2, %3;" : "=l"(d) : "l"(a), "l"(b), "l"(c)); return d;
}
__device__ __forceinline__ u64 fmul2(u64 a, u64 b) {
  u64 d; asm("mul.rn.f32x2 %0, %1, %2;" : "=l"(d) : "l"(a), "l"(b)); return d;
}
__device__ __forceinline__ u64 pack2(float lo, float hi) {
  u64 r; asm("mov.b64 %0, {%1, %2};" : "=l"(r) : "f"(lo), "f"(hi)); return r;
}
__device__ __forceinline__ float2 unpack2(u64 v) {
  float lo, hi; asm("mov.b64 {%0, %1}, %2;" : "=f"(lo), "=f"(hi) : "l"(v));
  return make_float2(lo, hi);
}
__device__ __forceinline__ float ex2f(float x) {
  float y; asm("ex2.approx.f32 %0, %1;" : "=f"(y) : "f"(x)); return y;
}

union F4U { float4 f4; ulonglong2 u2; };
union F2U { float2 f2; u64 u; };

__device__ __forceinline__ u64 ldf2(const float* p) {
  F2U t; t.f2 = *(const float2*)p; return t.u;
}

// ---------------- K0: conv1 3x3 (3->64) SAME + per-block BN partial stats ----------------
__global__ void __launch_bounds__(256) conv1_kernel(const float* __restrict__ x,
                                                    const float* __restrict__ w,
                                                    const float* __restrict__ bias) {
  int t = threadIdx.x;
  int oc = blockIdx.x, b = blockIdx.y;
  int p0 = t * 4;
  int y = p0 >> 5, x0 = p0 & 31;
  float w_[27];
  #pragma unroll
  for (int i = 0; i < 27; i++) w_[i] = __ldg(&w[oc * 27 + i]);
  float bv = __ldg(&bias[oc]);
  float a0 = bv, a1 = bv, a2 = bv, a3 = bv;
  #pragma unroll
  for (int ic = 0; ic < 3; ic++) {
    const float* base = x + (b * 3 + ic) * 1024;
    #pragma unroll
    for (int ky = 0; ky < 3; ky++) {
      int iy = y + ky - 1;
      if (iy < 0 || iy > 31) continue;
      const float* row = base + iy * 32;
      float r[6];
      #pragma unroll
      for (int dx = 0; dx < 6; dx++) {
        int c = x0 - 1 + dx;
        r[dx] = (c >= 0 && c < 32) ? __ldg(&row[c]) : 0.f;
      }
      #pragma unroll
      for (int kx = 0; kx < 3; kx++) {
        float wv = w_[ic * 9 + ky * 3 + kx];
        a0 = fmaf(wv, r[kx],     a0);
        a1 = fmaf(wv, r[kx + 1], a1);
        a2 = fmaf(wv, r[kx + 2], a2);
        a3 = fmaf(wv, r[kx + 3], a3);
      }
    }
  }
  *(float4*)(g_pre + (b * 64 + oc) * 1024 + p0) = make_float4(a0, a1, a2, a3);

  float s  = a0 + a1 + a2 + a3;
  float sq = fmaf(a0, a0, fmaf(a1, a1, fmaf(a2, a2, a3 * a3)));
  s = wred(s); sq = wred(sq);
  __shared__ float ss[8], s2m[8];
  int warp = t >> 5, lane = t & 31;
  if (lane == 0) { ss[warp] = s; s2m[warp] = sq; }
  __syncthreads();
  if (t == 0) {
    float S = 0.f, Q = 0.f;
    #pragma unroll
    for (int i = 0; i < 8; i++) { S += ss[i]; Q += s2m[i]; }
    g_bstats[oc * 16 + b] = make_float2(S, Q);
  }
}

// ---------------- K1: BN finalize + apply + relu (in place) + 9 window sums ----------------
__global__ void bnrelu_kernel(const float* __restrict__ gamma,
                              const float* __restrict__ beta) {
  int c = blockIdx.x, b = blockIdx.y;
  int p = threadIdx.x;                  // 1024 threads
  __shared__ float scb[2];
  if (p < 16) {
    float2 v = g_bstats[c * 16 + p];
    float s = v.x, q = v.y;
    #pragma unroll
    for (int o = 8; o; o >>= 1) {
      s += __shfl_down_sync(0xffffu, s, o, 16);
      q += __shfl_down_sync(0xffffu, q, o, 16);
    }
    if (p == 0) {
      float mean = s * (1.f / 16384.f);
      float var  = q * (1.f / 16384.f) - mean * mean;
      float sc = __ldg(&gamma[c]) * rsqrtf(var + 1e-5f);
      scb[0] = sc;
      scb[1] = __ldg(&beta[c]) - mean * sc;
    }
  }
  __syncthreads();

  int y = p >> 5, xx = p & 31;
  int idx = (b * 64 + c) * 1024 + p;
  float v = fmaxf(fmaf(g_pre[idx], scb[0], scb[1]), 0.f);
  g_pre[idx] = v;

  float t = v;
  float r0  = (y == 0)  ? v : 0.f;
  float r31 = (y == 31) ? v : 0.f;
  float c0  = (xx == 0)  ? v : 0.f;
  float c31 = (xx == 31) ? v : 0.f;

  __shared__ float red[32][5];
  __shared__ float corn[4];
  if (p == 0)    corn[0] = v;
  if (p == 31)   corn[1] = v;
  if (p == 992)  corn[2] = v;
  if (p == 1023) corn[3] = v;

  t = wred(t); r0 = wred(r0); r31 = wred(r31); c0 = wred(c0); c31 = wred(c31);
  int warp = p >> 5, lane = p & 31;
  if (lane == 0) { red[warp][0]=t; red[warp][1]=r0; red[warp][2]=r31; red[warp][3]=c0; red[warp][4]=c31; }
  __syncthreads();
  if (p < 32) {
    float a0 = red[p][0], a1 = red[p][1], a2 = red[p][2], a3 = red[p][3], a4 = red[p][4];
    a0 = wred(a0); a1 = wred(a1); a2 = wred(a2); a3 = wred(a3); a4 = wred(a4);
    if (p == 0) {
      float T = a0, R0 = a1, R31 = a2, C0 = a3, C31 = a4;
      float* Sp = g_S + (b * 64 + c) * 9;
      Sp[0] = T - R31 - C31 + corn[3];
      Sp[1] = T - R31;
      Sp[2] = T - R31 - C0 + corn[2];
      Sp[3] = T - C31;
      Sp[4] = T;
      Sp[5] = T - C0;
      Sp[6] = T - R0 - C31 + corn[1];
      Sp[7] = T - R0;
      Sp[8] = T - R0 - C0 + corn[0];
    }
  }
}

// ---------------- K2: qkv 1x1 conv (15 outputs/block) -> Q (scaled), KV interleaved ----------------
__global__ void __launch_bounds__(256) qkv_kernel(const float* __restrict__ w,
                                                  const float* __restrict__ bias) {
  int tid = threadIdx.x;        // 256
  int b = blockIdx.z;
  int o0 = blockIdx.y * 15;     // 8 groups of 15 output channels
  __shared__ float ws[960];
  __shared__ float bs[15];
  for (int i = tid; i < 960; i += 256) ws[i] = w[o0 * 64 + i];
  if (tid < 15) bs[tid] = bias[o0 + tid];
  __syncthreads();
  int n0 = tid * 4;
  float4 acc[15];
  #pragma unroll
  for (int u = 0; u < 15; u++) { float bv = bs[u]; acc[u] = make_float4(bv, bv, bv, bv); }
  const float* hp = g_pre + b * 64 * 1024 + n0;
  #pragma unroll 2
  for (int i = 0; i < 64; i++) {
    float4 hv = *(const float4*)(hp + i * 1024);
    #pragma unroll
    for (int u = 0; u < 15; u++) {
      float wv = ws[u * 64 + i];
      acc[u].x = fmaf(wv, hv.x, acc[u].x);
      acc[u].y = fmaf(wv, hv.y, acc[u].y);
      acc[u].z = fmaf(wv, hv.z, acc[u].z);
      acc[u].w = fmaf(wv, hv.w, acc[u].w);
    }
  }
  // Q gets dkh^-0.5 * log2(e) folded in (exp -> ex2 domain; exact)
  const float QMUL = 0.31622776601683794f * 1.4426950408889634f;
  #pragma unroll
  for (int u = 0; u < 15; u++) {
    int o = o0 + u;
    int which = o / 40;
    int r = o - which * 40;
    int head = r / 10, d = r - head * 10;
    int bh = b * 4 + head;
    if (which == 0) {
      float* pb = g_Q + (bh * 1024) * 10 + d;
      pb[(n0 + 0) * 10] = acc[u].x * QMUL;
      pb[(n0 + 1) * 10] = acc[u].y * QMUL;
      pb[(n0 + 2) * 10] = acc[u].z * QMUL;
      pb[(n0 + 3) * 10] = acc[u].w * QMUL;
    } else {
      float* pb = g_KV + (bh * 1024) * 20 + ((which == 1) ? d : 10 + d);
      pb[(n0 + 0) * 20] = acc[u].x;
      pb[(n0 + 1) * 20] = acc[u].y;
      pb[(n0 + 2) * 20] = acc[u].z;
      pb[(n0 + 3) * 20] = acc[u].w;
    }
  }
}

// ---------------- K3: attention, 2q/thread, split-K x4, rw packed in smem ----------------
// smem: KV 256*20 f32 (20480B) + RW [32][128] u64 (32768B) + Hs 630 (2520B) + Ws 630 (2520B)
#define ATTN_SMEM ((5120 + 8192 + 640 + 640) * 4)

__global__ void __launch_bounds__(128, 3) attn_kernel(const float* __restrict__ krh,
                                                      const float* __restrict__ krw) {
  extern __shared__ float sm[];
  float* KVs = sm;                    // [256][20]
  u64*   RWs = (u64*)(sm + 5120);     // [xm][tid] packed {rwa, rwb}
  float* Hs  = sm + 13312;            // key_rel_h 63*10
  float* Ws  = sm + 13952;            // key_rel_w 63*10
  int bh = blockIdx.z;
  int kc = blockIdx.y;                // key chunk 0..3 (256 keys each)
  int tid = threadIdx.x;              // 128
  int warp = tid >> 5, lane = tid & 31;

  // stage KV chunk (coalesced float4) + both rel tables
  {
    const float4* src = (const float4*)(g_KV + bh * 20480 + kc * 5120);
    float4* dst = (float4*)KVs;
    #pragma unroll 10
    for (int i = tid; i < 1280; i += 128) dst[i] = src[i];
    for (int i = tid; i < 630; i += 128) { Hs[i] = krh[i]; Ws[i] = krw[i]; }
  }

  int ya = blockIdx.x * 8 + warp;     // query row A (warp 0..3)
  int yb = ya + 4;                    // query row B
  int xq = lane;
  int na = ya * 32 + xq, nb = yb * 32 + xq;
  const float* qa = g_Q + (bh * 1024 + na) * 10;   // pre-scaled by dkh^-.5*log2e
  const float* qb = g_Q + (bh * 1024 + nb) * 10;
  u64 Qa01 = ldf2(qa), Qa23 = ldf2(qa + 2), Qa45 = ldf2(qa + 4),
      Qa67 = ldf2(qa + 6), Qa89 = ldf2(qa + 8);
  u64 Qb01 = ldf2(qb), Qb23 = ldf2(qb + 2), Qb45 = ldf2(qb + 4),
      Qb67 = ldf2(qb + 6), Qb89 = ldf2(qb + 8);

  __syncthreads();

  // rw per query from smem Ws; packed {a,b} -> thread-private smem slot
  #pragma unroll
  for (int xm = 0; xm < 32; xm++) {
    const float* kr = Ws + (xm - xq + 31) * 10;
    u64 k01 = ldf2(kr), k23 = ldf2(kr + 2), k45 = ldf2(kr + 4),
        k67 = ldf2(kr + 6), k89 = ldf2(kr + 8);
    u64 sa = fmul2(Qa01, k01);
    sa = ffma2(Qa23, k23, sa); sa = ffma2(Qa45, k45, sa);
    sa = ffma2(Qa67, k67, sa); sa = ffma2(Qa89, k89, sa);
    u64 sb = fmul2(Qb01, k01);
    sb = ffma2(Qb23, k23, sb); sb = ffma2(Qb45, k45, sb);
    sb = ffma2(Qb67, k67, sb); sb = ffma2(Qb89, k89, sb);
    float2 fa = unpack2(sa), fb = unpack2(sb);
    RWs[xm * 128 + tid] = pack2(fa.x + fa.y, fb.x + fb.y);
  }

  u64 Aa01 = 0, Aa23 = 0, Aa45 = 0, Aa67 = 0, Aa89 = 0;
  u64 Ab01 = 0, Ab23 = 0, Ab45 = 0, Ab67 = 0, Ab89 = 0;
  float la = 0.f, lb = 0.f;
  #pragma unroll 1
  for (int ym8 = 0; ym8 < 8; ym8++) {
    int ymg = kc * 8 + ym8;                       // global key row
    const float* kha = Hs + (ymg - ya + 31) * 10; // smem broadcast (row const per warp)
    const float* khb = Hs + (ymg - yb + 31) * 10;
    u64 ra = fmul2(Qa01, ldf2(kha));
    ra = ffma2(Qa23, ldf2(kha + 2), ra); ra = ffma2(Qa45, ldf2(kha + 4), ra);
    ra = ffma2(Qa67, ldf2(kha + 6), ra); ra = ffma2(Qa89, ldf2(kha + 8), ra);
    u64 rb = fmul2(Qb01, ldf2(khb));
    rb = ffma2(Qb23, ldf2(khb + 2), rb); rb = ffma2(Qb45, ldf2(khb + 4), rb);
    rb = ffma2(Qb67, ldf2(khb + 6), rb); rb = ffma2(Qb89, ldf2(khb + 8), rb);
    float2 fra = unpack2(ra), frb = unpack2(rb);
    float rha = fra.x + fra.y, rhb = frb.x + frb.y;

    const float4* kv = (const float4*)(KVs + ym8 * 640);
    #pragma unroll
    for (int xm = 0; xm < 32; xm++) {
      F4U c0, c1, c2, c3, c4;
      c0.f4 = kv[xm * 5];      // K0..K3
      c1.f4 = kv[xm * 5 + 1];  // K4..K7
      c2.f4 = kv[xm * 5 + 2];  // K8,K9,V0,V1
      c3.f4 = kv[xm * 5 + 3];  // V2..V5
      c4.f4 = kv[xm * 5 + 4];  // V6..V9
      float2 rw2 = unpack2(RWs[xm * 128 + tid]);  // {rwa, rwb}
      u64 sa = ffma2(Qa01, c0.u2.x, pack2(rha, rw2.x));
      sa = ffma2(Qa23, c0.u2.y, sa);
      sa = ffma2(Qa45, c1.u2.x, sa);
      sa = ffma2(Qa67, c1.u2.y, sa);
      sa = ffma2(Qa89, c2.u2.x, sa);
      u64 sb = ffma2(Qb01, c0.u2.x, pack2(rhb, rw2.y));
      sb = ffma2(Qb23, c0.u2.y, sb);
      sb = ffma2(Qb45, c1.u2.x, sb);
      sb = ffma2(Qb67, c1.u2.y, sb);
      sb = ffma2(Qb89, c2.u2.x, sb);
      float2 pa2 = unpack2(sa), pb2 = unpack2(sb);
      float pa = ex2f(pa2.x + pa2.y);   // logits tiny; no max-subtract needed
      float pb = ex2f(pb2.x + pb2.y);
      la += pa; lb += pb;
      u64 Pa = pack2(pa, pa), Pb = pack2(pb, pb);
      Aa01 = ffma2(Pa, c2.u2.y, Aa01);
      Aa23 = ffma2(Pa, c3.u2.x, Aa23);
      Aa45 = ffma2(Pa, c3.u2.y, Aa45);
      Aa67 = ffma2(Pa, c4.u2.x, Aa67);
      Aa89 = ffma2(Pa, c4.u2.y, Aa89);
      Ab01 = ffma2(Pb, c2.u2.y, Ab01);
      Ab23 = ffma2(Pb, c3.u2.x, Ab23);
      Ab45 = ffma2(Pb, c3.u2.y, Ab45);
      Ab67 = ffma2(Pb, c4.u2.x, Ab67);
      Ab89 = ffma2(Pb, c4.u2.y, Ab89);
    }
  }
  // store unnormalized partials (normalization in final_kernel)
  int base = (kc * 64 + bh) * 1024;
  u64* oa = (u64*)(g_pA + (base + na) * 10);
  oa[0] = Aa01; oa[1] = Aa23; oa[2] = Aa45; oa[3] = Aa67; oa[4] = Aa89;
  g_pl[base + na] = la;
  u64* ob = (u64*)(g_pA + (base + nb) * 10);
  ob[0] = Ab01; ob[1] = Ab23; ob[2] = Ab45; ob[3] = Ab67; ob[4] = Ab89;
  g_pl[base + nb] = lb;
}

// ---------------- K4: combine partials + poolconv + attno + fc ----------------
__global__ void final_kernel(const float* __restrict__ convo_w,
                             const float* __restrict__ convo_b,
                             const float* __restrict__ attno_w,
                             const float* __restrict__ attno_b,
                             const float* __restrict__ fc_w,
                             const float* __restrict__ fc_b,
                             float* __restrict__ out) {
  int b = blockIdx.x, tid = threadIdx.x;  // 256 threads
  int warp = tid >> 5, lane = tid & 31;
  __shared__ float Ssm[576];
  __shared__ float invl[4096];   // per (head,n) 1/(l0+l1+l2+l3)
  __shared__ float pooled[88];
  __shared__ float mean_s[40], pa[40];

  for (int i = tid; i < 576; i += 256) Ssm[i] = g_S[b * 576 + i];
  #pragma unroll 4
  for (int i = tid; i < 4096; i += 256) {
    float l = g_pl[b * 4096 + i]
            + g_pl[65536 + b * 4096 + i]
            + g_pl[131072 + b * 4096 + i]
            + g_pl[196608 + b * 4096 + i];
    invl[i] = __frcp_rn(l);
  }
  __syncthreads();

  #pragma unroll
  for (int i = 0; i < 11; i++) {
    int oc = warp * 11 + i;
    float acc = 0.f;
    const float* wp = convo_w + oc * 576;
    #pragma unroll
    for (int j = lane; j < 576; j += 32) acc = fmaf(__ldg(&wp[j]), Ssm[j], acc);
    acc = wred(acc);
    if (lane == 0) pooled[oc] = __ldg(&convo_b[oc]) + acc * (1.f / 1024.f);
  }

  // attn channel means over (n,d)-flat layout; invl index = flat/10
  #pragma unroll
  for (int cc = 0; cc < 5; cc++) {
    int c = warp * 5 + cc;
    const float* pA0 = g_pA + b * 40960 + c * 1024;
    int fbase = c * 1024;
    float s = 0.f;
    #pragma unroll 4
    for (int j = lane; j < 1024; j += 32) {
      float a = pA0[j] + pA0[655360 + j] + pA0[1310720 + j] + pA0[1966080 + j];
      s = fmaf(a, invl[(fbase + j) / 10], s);
    }
    s = wred(s);
    if (lane == 0) mean_s[c] = s * (1.f / 1024.f);
  }
  __syncthreads();
  if (tid < 40) {
    float acc = __ldg(&attno_b[tid]);
    #pragma unroll 4
    for (int c = 0; c < 40; c++) acc = fmaf(__ldg(&attno_w[tid * 40 + c]), mean_s[c], acc);
    pa[tid] = acc;
  }
  __syncthreads();
  if (tid < 100) {
    float acc = __ldg(&fc_b[tid]);
    const float* wp = fc_w + tid * 128;
    #pragma unroll 4
    for (int c = 0; c < 88; c++) acc = fmaf(__ldg(&wp[c]), pooled[c], acc);
    #pragma unroll 4
    for (int c = 0; c < 40; c++) acc = fmaf(__ldg(&wp[88 + c]), pa[c], acc);
    out[b * 100 + tid] = acc;
  }
}

// ---------------- launch ----------------
extern "C" void kernel_launch(void* const* d_in, const int* in_sizes, int n_in,
                              void* d_out, int out_size) {
  const float* x         = (const float*)d_in[0];
  const float* conv1_w   = (const float*)d_in[1];
  const float* conv1_b   = (const float*)d_in[2];
  const float* bn1_g     = (const float*)d_in[3];
  const float* bn1_b     = (const float*)d_in[4];
  const float* convo_w   = (const float*)d_in[5];
  const float* convo_b   = (const float*)d_in[6];
  const float* qkv_w     = (const float*)d_in[7];
  const float* qkv_b     = (const float*)d_in[8];
  const float* attno_w   = (const float*)d_in[9];
  const float* attno_b   = (const float*)d_in[10];
  const float* key_rel_h = (const float*)d_in[11];
  const float* key_rel_w = (const float*)d_in[12];
  const float* fc_w      = (const float*)d_in[13];
  const float* fc_b      = (const float*)d_in[14];
  float* out = (float*)d_out;

  cudaFuncSetAttribute(attn_kernel, cudaFuncAttributeMaxDynamicSharedMemorySize, ATTN_SMEM);

  conv1_kernel<<<dim3(64, 16), 256>>>(x, conv1_w, conv1_b);     // #0
  bnrelu_kernel<<<dim3(64, 16), 1024>>>(bn1_g, bn1_b);          // #1
  qkv_kernel<<<dim3(1, 8, 16), 256>>>(qkv_w, qkv_b);            // #2
  attn_kernel<<<dim3(4, 4, 64), 128, ATTN_SMEM>>>(key_rel_h, key_rel_w);  // #3 (profiled)
  final_kernel<<<16, 256>>>(convo_w, convo_b, attno_w, attno_b, fc_w, fc_b, out);
}

// round 10
// speedup vs baseline: 1.2388x; 1.2246x over previous
#include <cuda_runtime.h>

typedef unsigned long long u64;

// ---------------- scratch (device globals; no allocation) ----------------
__device__ float g_pre[16*64*1024];     // conv1 out, then h (in-place)
__device__ float2 g_bstats[64*16];      // per (oc,b) partial {sum, sumsq}
__device__ float g_S[16*64*9];          // 9 shifted window sums per (b, in-ch)
__device__ float g_Q[16*4*1024*10];
__device__ float g_KV[16*4*1024*20];    // interleaved K(10) | V(10) per key
__device__ float g_attn[16*4*1024*10];  // normalized attention output
__device__ float g_pooled[16*88];
__device__ float g_means[16*40];

__device__ __forceinline__ float wred(float v) {
  #pragma unroll
  for (int o = 16; o; o >>= 1) v += __shfl_down_sync(0xffffffffu, v, o);
  return v;
}

// ---- packed f32x2 helpers (sm_100+) ----
__device__ __forceinline__ u64 ffma2(u64 a, u64 b, u64 c) {
  u64 d; asm("fma.rn.f32x2 %0, %1, %2, %3;" : "=l"(d) : "l"(a), "l"(b), "l"(c)); return d;
}
__device__ __forceinline__ u64 fmul2(u64 a, u64 b) {
  u64 d; asm("mul.rn.f32x2 %0, %1, %2;" : "=l"(d) : "l"(a), "l"(b)); return d;
}
__device__ __forceinline__ u64 pack2(float lo, float hi) {
  u64 r; asm("mov.b64 %0, {%1, %2};" : "=l"(r) : "f"(lo), "f"(hi)); return r;
}
__device__ __forceinline__ float2 unpack2(u64 v) {
  float lo, hi; asm("mov.b64 {%0, %1}, %2;" : "=f"(lo), "=f"(hi) : "l"(v));
  return make_float2(lo, hi);
}
__device__ __forceinline__ float ex2f(float x) {
  float y; asm("ex2.approx.f32 %0, %1;" : "=f"(y) : "f"(x)); return y;
}

union F4U { float4 f4; ulonglong2 u2; };
union F2U { float2 f2; u64 u; };

__device__ __forceinline__ u64 ldf2(const float* p) {
  F2U t; t.f2 = *(const float2*)p; return t.u;
}

// ---------------- K0: conv1 3x3 (3->64) SAME + per-block BN partial stats ----------------
__global__ void __launch_bounds__(256) conv1_kernel(const float* __restrict__ x,
                                                    const float* __restrict__ w,
                                                    const float* __restrict__ bias) {
  int t = threadIdx.x;
  int oc = blockIdx.x, b = blockIdx.y;
  int p0 = t * 4;
  int y = p0 >> 5, x0 = p0 & 31;
  float w_[27];
  #pragma unroll
  for (int i = 0; i < 27; i++) w_[i] = __ldg(&w[oc * 27 + i]);
  float bv = __ldg(&bias[oc]);
  float a0 = bv, a1 = bv, a2 = bv, a3 = bv;
  #pragma unroll
  for (int ic = 0; ic < 3; ic++) {
    const float* base = x + (b * 3 + ic) * 1024;
    #pragma unroll
    for (int ky = 0; ky < 3; ky++) {
      int iy = y + ky - 1;
      if (iy < 0 || iy > 31) continue;
      const float* row = base + iy * 32;
      float r[6];
      #pragma unroll
      for (int dx = 0; dx < 6; dx++) {
        int c = x0 - 1 + dx;
        r[dx] = (c >= 0 && c < 32) ? __ldg(&row[c]) : 0.f;
      }
      #pragma unroll
      for (int kx = 0; kx < 3; kx++) {
        float wv = w_[ic * 9 + ky * 3 + kx];
        a0 = fmaf(wv, r[kx],     a0);
        a1 = fmaf(wv, r[kx + 1], a1);
        a2 = fmaf(wv, r[kx + 2], a2);
        a3 = fmaf(wv, r[kx + 3], a3);
      }
    }
  }
  *(float4*)(g_pre + (b * 64 + oc) * 1024 + p0) = make_float4(a0, a1, a2, a3);

  float s  = a0 + a1 + a2 + a3;
  float sq = fmaf(a0, a0, fmaf(a1, a1, fmaf(a2, a2, a3 * a3)));
  s = wred(s); sq = wred(sq);
  __shared__ float ss[8], s2m[8];
  int warp = t >> 5, lane = t & 31;
  if (lane == 0) { ss[warp] = s; s2m[warp] = sq; }
  __syncthreads();
  if (t == 0) {
    float S = 0.f, Q = 0.f;
    #pragma unroll
    for (int i = 0; i < 8; i++) { S += ss[i]; Q += s2m[i]; }
    g_bstats[oc * 16 + b] = make_float2(S, Q);
  }
}

// ---------------- K1: BN finalize + apply + relu (in place) + 9 window sums ----------------
__global__ void bnrelu_kernel(const float* __restrict__ gamma,
                              const float* __restrict__ beta) {
  int c = blockIdx.x, b = blockIdx.y;
  int p = threadIdx.x;                  // 1024 threads
  __shared__ float scb[2];
  if (p < 16) {
    float2 v = g_bstats[c * 16 + p];
    float s = v.x, q = v.y;
    #pragma unroll
    for (int o = 8; o; o >>= 1) {
      s += __shfl_down_sync(0xffffu, s, o, 16);
      q += __shfl_down_sync(0xffffu, q, o, 16);
    }
    if (p == 0) {
      float mean = s * (1.f / 16384.f);
      float var  = q * (1.f / 16384.f) - mean * mean;
      float sc = __ldg(&gamma[c]) * rsqrtf(var + 1e-5f);
      scb[0] = sc;
      scb[1] = __ldg(&beta[c]) - mean * sc;
    }
  }
  __syncthreads();

  int y = p >> 5, xx = p & 31;
  int idx = (b * 64 + c) * 1024 + p;
  float v = fmaxf(fmaf(g_pre[idx], scb[0], scb[1]), 0.f);
  g_pre[idx] = v;

  float t = v;
  float r0  = (y == 0)  ? v : 0.f;
  float r31 = (y == 31) ? v : 0.f;
  float c0  = (xx == 0)  ? v : 0.f;
  float c31 = (xx == 31) ? v : 0.f;

  __shared__ float red[32][5];
  __shared__ float corn[4];
  if (p == 0)    corn[0] = v;
  if (p == 31)   corn[1] = v;
  if (p == 992)  corn[2] = v;
  if (p == 1023) corn[3] = v;

  t = wred(t); r0 = wred(r0); r31 = wred(r31); c0 = wred(c0); c31 = wred(c31);
  int warp = p >> 5, lane = p & 31;
  if (lane == 0) { red[warp][0]=t; red[warp][1]=r0; red[warp][2]=r31; red[warp][3]=c0; red[warp][4]=c31; }
  __syncthreads();
  if (p < 32) {
    float a0 = red[p][0], a1 = red[p][1], a2 = red[p][2], a3 = red[p][3], a4 = red[p][4];
    a0 = wred(a0); a1 = wred(a1); a2 = wred(a2); a3 = wred(a3); a4 = wred(a4);
    if (p == 0) {
      float T = a0, R0 = a1, R31 = a2, C0 = a3, C31 = a4;
      float* Sp = g_S + (b * 64 + c) * 9;
      Sp[0] = T - R31 - C31 + corn[3];
      Sp[1] = T - R31;
      Sp[2] = T - R31 - C0 + corn[2];
      Sp[3] = T - C31;
      Sp[4] = T;
      Sp[5] = T - C0;
      Sp[6] = T - R0 - C31 + corn[1];
      Sp[7] = T - R0;
      Sp[8] = T - R0 - C0 + corn[0];
    }
  }
}

// ---------------- K2: qkv 1x1 conv (15 outputs/block) -> Q (scaled), KV interleaved ----------------
__global__ void __launch_bounds__(256) qkv_kernel(const float* __restrict__ w,
                                                  const float* __restrict__ bias) {
  int tid = threadIdx.x;        // 256
  int b = blockIdx.z;
  int o0 = blockIdx.y * 15;     // 8 groups of 15 output channels
  __shared__ float ws[960];
  __shared__ float bs[15];
  for (int i = tid; i < 960; i += 256) ws[i] = w[o0 * 64 + i];
  if (tid < 15) bs[tid] = bias[o0 + tid];
  __syncthreads();
  int n0 = tid * 4;
  float4 acc[15];
  #pragma unroll
  for (int u = 0; u < 15; u++) { float bv = bs[u]; acc[u] = make_float4(bv, bv, bv, bv); }
  const float* hp = g_pre + b * 64 * 1024 + n0;
  #pragma unroll 2
  for (int i = 0; i < 64; i++) {
    float4 hv = *(const float4*)(hp + i * 1024);
    #pragma unroll
    for (int u = 0; u < 15; u++) {
      float wv = ws[u * 64 + i];
      acc[u].x = fmaf(wv, hv.x, acc[u].x);
      acc[u].y = fmaf(wv, hv.y, acc[u].y);
      acc[u].z = fmaf(wv, hv.z, acc[u].z);
      acc[u].w = fmaf(wv, hv.w, acc[u].w);
    }
  }
  // Q gets dkh^-0.5 * log2(e) folded in (exp -> ex2 domain; exact)
  const float QMUL = 0.31622776601683794f * 1.4426950408889634f;
  #pragma unroll
  for (int u = 0; u < 15; u++) {
    int o = o0 + u;
    int which = o / 40;
    int r = o - which * 40;
    int head = r / 10, d = r - head * 10;
    int bh = b * 4 + head;
    if (which == 0) {
      float* pb = g_Q + (bh * 1024) * 10 + d;
      pb[(n0 + 0) * 10] = acc[u].x * QMUL;
      pb[(n0 + 1) * 10] = acc[u].y * QMUL;
      pb[(n0 + 2) * 10] = acc[u].z * QMUL;
      pb[(n0 + 3) * 10] = acc[u].w * QMUL;
    } else {
      float* pb = g_KV + (bh * 1024) * 20 + ((which == 1) ? d : 10 + d);
      pb[(n0 + 0) * 20] = acc[u].x;
      pb[(n0 + 1) * 20] = acc[u].y;
      pb[(n0 + 2) * 20] = acc[u].z;
      pb[(n0 + 3) * 20] = acc[u].w;
    }
  }
}

// ---------------- K3: attention, 2 queries/thread, KV interleaved (R5 config) ----------------
// smem: KV 1024*20 floats (81920B) + krh 630 (2520B) + krw 630 (2520B)
#define ATTN_SMEM ((20480 + 640 + 640) * 4)

__global__ void __launch_bounds__(128) attn_kernel(const float* __restrict__ krh,
                                                   const float* __restrict__ krw) {
  extern __shared__ float sm[];
  float* KVs = sm;               // [m][20]
  float* Hs  = sm + 20480;       // key_rel_h 63*10
  float* Ws  = sm + 21120;       // key_rel_w 63*10
  int b = blockIdx.z, h = blockIdx.y;
  int bh = b * 4 + h;
  int tid = threadIdx.x;         // 128
  int warp = tid >> 5, lane = tid & 31;

  // stage KV (coalesced float4 copy) + rel tables
  {
    const float4* src = (const float4*)(g_KV + bh * 20480);
    float4* dst = (float4*)KVs;
    #pragma unroll 8
    for (int i = tid; i < 5120; i += 128) dst[i] = src[i];
    for (int i = tid; i < 630; i += 128) { Hs[i] = krh[i]; Ws[i] = krw[i]; }
  }

  int ya = blockIdx.x * 8 + warp;        // query row A
  int yb = ya + 4;                       // query row B
  int xq = lane;
  int na = ya * 32 + xq, nb = yb * 32 + xq;
  const float* qa = g_Q + (bh * 1024 + na) * 10;
  const float* qb = g_Q + (bh * 1024 + nb) * 10;
  u64 Qa01 = ldf2(qa), Qa23 = ldf2(qa + 2), Qa45 = ldf2(qa + 4),
      Qa67 = ldf2(qa + 6), Qa89 = ldf2(qa + 8);
  u64 Qb01 = ldf2(qb), Qb23 = ldf2(qb + 2), Qb45 = ldf2(qb + 4),
      Qb67 = ldf2(qb + 6), Qb89 = ldf2(qb + 8);

  __syncthreads();

  // rw[xm] per query (same xq -> shared krw rows)
  float rwa[32], rwb[32];
  #pragma unroll
  for (int xm = 0; xm < 32; xm++) {
    const float* kr = Ws + (xm - xq + 31) * 10;
    u64 k01 = ldf2(kr), k23 = ldf2(kr + 2), k45 = ldf2(kr + 4),
        k67 = ldf2(kr + 6), k89 = ldf2(kr + 8);
    u64 sa = fmul2(Qa01, k01);
    sa = ffma2(Qa23, k23, sa); sa = ffma2(Qa45, k45, sa);
    sa = ffma2(Qa67, k67, sa); sa = ffma2(Qa89, k89, sa);
    u64 sb = fmul2(Qb01, k01);
    sb = ffma2(Qb23, k23, sb); sb = ffma2(Qb45, k45, sb);
    sb = ffma2(Qb67, k67, sb); sb = ffma2(Qb89, k89, sb);
    float2 fa = unpack2(sa), fb = unpack2(sb);
    rwa[xm] = fa.x + fa.y;
    rwb[xm] = fb.x + fb.y;
  }

  u64 Aa01 = 0, Aa23 = 0, Aa45 = 0, Aa67 = 0, Aa89 = 0;
  u64 Ab01 = 0, Ab23 = 0, Ab45 = 0, Ab67 = 0, Ab89 = 0;
  float la = 0.f, lb = 0.f;
  #pragma unroll 1
  for (int ym = 0; ym < 32; ym++) {
    const float* kha = Hs + (ym - ya + 31) * 10;
    const float* khb = Hs + (ym - yb + 31) * 10;
    u64 ra = fmul2(Qa01, ldf2(kha));
    ra = ffma2(Qa23, ldf2(kha + 2), ra); ra = ffma2(Qa45, ldf2(kha + 4), ra);
    ra = ffma2(Qa67, ldf2(kha + 6), ra); ra = ffma2(Qa89, ldf2(kha + 8), ra);
    u64 rb = fmul2(Qb01, ldf2(khb));
    rb = ffma2(Qb23, ldf2(khb + 2), rb); rb = ffma2(Qb45, ldf2(khb + 4), rb);
    rb = ffma2(Qb67, ldf2(khb + 6), rb); rb = ffma2(Qb89, ldf2(khb + 8), rb);
    float2 fra = unpack2(ra), frb = unpack2(rb);
    float rha = fra.x + fra.y, rhb = frb.x + frb.y;

    const float4* kv = (const float4*)(KVs + ym * 640);
    #pragma unroll
    for (int xm = 0; xm < 32; xm++) {
      F4U c0, c1, c2, c3, c4;
      c0.f4 = kv[xm * 5];      // K0..K3
      c1.f4 = kv[xm * 5 + 1];  // K4..K7
      c2.f4 = kv[xm * 5 + 2];  // K8,K9,V0,V1
      c3.f4 = kv[xm * 5 + 3];  // V2..V5
      c4.f4 = kv[xm * 5 + 4];  // V6..V9
      u64 sa = ffma2(Qa01, c0.u2.x, pack2(rha, rwa[xm]));
      sa = ffma2(Qa23, c0.u2.y, sa);
      sa = ffma2(Qa45, c1.u2.x, sa);
      sa = ffma2(Qa67, c1.u2.y, sa);
      sa = ffma2(Qa89, c2.u2.x, sa);
      u64 sb = ffma2(Qb01, c0.u2.x, pack2(rhb, rwb[xm]));
      sb = ffma2(Qb23, c0.u2.y, sb);
      sb = ffma2(Qb45, c1.u2.x, sb);
      sb = ffma2(Qb67, c1.u2.y, sb);
      sb = ffma2(Qb89, c2.u2.x, sb);
      float2 pa2 = unpack2(sa), pb2 = unpack2(sb);
      float pa = ex2f(pa2.x + pa2.y);
      float pb = ex2f(pb2.x + pb2.y);
      la += pa; lb += pb;
      u64 Pa = pack2(pa, pa), Pb = pack2(pb, pb);
      Aa01 = ffma2(Pa, c2.u2.y, Aa01);
      Aa23 = ffma2(Pa, c3.u2.x, Aa23);
      Aa45 = ffma2(Pa, c3.u2.y, Aa45);
      Aa67 = ffma2(Pa, c4.u2.x, Aa67);
      Aa89 = ffma2(Pa, c4.u2.y, Aa89);
      Ab01 = ffma2(Pb, c2.u2.y, Ab01);
      Ab23 = ffma2(Pb, c3.u2.x, Ab23);
      Ab45 = ffma2(Pb, c3.u2.y, Ab45);
      Ab67 = ffma2(Pb, c4.u2.x, Ab67);
      Ab89 = ffma2(Pb, c4.u2.y, Ab89);
    }
  }
  float inva = __frcp_rn(la), invb = __frcp_rn(lb);
  u64 ia = pack2(inva, inva), ib = pack2(invb, invb);
  u64* oa = (u64*)(g_attn + (bh * 1024 + na) * 10);
  oa[0] = fmul2(Aa01, ia); oa[1] = fmul2(Aa23, ia); oa[2] = fmul2(Aa45, ia);
  oa[3] = fmul2(Aa67, ia); oa[4] = fmul2(Aa89, ia);
  u64* ob = (u64*)(g_attn + (bh * 1024 + nb) * 10);
  ob[0] = fmul2(Ab01, ib); ob[1] = fmul2(Ab23, ib); ob[2] = fmul2(Ab45, ib);
  ob[3] = fmul2(Ab67, ib); ob[4] = fmul2(Ab89, ib);
}

// ---------------- K4: pool (warp per task: 88 poolconv dots + 40 attn means) ----------------
__global__ void __launch_bounds__(1024) pool_kernel(const float* __restrict__ convo_w,
                                                    const float* __restrict__ convo_b) {
  int q = blockIdx.x, b = blockIdx.y;     // q 0..3
  int tid = threadIdx.x;                   // 1024
  int warp = tid >> 5, lane = tid & 31;
  int task = q * 32 + warp;                // 0..127
  __shared__ float Ssm[576];
  for (int i = tid; i < 576; i += 1024) Ssm[i] = g_S[b * 576 + i];
  __syncthreads();
  if (task < 88) {
    const float* wp = convo_w + task * 576;
    float acc = 0.f;
    #pragma unroll
    for (int i = lane; i < 576; i += 32) acc = fmaf(__ldg(&wp[i]), Ssm[i], acc);
    acc = wred(acc);
    if (lane == 0) g_pooled[b * 88 + task] = __ldg(&convo_b[task]) + acc * (1.f / 1024.f);
  } else {
    int c = task - 88;   // 0..39: channel c = contiguous span of (n,d)-flat attn
    const float* p = g_attn + b * 40960 + c * 1024;
    float s = 0.f;
    #pragma unroll 8
    for (int j = lane; j < 1024; j += 32) s += p[j];
    s = wred(s);
    if (lane == 0) g_means[b * 40 + c] = s * (1.f / 1024.f);
  }
}

// ---------------- K5: attno + fc ----------------
__global__ void __launch_bounds__(128) fc_kernel(const float* __restrict__ attno_w,
                                                 const float* __restrict__ attno_b,
                                                 const float* __restrict__ fc_w,
                                                 const float* __restrict__ fc_b,
                                                 float* __restrict__ out) {
  int b = blockIdx.x, tid = threadIdx.x;  // 128
  __shared__ float pooled[88], means[40], pa[40];
  if (tid < 88) pooled[tid] = g_pooled[b * 88 + tid];
  if (tid < 40) means[tid] = g_means[b * 40 + tid];
  __syncthreads();
  if (tid < 40) {
    float acc = __ldg(&attno_b[tid]);
    #pragma unroll 4
    for (int c = 0; c < 40; c++) acc = fmaf(__ldg(&attno_w[tid * 40 + c]), means[c], acc);
    pa[tid] = acc;
  }
  __syncthreads();
  if (tid < 100) {
    float acc = __ldg(&fc_b[tid]);
    const float* wp = fc_w + tid * 128;
    #pragma unroll 4
    for (int c = 0; c < 88; c++) acc = fmaf(__ldg(&wp[c]), pooled[c], acc);
    #pragma unroll 4
    for (int c = 0; c < 40; c++) acc = fmaf(__ldg(&wp[88 + c]), pa[c], acc);
    out[b * 100 + tid] = acc;
  }
}

// ---------------- launch ----------------
extern "C" void kernel_launch(void* const* d_in, const int* in_sizes, int n_in,
                              void* d_out, int out_size) {
  const float* x         = (const float*)d_in[0];
  const float* conv1_w   = (const float*)d_in[1];
  const float* conv1_b   = (const float*)d_in[2];
  const float* bn1_g     = (const float*)d_in[3];
  const float* bn1_b     = (const float*)d_in[4];
  const float* convo_w   = (const float*)d_in[5];
  const float* convo_b   = (const float*)d_in[6];
  const float* qkv_w     = (const float*)d_in[7];
  const float* qkv_b     = (const float*)d_in[8];
  const float* attno_w   = (const float*)d_in[9];
  const float* attno_b   = (const float*)d_in[10];
  const float* key_rel_h = (const float*)d_in[11];
  const float* key_rel_w = (const float*)d_in[12];
  const float* fc_w      = (const float*)d_in[13];
  const float* fc_b      = (const float*)d_in[14];
  float* out = (float*)d_out;

  cudaFuncSetAttribute(attn_kernel, cudaFuncAttributeMaxDynamicSharedMemorySize, ATTN_SMEM);

  conv1_kernel<<<dim3(64, 16), 256>>>(x, conv1_w, conv1_b);     // #0
  bnrelu_kernel<<<dim3(64, 16), 1024>>>(bn1_g, bn1_b);          // #1
  qkv_kernel<<<dim3(1, 8, 16), 256>>>(qkv_w, qkv_b);            // #2
  attn_kernel<<<dim3(4, 4, 16), 128, ATTN_SMEM>>>(key_rel_h, key_rel_w);  // #3 (profiled)
  pool_kernel<<<dim3(4, 16), 1024>>>(convo_w, convo_b);         // #4
  fc_kernel<<<16, 128>>>(attno_w, attno_b, fc_w, fc_b, out);    // #5
}

// round 12
// speedup vs baseline: 1.3910x; 1.1229x over previous
#include <cuda_runtime.h>
#include <cuda_fp16.h>

typedef unsigned long long u64;
typedef unsigned u32;

// ---------------- scratch (device globals; no allocation) ----------------
__device__ float g_pre[16*64*1024];     // conv1 out, then h (in-place)
__device__ float2 g_bstats[64*16];      // per (oc,b) partial {sum, sumsq}
__device__ float g_S[16*64*9];          // 9 shifted window sums per (b, in-ch)
__device__ float g_Q[16*4*1024*10];
__device__ float g_KV[16*4*1024*20];    // interleaved K(10) | V(10) per key
__device__ float g_attn[16*4*1024*10];  // normalized attention output
__device__ float g_pooled[16*88];
__device__ float g_means[16*40];

__device__ __forceinline__ float wred(float v) {
  #pragma unroll
  for (int o = 16; o; o >>= 1) v += __shfl_down_sync(0xffffffffu, v, o);
  return v;
}
__device__ __forceinline__ float ex2f(float x) {
  float y; asm("ex2.approx.f32 %0, %1;" : "=f"(y) : "f"(x)); return y;
}
// pack two f32 -> f16x2 (lo in low half)
__device__ __forceinline__ u32 f16x2(float lo, float hi) {
  u32 r; asm("cvt.rn.f16x2.f32 %0, %1, %2;" : "=r"(r) : "f"(hi), "f"(lo)); return r;
}
// D += A*B (m16n8k16, f16 in, f32 acc), D/C in-place
__device__ __forceinline__ void mma_acc(float& d0, float& d1, float& d2, float& d3,
                                        u32 a0, u32 a1, u32 a2, u32 a3,
                                        u32 b0, u32 b1) {
  asm volatile(
    "mma.sync.aligned.m16n8k16.row.col.f32.f16.f16.f32 "
    "{%0,%1,%2,%3}, {%4,%5,%6,%7}, {%8,%9}, {%0,%1,%2,%3};"
    : "+f"(d0), "+f"(d1), "+f"(d2), "+f"(d3)
    : "r"(a0), "r"(a1), "r"(a2), "r"(a3), "r"(b0), "r"(b1));
}

// ---------------- K0: conv1 3x3 (3->64) SAME + per-block BN partial stats ----------------
__global__ void __launch_bounds__(256) conv1_kernel(const float* __restrict__ x,
                                                    const float* __restrict__ w,
                                                    const float* __restrict__ bias) {
  int t = threadIdx.x;
  int oc = blockIdx.x, b = blockIdx.y;
  int p0 = t * 4;
  int y = p0 >> 5, x0 = p0 & 31;
  float w_[27];
  #pragma unroll
  for (int i = 0; i < 27; i++) w_[i] = __ldg(&w[oc * 27 + i]);
  float bv = __ldg(&bias[oc]);
  float a0 = bv, a1 = bv, a2 = bv, a3 = bv;
  #pragma unroll
  for (int ic = 0; ic < 3; ic++) {
    const float* base = x + (b * 3 + ic) * 1024;
    #pragma unroll
    for (int ky = 0; ky < 3; ky++) {
      int iy = y + ky - 1;
      if (iy < 0 || iy > 31) continue;
      const float* row = base + iy * 32;
      float r[6];
      #pragma unroll
      for (int dx = 0; dx < 6; dx++) {
        int c = x0 - 1 + dx;
        r[dx] = (c >= 0 && c < 32) ? __ldg(&row[c]) : 0.f;
      }
      #pragma unroll
      for (int kx = 0; kx < 3; kx++) {
        float wv = w_[ic * 9 + ky * 3 + kx];
        a0 = fmaf(wv, r[kx],     a0);
        a1 = fmaf(wv, r[kx + 1], a1);
        a2 = fmaf(wv, r[kx + 2], a2);
        a3 = fmaf(wv, r[kx + 3], a3);
      }
    }
  }
  *(float4*)(g_pre + (b * 64 + oc) * 1024 + p0) = make_float4(a0, a1, a2, a3);

  float s  = a0 + a1 + a2 + a3;
  float sq = fmaf(a0, a0, fmaf(a1, a1, fmaf(a2, a2, a3 * a3)));
  s = wred(s); sq = wred(sq);
  __shared__ float ss[8], s2m[8];
  int warp = t >> 5, lane = t & 31;
  if (lane == 0) { ss[warp] = s; s2m[warp] = sq; }
  __syncthreads();
  if (t == 0) {
    float S = 0.f, Q = 0.f;
    #pragma unroll
    for (int i = 0; i < 8; i++) { S += ss[i]; Q += s2m[i]; }
    g_bstats[oc * 16 + b] = make_float2(S, Q);
  }
}

// ---------------- K1: BN finalize + apply + relu + 9 window sums ----------------
__global__ void bnrelu_kernel(const float* __restrict__ gamma,
                              const float* __restrict__ beta) {
  int c = blockIdx.x, b = blockIdx.y;
  int p = threadIdx.x;                  // 1024 threads
  __shared__ float scb[2];
  if (p < 16) {
    float2 v = g_bstats[c * 16 + p];
    float s = v.x, q = v.y;
    #pragma unroll
    for (int o = 8; o; o >>= 1) {
      s += __shfl_down_sync(0xffffu, s, o, 16);
      q += __shfl_down_sync(0xffffu, q, o, 16);
    }
    if (p == 0) {
      float mean = s * (1.f / 16384.f);
      float var  = q * (1.f / 16384.f) - mean * mean;
      float sc = __ldg(&gamma[c]) * rsqrtf(var + 1e-5f);
      scb[0] = sc;
      scb[1] = __ldg(&beta[c]) - mean * sc;
    }
  }
  __syncthreads();

  int y = p >> 5, xx = p & 31;
  int idx = (b * 64 + c) * 1024 + p;
  float v = fmaxf(fmaf(g_pre[idx], scb[0], scb[1]), 0.f);
  g_pre[idx] = v;

  float t = v;
  float r0  = (y == 0)  ? v : 0.f;
  float r31 = (y == 31) ? v : 0.f;
  float c0  = (xx == 0)  ? v : 0.f;
  float c31 = (xx == 31) ? v : 0.f;

  __shared__ float red[32][5];
  __shared__ float corn[4];
  if (p == 0)    corn[0] = v;
  if (p == 31)   corn[1] = v;
  if (p == 992)  corn[2] = v;
  if (p == 1023) corn[3] = v;

  t = wred(t); r0 = wred(r0); r31 = wred(r31); c0 = wred(c0); c31 = wred(c31);
  int warp = p >> 5, lane = p & 31;
  if (lane == 0) { red[warp][0]=t; red[warp][1]=r0; red[warp][2]=r31; red[warp][3]=c0; red[warp][4]=c31; }
  __syncthreads();
  if (p < 32) {
    float a0 = red[p][0], a1 = red[p][1], a2 = red[p][2], a3 = red[p][3], a4 = red[p][4];
    a0 = wred(a0); a1 = wred(a1); a2 = wred(a2); a3 = wred(a3); a4 = wred(a4);
    if (p == 0) {
      float T = a0, R0 = a1, R31 = a2, C0 = a3, C31 = a4;
      float* Sp = g_S + (b * 64 + c) * 9;
      Sp[0] = T - R31 - C31 + corn[3];
      Sp[1] = T - R31;
      Sp[2] = T - R31 - C0 + corn[2];
      Sp[3] = T - C31;
      Sp[4] = T;
      Sp[5] = T - C0;
      Sp[6] = T - R0 - C31 + corn[1];
      Sp[7] = T - R0;
      Sp[8] = T - R0 - C0 + corn[0];
    }
  }
}

// ---------------- K2: qkv 1x1 conv -> Q (scaled), KV interleaved ----------------
__global__ void __launch_bounds__(256) qkv_kernel(const float* __restrict__ w,
                                                  const float* __restrict__ bias) {
  int tid = threadIdx.x;        // 256
  int b = blockIdx.z;
  int o0 = blockIdx.y * 15;     // 8 groups of 15 output channels
  __shared__ float ws[960];
  __shared__ float bs[15];
  for (int i = tid; i < 960; i += 256) ws[i] = w[o0 * 64 + i];
  if (tid < 15) bs[tid] = bias[o0 + tid];
  __syncthreads();
  int n0 = tid * 4;
  float4 acc[15];
  #pragma unroll
  for (int u = 0; u < 15; u++) { float bv = bs[u]; acc[u] = make_float4(bv, bv, bv, bv); }
  const float* hp = g_pre + b * 64 * 1024 + n0;
  #pragma unroll 2
  for (int i = 0; i < 64; i++) {
    float4 hv = *(const float4*)(hp + i * 1024);
    #pragma unroll
    for (int u = 0; u < 15; u++) {
      float wv = ws[u * 64 + i];
      acc[u].x = fmaf(wv, hv.x, acc[u].x);
      acc[u].y = fmaf(wv, hv.y, acc[u].y);
      acc[u].z = fmaf(wv, hv.z, acc[u].z);
      acc[u].w = fmaf(wv, hv.w, acc[u].w);
    }
  }
  const float QMUL = 0.31622776601683794f * 1.4426950408889634f;  // dkh^-.5 * log2e
  #pragma unroll
  for (int u = 0; u < 15; u++) {
    int o = o0 + u;
    int which = o / 40;
    int r = o - which * 40;
    int head = r / 10, d = r - head * 10;
    int bh = b * 4 + head;
    if (which == 0) {
      float* pb = g_Q + (bh * 1024) * 10 + d;
      pb[(n0 + 0) * 10] = acc[u].x * QMUL;
      pb[(n0 + 1) * 10] = acc[u].y * QMUL;
      pb[(n0 + 2) * 10] = acc[u].z * QMUL;
      pb[(n0 + 3) * 10] = acc[u].w * QMUL;
    } else {
      float* pb = g_KV + (bh * 1024) * 20 + ((which == 1) ? d : 10 + d);
      pb[(n0 + 0) * 20] = acc[u].x;
      pb[(n0 + 1) * 20] = acc[u].y;
      pb[(n0 + 2) * 20] = acc[u].z;
      pb[(n0 + 3) * 20] = acc[u].w;
    }
  }
}

// ---------------- K3: HMMA attention (mma.sync m16n8k16 f16) ----------------
// CTA: 128 queries (8 warps x 16 rows) x full 1024 keys, per bh. grid (8, 64).
// smem: KS [1024][18] f16 | VT [16][1032] f16 | RH [128][33] f32 | RW2 [128][17] float2
//       | KRH 630 f32 | KRW 630 f32
#define KS_OFF  0
#define VT_OFF  36864
#define RH_OFF  69888
#define RW_OFF  86784
#define KRH_OFF 104192
#define KRW_OFF 106712
#define ATTN_SMEM_BYTES 109248

__global__ void __launch_bounds__(256, 2) attn_kernel(const float* __restrict__ krh,
                                                      const float* __restrict__ krw) {
  extern __shared__ char smem[];
  __half* KS   = (__half*)(smem + KS_OFF);
  __half* VT   = (__half*)(smem + VT_OFF);
  float*  RH   = (float*)(smem + RH_OFF);
  float2* RW2  = (float2*)(smem + RW_OFF);
  float*  KRH  = (float*)(smem + KRH_OFF);
  float*  KRW  = (float*)(smem + KRW_OFF);
  int qt = blockIdx.x, bh = blockIdx.y;
  int tid = threadIdx.x;
  int qbase = qt * 128;

  // stage rel tables + K/V (f16, padded)
  for (int i = tid; i < 630; i += 256) { KRH[i] = krh[i]; KRW[i] = krw[i]; }
  for (int k = tid; k < 1024; k += 256) {
    const float4* src = (const float4*)(g_KV + (bh * 1024 + k) * 20);
    float4 v0 = src[0], v1 = src[1], v2 = src[2], v3 = src[3], v4 = src[4];
    u32* kw = (u32*)(KS + k * 18);
    kw[0] = f16x2(v0.x, v0.y); kw[1] = f16x2(v0.z, v0.w);
    kw[2] = f16x2(v1.x, v1.y); kw[3] = f16x2(v1.z, v1.w);
    kw[4] = f16x2(v2.x, v2.y);
    kw[5] = 0u; kw[6] = 0u; kw[7] = 0u; kw[8] = 0u;
    VT[0 * 1032 + k] = __float2half_rn(v2.z);
    VT[1 * 1032 + k] = __float2half_rn(v2.w);
    VT[2 * 1032 + k] = __float2half_rn(v3.x);
    VT[3 * 1032 + k] = __float2half_rn(v3.y);
    VT[4 * 1032 + k] = __float2half_rn(v3.z);
    VT[5 * 1032 + k] = __float2half_rn(v3.w);
    VT[6 * 1032 + k] = __float2half_rn(v4.x);
    VT[7 * 1032 + k] = __float2half_rn(v4.y);
    VT[8 * 1032 + k] = __float2half_rn(v4.z);
    VT[9 * 1032 + k] = __float2half_rn(v4.w);
    #pragma unroll
    for (int d = 10; d < 16; d++) VT[d * 1032 + k] = __ushort_as_half(0);
  }
  __syncthreads();

  // per-query relative-bias tables (log2e domain; q pre-scaled)
  {
    int ql = tid >> 1;
    int n = qbase + ql;
    const float* qp = g_Q + (bh * 1024 + n) * 10;
    float q[10];
    #pragma unroll
    for (int i = 0; i < 10; i++) q[i] = qp[i];
    int yq = n >> 5, xq = n & 31;
    if ((tid & 1) == 0) {
      #pragma unroll 4
      for (int ym = 0; ym < 32; ym++) {
        const float* t = KRH + (ym - yq + 31) * 10;
        float s = q[0] * t[0];
        #pragma unroll
        for (int i = 1; i < 10; i++) s = fmaf(q[i], t[i], s);
        RH[ql * 33 + ym] = s;
      }
    } else {
      #pragma unroll 4
      for (int j = 0; j < 16; j++) {
        const float* t0 = KRW + (2 * j - xq + 31) * 10;
        const float* t1 = t0 + 10;
        float s0 = q[0] * t0[0], s1 = q[0] * t1[0];
        #pragma unroll
        for (int i = 1; i < 10; i++) { s0 = fmaf(q[i], t0[i], s0); s1 = fmaf(q[i], t1[i], s1); }
        RW2[ql * 17 + j] = make_float2(s0, s1);
      }
    }
  }

  // Q fragment (from gmem; dims 10-15 zero)
  int lane = tid & 31, w = tid >> 5;
  int r = lane >> 2, c0 = (lane & 3) * 2;
  int ql_lo = w * 16 + r, ql_hi = ql_lo + 8;
  int n_lo = qbase + ql_lo, n_hi = qbase + ql_hi;
  const float* qlo = g_Q + (bh * 1024 + n_lo) * 10;
  const float* qhi = g_Q + (bh * 1024 + n_hi) * 10;
  u32 aq0 = f16x2(qlo[c0], qlo[c0 + 1]);
  u32 aq1 = f16x2(qhi[c0], qhi[c0 + 1]);
  u32 aq2 = (c0 == 0) ? f16x2(qlo[8], qlo[9]) : 0u;
  u32 aq3 = (c0 == 0) ? f16x2(qhi[8], qhi[9]) : 0u;

  __syncthreads();

  const __half* KSr  = KS + r * 18 + c0;
  const __half* VTlo = VT + r * 1032;
  const __half* VThi = VT + (r + 8) * 1032;
  const float*  RHlo = RH + ql_lo * 33;
  const float*  RHhi = RH + ql_hi * 33;
  const float2* RWlo = RW2 + ql_lo * 17;
  const float2* RWhi = RW2 + ql_hi * 17;

  float D0a = 0.f, D0b = 0.f, D0c = 0.f, D0d = 0.f;
  float D1a = 0.f, D1b = 0.f, D1c = 0.f, D1d = 0.f;
  float l_lo = 0.f, l_hi = 0.f;

  #pragma unroll 2
  for (int ch = 0; ch < 64; ch++) {
    int kb = ch * 16;
    int ym = ch >> 1;
    // QK: two 16x8 tiles (keys kb..kb+7, kb+8..kb+15)
    u32 b00 = *(const u32*)(KSr + kb * 18);
    u32 b01 = *(const u32*)(KSr + kb * 18 + 8);
    u32 b10 = *(const u32*)(KSr + (kb + 8) * 18);
    u32 b11 = *(const u32*)(KSr + (kb + 8) * 18 + 8);
    float s0 = 0.f, s1 = 0.f, s2 = 0.f, s3 = 0.f;
    float s4 = 0.f, s5 = 0.f, s6 = 0.f, s7 = 0.f;
    mma_acc(s0, s1, s2, s3, aq0, aq1, aq2, aq3, b00, b01);
    mma_acc(s4, s5, s6, s7, aq0, aq1, aq2, aq3, b10, b11);
    // biases (ym const per chunk; xm pairs from RW2)
    float rh_lo = RHlo[ym], rh_hi = RHhi[ym];
    int x2 = (ch & 1) * 8 + (lane & 3);
    float2 rwl0 = RWlo[x2],     rwh0 = RWhi[x2];
    float2 rwl1 = RWlo[x2 + 4], rwh1 = RWhi[x2 + 4];
    float e0 = ex2f(s0 + rh_lo + rwl0.x), e1 = ex2f(s1 + rh_lo + rwl0.y);
    float e2 = ex2f(s2 + rh_hi + rwh0.x), e3 = ex2f(s3 + rh_hi + rwh0.y);
    float e4 = ex2f(s4 + rh_lo + rwl1.x), e5 = ex2f(s5 + rh_lo + rwl1.y);
    float e6 = ex2f(s6 + rh_hi + rwh1.x), e7 = ex2f(s7 + rh_hi + rwh1.y);
    l_lo += e0 + e1 + e4 + e5;
    l_hi += e2 + e3 + e6 + e7;
    // P fragment (register reuse: S tiles -> A of PV)
    u32 pa0 = f16x2(e0, e1), pa1 = f16x2(e2, e3);
    u32 pa2 = f16x2(e4, e5), pa3 = f16x2(e6, e7);
    // V fragments: tile dims 0-7 (n=r), tile dims 8-15 (n=r+8)
    u32 vb0 = *(const u32*)(VTlo + kb + c0);
    u32 vb1 = *(const u32*)(VTlo + kb + 8 + c0);
    u32 vb2 = *(const u32*)(VThi + kb + c0);
    u32 vb3 = *(const u32*)(VThi + kb + 8 + c0);
    mma_acc(D0a, D0b, D0c, D0d, pa0, pa1, pa2, pa3, vb0, vb1);
    mma_acc(D1a, D1b, D1c, D1d, pa0, pa1, pa2, pa3, vb2, vb3);
  }

  // row sums across the 4 lanes sharing each row
  l_lo += __shfl_xor_sync(0xffffffffu, l_lo, 1);
  l_lo += __shfl_xor_sync(0xffffffffu, l_lo, 2);
  l_hi += __shfl_xor_sync(0xffffffffu, l_hi, 1);
  l_hi += __shfl_xor_sync(0xffffffffu, l_hi, 2);
  float il = __frcp_rn(l_lo), ih = __frcp_rn(l_hi);

  float* olo = g_attn + (bh * 1024 + n_lo) * 10;
  float* ohi = g_attn + (bh * 1024 + n_hi) * 10;
  *(float2*)(olo + c0) = make_float2(D0a * il, D0b * il);
  *(float2*)(ohi + c0) = make_float2(D0c * ih, D0d * ih);
  if (c0 == 0) {
    *(float2*)(olo + 8) = make_float2(D1a * il, D1b * il);
    *(float2*)(ohi + 8) = make_float2(D1c * ih, D1d * ih);
  }
}

// ---------------- K4: pool (warp per task) ----------------
__global__ void __launch_bounds__(1024) pool_kernel(const float* __restrict__ convo_w,
                                                    const float* __restrict__ convo_b) {
  int q = blockIdx.x, b = blockIdx.y;     // q 0..3
  int tid = threadIdx.x;
  int warp = tid >> 5, lane = tid & 31;
  int task = q * 32 + warp;                // 0..127
  __shared__ float Ssm[576];
  for (int i = tid; i < 576; i += 1024) Ssm[i] = g_S[b * 576 + i];
  __syncthreads();
  if (task < 88) {
    const float* wp = convo_w + task * 576;
    float acc = 0.f;
    #pragma unroll
    for (int i = lane; i < 576; i += 32) acc = fmaf(__ldg(&wp[i]), Ssm[i], acc);
    acc = wred(acc);
    if (lane == 0) g_pooled[b * 88 + task] = __ldg(&convo_b[task]) + acc * (1.f / 1024.f);
  } else {
    int c = task - 88;
    const float* p = g_attn + b * 40960 + c * 1024;
    float s = 0.f;
    #pragma unroll 8
    for (int j = lane; j < 1024; j += 32) s += p[j];
    s = wred(s);
    if (lane == 0) g_means[b * 40 + c] = s * (1.f / 1024.f);
  }
}

// ---------------- K5: attno + fc ----------------
__global__ void __launch_bounds__(128) fc_kernel(const float* __restrict__ attno_w,
                                                 const float* __restrict__ attno_b,
                                                 const float* __restrict__ fc_w,
                                                 const float* __restrict__ fc_b,
                                                 float* __restrict__ out) {
  int b = blockIdx.x, tid = threadIdx.x;  // 128
  __shared__ float pooled[88], means[40], pa[40];
  if (tid < 88) pooled[tid] = g_pooled[b * 88 + tid];
  if (tid < 40) means[tid] = g_means[b * 40 + tid];
  __syncthreads();
  if (tid < 40) {
    float acc = __ldg(&attno_b[tid]);
    #pragma unroll 4
    for (int c = 0; c < 40; c++) acc = fmaf(__ldg(&attno_w[tid * 40 + c]), means[c], acc);
    pa[tid] = acc;
  }
  __syncthreads();
  if (tid < 100) {
    float acc = __ldg(&fc_b[tid]);
    const float* wp = fc_w + tid * 128;
    #pragma unroll 4
    for (int c = 0; c < 88; c++) acc = fmaf(__ldg(&wp[c]), pooled[c], acc);
    #pragma unroll 4
    for (int c = 0; c < 40; c++) acc = fmaf(__ldg(&wp[88 + c]), pa[c], acc);
    out[b * 100 + tid] = acc;
  }
}

// ---------------- launch ----------------
extern "C" void kernel_launch(void* const* d_in, const int* in_sizes, int n_in,
                              void* d_out, int out_size) {
  const float* x         = (const float*)d_in[0];
  const float* conv1_w   = (const float*)d_in[1];
  const float* conv1_b   = (const float*)d_in[2];
  const float* bn1_g     = (const float*)d_in[3];
  const float* bn1_b     = (const float*)d_in[4];
  const float* convo_w   = (const float*)d_in[5];
  const float* convo_b   = (const float*)d_in[6];
  const float* qkv_w     = (const float*)d_in[7];
  const float* qkv_b     = (const float*)d_in[8];
  const float* attno_w   = (const float*)d_in[9];
  const float* attno_b   = (const float*)d_in[10];
  const float* key_rel_h = (const float*)d_in[11];
  const float* key_rel_w = (const float*)d_in[12];
  const float* fc_w      = (const float*)d_in[13];
  const float* fc_b      = (const float*)d_in[14];
  float* out = (float*)d_out;

  cudaFuncSetAttribute(attn_kernel, cudaFuncAttributeMaxDynamicSharedMemorySize, ATTN_SMEM_BYTES);

  conv1_kernel<<<dim3(64, 16), 256>>>(x, conv1_w, conv1_b);     // #0
  bnrelu_kernel<<<dim3(64, 16), 1024>>>(bn1_g, bn1_b);          // #1
  qkv_kernel<<<dim3(1, 8, 16), 256>>>(qkv_w, qkv_b);            // #2
  attn_kernel<<<dim3(8, 64), 256, ATTN_SMEM_BYTES>>>(key_rel_h, key_rel_w);  // #3 (profiled)
  pool_kernel<<<dim3(4, 16), 1024>>>(convo_w, convo_b);         // #4
  fc_kernel<<<16, 128>>>(attno_w, attno_b, fc_w, fc_b, out);    // #5
}

// round 13
// speedup vs baseline: 1.6959x; 1.2192x over previous
#include <cuda_runtime.h>
#include <cuda_fp16.h>

typedef unsigned long long u64;
typedef unsigned u32;

// ---------------- scratch (device globals; no allocation) ----------------
__device__ float g_pre[16*64*1024];     // conv1 out, then h (in-place)
__device__ float2 g_bstats[64*16];      // per (oc,b) partial {sum, sumsq}
__device__ float g_S[16*64*9];          // 9 shifted window sums per (b, in-ch)
__device__ float g_Q[16*4*1024*10];
__device__ float g_KV[16*4*1024*20];    // interleaved K(10) | V(10) per key
__device__ float g_attn[16*4*1024*10];  // normalized attention output
__device__ float g_pooled[16*88];
__device__ float g_means[16*40];

__device__ __forceinline__ float wred(float v) {
  #pragma unroll
  for (int o = 16; o; o >>= 1) v += __shfl_down_sync(0xffffffffu, v, o);
  return v;
}
__device__ __forceinline__ float ex2f(float x) {
  float y; asm("ex2.approx.f32 %0, %1;" : "=f"(y) : "f"(x)); return y;
}
// pack two f32 -> f16x2 (lo in low half)
__device__ __forceinline__ u32 f16x2(float lo, float hi) {
  u32 r; asm("cvt.rn.f16x2.f32 %0, %1, %2;" : "=r"(r) : "f"(hi), "f"(lo)); return r;
}
// D += A*B (m16n8k16, f16 in, f32 acc), D/C in-place
__device__ __forceinline__ void mma_acc(float& d0, float& d1, float& d2, float& d3,
                                        u32 a0, u32 a1, u32 a2, u32 a3,
                                        u32 b0, u32 b1) {
  asm volatile(
    "mma.sync.aligned.m16n8k16.row.col.f32.f16.f16.f32 "
    "{%0,%1,%2,%3}, {%4,%5,%6,%7}, {%8,%9}, {%0,%1,%2,%3};"
    : "+f"(d0), "+f"(d1), "+f"(d2), "+f"(d3)
    : "r"(a0), "r"(a1), "r"(a2), "r"(a3), "r"(b0), "r"(b1));
}

// ---------------- K0: conv1 3x3 (3->64) SAME + per-block BN partial stats ----------------
__global__ void __launch_bounds__(256) conv1_kernel(const float* __restrict__ x,
                                                    const float* __restrict__ w,
                                                    const float* __restrict__ bias) {
  int t = threadIdx.x;
  int oc = blockIdx.x, b = blockIdx.y;
  int p0 = t * 4;
  int y = p0 >> 5, x0 = p0 & 31;
  float w_[27];
  #pragma unroll
  for (int i = 0; i < 27; i++) w_[i] = __ldg(&w[oc * 27 + i]);
  float bv = __ldg(&bias[oc]);
  float a0 = bv, a1 = bv, a2 = bv, a3 = bv;
  #pragma unroll
  for (int ic = 0; ic < 3; ic++) {
    const float* base = x + (b * 3 + ic) * 1024;
    #pragma unroll
    for (int ky = 0; ky < 3; ky++) {
      int iy = y + ky - 1;
      if (iy < 0 || iy > 31) continue;
      const float* row = base + iy * 32;
      float r[6];
      #pragma unroll
      for (int dx = 0; dx < 6; dx++) {
        int c = x0 - 1 + dx;
        r[dx] = (c >= 0 && c < 32) ? __ldg(&row[c]) : 0.f;
      }
      #pragma unroll
      for (int kx = 0; kx < 3; kx++) {
        float wv = w_[ic * 9 + ky * 3 + kx];
        a0 = fmaf(wv, r[kx],     a0);
        a1 = fmaf(wv, r[kx + 1], a1);
        a2 = fmaf(wv, r[kx + 2], a2);
        a3 = fmaf(wv, r[kx + 3], a3);
      }
    }
  }
  *(float4*)(g_pre + (b * 64 + oc) * 1024 + p0) = make_float4(a0, a1, a2, a3);

  float s  = a0 + a1 + a2 + a3;
  float sq = fmaf(a0, a0, fmaf(a1, a1, fmaf(a2, a2, a3 * a3)));
  s = wred(s); sq = wred(sq);
  __shared__ float ss[8], s2m[8];
  int warp = t >> 5, lane = t & 31;
  if (lane == 0) { ss[warp] = s; s2m[warp] = sq; }
  __syncthreads();
  if (t == 0) {
    float S = 0.f, Q = 0.f;
    #pragma unroll
    for (int i = 0; i < 8; i++) { S += ss[i]; Q += s2m[i]; }
    g_bstats[oc * 16 + b] = make_float2(S, Q);
  }
}

// ---------------- K1: BN finalize + apply + relu + 9 window sums ----------------
__global__ void bnrelu_kernel(const float* __restrict__ gamma,
                              const float* __restrict__ beta) {
  int c = blockIdx.x, b = blockIdx.y;
  int p = threadIdx.x;                  // 1024 threads
  __shared__ float scb[2];
  if (p < 16) {
    float2 v = g_bstats[c * 16 + p];
    float s = v.x, q = v.y;
    #pragma unroll
    for (int o = 8; o; o >>= 1) {
      s += __shfl_down_sync(0xffffu, s, o, 16);
      q += __shfl_down_sync(0xffffu, q, o, 16);
    }
    if (p == 0) {
      float mean = s * (1.f / 16384.f);
      float var  = q * (1.f / 16384.f) - mean * mean;
      float sc = __ldg(&gamma[c]) * rsqrtf(var + 1e-5f);
      scb[0] = sc;
      scb[1] = __ldg(&beta[c]) - mean * sc;
    }
  }
  __syncthreads();

  int y = p >> 5, xx = p & 31;
  int idx = (b * 64 + c) * 1024 + p;
  float v = fmaxf(fmaf(g_pre[idx], scb[0], scb[1]), 0.f);
  g_pre[idx] = v;

  float t = v;
  float r0  = (y == 0)  ? v : 0.f;
  float r31 = (y == 31) ? v : 0.f;
  float c0  = (xx == 0)  ? v : 0.f;
  float c31 = (xx == 31) ? v : 0.f;

  __shared__ float red[32][5];
  __shared__ float corn[4];
  if (p == 0)    corn[0] = v;
  if (p == 31)   corn[1] = v;
  if (p == 992)  corn[2] = v;
  if (p == 1023) corn[3] = v;

  t = wred(t); r0 = wred(r0); r31 = wred(r31); c0 = wred(c0); c31 = wred(c31);
  int warp = p >> 5, lane = p & 31;
  if (lane == 0) { red[warp][0]=t; red[warp][1]=r0; red[warp][2]=r31; red[warp][3]=c0; red[warp][4]=c31; }
  __syncthreads();
  if (p < 32) {
    float a0 = red[p][0], a1 = red[p][1], a2 = red[p][2], a3 = red[p][3], a4 = red[p][4];
    a0 = wred(a0); a1 = wred(a1); a2 = wred(a2); a3 = wred(a3); a4 = wred(a4);
    if (p == 0) {
      float T = a0, R0 = a1, R31 = a2, C0 = a3, C31 = a4;
      float* Sp = g_S + (b * 64 + c) * 9;
      Sp[0] = T - R31 - C31 + corn[3];
      Sp[1] = T - R31;
      Sp[2] = T - R31 - C0 + corn[2];
      Sp[3] = T - C31;
      Sp[4] = T;
      Sp[5] = T - C0;
      Sp[6] = T - R0 - C31 + corn[1];
      Sp[7] = T - R0;
      Sp[8] = T - R0 - C0 + corn[0];
    }
  }
}

// ---------------- K2: qkv 1x1 conv -> Q (scaled), KV interleaved ----------------
__global__ void __launch_bounds__(256) qkv_kernel(const float* __restrict__ w,
                                                  const float* __restrict__ bias) {
  int tid = threadIdx.x;        // 256
  int b = blockIdx.z;
  int o0 = blockIdx.y * 15;     // 8 groups of 15 output channels
  __shared__ float ws[960];
  __shared__ float bs[15];
  for (int i = tid; i < 960; i += 256) ws[i] = w[o0 * 64 + i];
  if (tid < 15) bs[tid] = bias[o0 + tid];
  __syncthreads();
  int n0 = tid * 4;
  float4 acc[15];
  #pragma unroll
  for (int u = 0; u < 15; u++) { float bv = bs[u]; acc[u] = make_float4(bv, bv, bv, bv); }
  const float* hp = g_pre + b * 64 * 1024 + n0;
  #pragma unroll 2
  for (int i = 0; i < 64; i++) {
    float4 hv = *(const float4*)(hp + i * 1024);
    #pragma unroll
    for (int u = 0; u < 15; u++) {
      float wv = ws[u * 64 + i];
      acc[u].x = fmaf(wv, hv.x, acc[u].x);
      acc[u].y = fmaf(wv, hv.y, acc[u].y);
      acc[u].z = fmaf(wv, hv.z, acc[u].z);
      acc[u].w = fmaf(wv, hv.w, acc[u].w);
    }
  }
  const float QMUL = 0.31622776601683794f * 1.4426950408889634f;  // dkh^-.5 * log2e
  #pragma unroll
  for (int u = 0; u < 15; u++) {
    int o = o0 + u;
    int which = o / 40;
    int r = o - which * 40;
    int head = r / 10, d = r - head * 10;
    int bh = b * 4 + head;
    if (which == 0) {
      float* pb = g_Q + (bh * 1024) * 10 + d;
      pb[(n0 + 0) * 10] = acc[u].x * QMUL;
      pb[(n0 + 1) * 10] = acc[u].y * QMUL;
      pb[(n0 + 2) * 10] = acc[u].z * QMUL;
      pb[(n0 + 3) * 10] = acc[u].w * QMUL;
    } else {
      float* pb = g_KV + (bh * 1024) * 20 + ((which == 1) ? d : 10 + d);
      pb[(n0 + 0) * 20] = acc[u].x;
      pb[(n0 + 1) * 20] = acc[u].y;
      pb[(n0 + 2) * 20] = acc[u].z;
      pb[(n0 + 3) * 20] = acc[u].w;
    }
  }
}

// ---------------- K3: HMMA attention (mma.sync m16n8k16 f16) ----------------
// CTA: 128 queries (8 warps x 16 rows) x full 1024 keys, per bh. grid (8, 64).
// smem: KS [1024][18] f16 | VT [16][1032] f16 | RH [128][33] f32 | RW2 [128][17] float2
//       | KRH 630 f32 | KRW 630 f32
#define KS_OFF  0
#define VT_OFF  36864
#define RH_OFF  69888
#define RW_OFF  86784
#define KRH_OFF 104192
#define KRW_OFF 106712
#define ATTN_SMEM_BYTES 109248

// one 16-key chunk; biases pre-combined (rh+rw) per tile element
#define CHUNK(kb, bl0x, bl0y, bh0x, bh0y, bl1x, bl1y, bh1x, bh1y) do { \
  u32 b00 = *(const u32*)(KSr + (kb) * 18); \
  u32 b01 = *(const u32*)(KSr + (kb) * 18 + 8); \
  u32 b10 = *(const u32*)(KSr + ((kb) + 8) * 18); \
  u32 b11 = *(const u32*)(KSr + ((kb) + 8) * 18 + 8); \
  float s0 = 0.f, s1 = 0.f, s2 = 0.f, s3 = 0.f; \
  float s4 = 0.f, s5 = 0.f, s6 = 0.f, s7 = 0.f; \
  mma_acc(s0, s1, s2, s3, aq0, aq1, aq2, aq3, b00, b01); \
  mma_acc(s4, s5, s6, s7, aq0, aq1, aq2, aq3, b10, b11); \
  float e0 = ex2f(s0 + (bl0x)), e1 = ex2f(s1 + (bl0y)); \
  float e2 = ex2f(s2 + (bh0x)), e3 = ex2f(s3 + (bh0y)); \
  float e4 = ex2f(s4 + (bl1x)), e5 = ex2f(s5 + (bl1y)); \
  float e6 = ex2f(s6 + (bh1x)), e7 = ex2f(s7 + (bh1y)); \
  l_lo += e0 + e1 + e4 + e5; \
  l_hi += e2 + e3 + e6 + e7; \
  u32 pa0 = f16x2(e0, e1), pa1 = f16x2(e2, e3); \
  u32 pa2 = f16x2(e4, e5), pa3 = f16x2(e6, e7); \
  u32 vb0 = *(const u32*)(VTlo + (kb) + c0); \
  u32 vb1 = *(const u32*)(VTlo + (kb) + 8 + c0); \
  u32 vb2 = *(const u32*)(VThi + (kb) + c0); \
  u32 vb3 = *(const u32*)(VThi + (kb) + 8 + c0); \
  mma_acc(D0a, D0b, D0c, D0d, pa0, pa1, pa2, pa3, vb0, vb1); \
  mma_acc(D1a, D1b, D1c, D1d, pa0, pa1, pa2, pa3, vb2, vb3); \
} while (0)

__global__ void __launch_bounds__(256, 2) attn_kernel(const float* __restrict__ krh,
                                                      const float* __restrict__ krw) {
  extern __shared__ char smem[];
  __half* KS   = (__half*)(smem + KS_OFF);
  __half* VT   = (__half*)(smem + VT_OFF);
  float*  RH   = (float*)(smem + RH_OFF);
  float2* RW2  = (float2*)(smem + RW_OFF);
  float*  KRH  = (float*)(smem + KRH_OFF);
  float*  KRW  = (float*)(smem + KRW_OFF);
  int qt = blockIdx.x, bh = blockIdx.y;
  int tid = threadIdx.x;
  int qbase = qt * 128;

  // stage rel tables + K/V (f16, padded)
  for (int i = tid; i < 630; i += 256) { KRH[i] = krh[i]; KRW[i] = krw[i]; }
  for (int k = tid; k < 1024; k += 256) {
    const float4* src = (const float4*)(g_KV + (bh * 1024 + k) * 20);
    float4 v0 = src[0], v1 = src[1], v2 = src[2], v3 = src[3], v4 = src[4];
    u32* kw = (u32*)(KS + k * 18);
    kw[0] = f16x2(v0.x, v0.y); kw[1] = f16x2(v0.z, v0.w);
    kw[2] = f16x2(v1.x, v1.y); kw[3] = f16x2(v1.z, v1.w);
    kw[4] = f16x2(v2.x, v2.y);
    kw[5] = 0u; kw[6] = 0u; kw[7] = 0u; kw[8] = 0u;
    VT[0 * 1032 + k] = __float2half_rn(v2.z);
    VT[1 * 1032 + k] = __float2half_rn(v2.w);
    VT[2 * 1032 + k] = __float2half_rn(v3.x);
    VT[3 * 1032 + k] = __float2half_rn(v3.y);
    VT[4 * 1032 + k] = __float2half_rn(v3.z);
    VT[5 * 1032 + k] = __float2half_rn(v3.w);
    VT[6 * 1032 + k] = __float2half_rn(v4.x);
    VT[7 * 1032 + k] = __float2half_rn(v4.y);
    VT[8 * 1032 + k] = __float2half_rn(v4.z);
    VT[9 * 1032 + k] = __float2half_rn(v4.w);
    #pragma unroll
    for (int d = 10; d < 16; d++) VT[d * 1032 + k] = __ushort_as_half(0);
  }
  __syncthreads();

  // per-query relative-bias tables (log2e domain; q pre-scaled)
  {
    int ql = tid >> 1;
    int n = qbase + ql;
    const float* qp = g_Q + (bh * 1024 + n) * 10;
    float q[10];
    #pragma unroll
    for (int i = 0; i < 10; i++) q[i] = qp[i];
    int yq = n >> 5, xq = n & 31;
    if ((tid & 1) == 0) {
      #pragma unroll 4
      for (int ym = 0; ym < 32; ym++) {
        const float* t = KRH + (ym - yq + 31) * 10;
        float s = q[0] * t[0];
        #pragma unroll
        for (int i = 1; i < 10; i++) s = fmaf(q[i], t[i], s);
        RH[ql * 33 + ym] = s;
      }
    } else {
      #pragma unroll 4
      for (int j = 0; j < 16; j++) {
        const float* t0 = KRW + (2 * j - xq + 31) * 10;
        const float* t1 = t0 + 10;
        float s0 = q[0] * t0[0], s1 = q[0] * t1[0];
        #pragma unroll
        for (int i = 1; i < 10; i++) { s0 = fmaf(q[i], t0[i], s0); s1 = fmaf(q[i], t1[i], s1); }
        RW2[ql * 17 + j] = make_float2(s0, s1);
      }
    }
  }

  // Q fragment (from gmem; dims 10-15 zero)
  int lane = tid & 31, w = tid >> 5;
  int r = lane >> 2, c0 = (lane & 3) * 2;
  int ql_lo = w * 16 + r, ql_hi = ql_lo + 8;
  int n_lo = qbase + ql_lo, n_hi = qbase + ql_hi;
  const float* qlo = g_Q + (bh * 1024 + n_lo) * 10;
  const float* qhi = g_Q + (bh * 1024 + n_hi) * 10;
  u32 aq0 = f16x2(qlo[c0], qlo[c0 + 1]);
  u32 aq1 = f16x2(qhi[c0], qhi[c0 + 1]);
  u32 aq2 = (c0 == 0) ? f16x2(qlo[8], qlo[9]) : 0u;
  u32 aq3 = (c0 == 0) ? f16x2(qhi[8], qhi[9]) : 0u;

  __syncthreads();

  const __half* KSr  = KS + r * 18 + c0;
  const __half* VTlo = VT + r * 1032;
  const __half* VThi = VT + (r + 8) * 1032;
  const float*  RHlo = RH + ql_lo * 33;
  const float*  RHhi = RH + ql_hi * 33;

  // hoist this thread's 8 RW2 entries into registers
  int l3 = lane & 3;
  const float2* RWlo = RW2 + ql_lo * 17;
  const float2* RWhi = RW2 + ql_hi * 17;
  float2 wla0 = RWlo[l3],      wla1 = RWlo[l3 + 4];    // even chunk (keys kb..)
  float2 wlb0 = RWlo[l3 + 8],  wlb1 = RWlo[l3 + 12];   // odd chunk
  float2 wha0 = RWhi[l3],      wha1 = RWhi[l3 + 4];
  float2 whb0 = RWhi[l3 + 8],  whb1 = RWhi[l3 + 12];

  float D0a = 0.f, D0b = 0.f, D0c = 0.f, D0d = 0.f;
  float D1a = 0.f, D1b = 0.f, D1c = 0.f, D1d = 0.f;
  float l_lo = 0.f, l_hi = 0.f;

  #pragma unroll 4
  for (int ym = 0; ym < 32; ym++) {
    float rhl = RHlo[ym], rhh = RHhi[ym];
    int kb = ym * 32;
    CHUNK(kb,
          rhl + wla0.x, rhl + wla0.y, rhh + wha0.x, rhh + wha0.y,
          rhl + wla1.x, rhl + wla1.y, rhh + wha1.x, rhh + wha1.y);
    CHUNK(kb + 16,
          rhl + wlb0.x, rhl + wlb0.y, rhh + whb0.x, rhh + whb0.y,
          rhl + wlb1.x, rhl + wlb1.y, rhh + whb1.x, rhh + whb1.y);
  }

  // row sums across the 4 lanes sharing each row
  l_lo += __shfl_xor_sync(0xffffffffu, l_lo, 1);
  l_lo += __shfl_xor_sync(0xffffffffu, l_lo, 2);
  l_hi += __shfl_xor_sync(0xffffffffu, l_hi, 1);
  l_hi += __shfl_xor_sync(0xffffffffu, l_hi, 2);
  float il = __frcp_rn(l_lo), ih = __frcp_rn(l_hi);

  float* olo = g_attn + (bh * 1024 + n_lo) * 10;
  float* ohi = g_attn + (bh * 1024 + n_hi) * 10;
  *(float2*)(olo + c0) = make_float2(D0a * il, D0b * il);
  *(float2*)(ohi + c0) = make_float2(D0c * ih, D0d * ih);
  if (c0 == 0) {
    *(float2*)(olo + 8) = make_float2(D1a * il, D1b * il);
    *(float2*)(ohi + 8) = make_float2(D1c * ih, D1d * ih);
  }
}

// ---------------- K4: pool (warp per task) ----------------
__global__ void __launch_bounds__(1024) pool_kernel(const float* __restrict__ convo_w,
                                                    const float* __restrict__ convo_b) {
  int q = blockIdx.x, b = blockIdx.y;     // q 0..3
  int tid = threadIdx.x;
  int warp = tid >> 5, lane = tid & 31;
  int task = q * 32 + warp;                // 0..127
  __shared__ float Ssm[576];
  for (int i = tid; i < 576; i += 1024) Ssm[i] = g_S[b * 576 + i];
  __syncthreads();
  if (task < 88) {
    const float* wp = convo_w + task * 576;
    float acc = 0.f;
    #pragma unroll
    for (int i = lane; i < 576; i += 32) acc = fmaf(__ldg(&wp[i]), Ssm[i], acc);
    acc = wred(acc);
    if (lane == 0) g_pooled[b * 88 + task] = __ldg(&convo_b[task]) + acc * (1.f / 1024.f);
  } else {
    int c = task - 88;
    const float* p = g_attn + b * 40960 + c * 1024;
    float s = 0.f;
    #pragma unroll 8
    for (int j = lane; j < 1024; j += 32) s += p[j];
    s = wred(s);
    if (lane == 0) g_means[b * 40 + c] = s * (1.f / 1024.f);
  }
}

// ---------------- K5: attno + fc ----------------
__global__ void __launch_bounds__(128) fc_kernel(const float* __restrict__ attno_w,
                                                 const float* __restrict__ attno_b,
                                                 const float* __restrict__ fc_w,
                                                 const float* __restrict__ fc_b,
                                                 float* __restrict__ out) {
  int b = blockIdx.x, tid = threadIdx.x;  // 128
  __shared__ float pooled[88], means[40], pa[40];
  if (tid < 88) pooled[tid] = g_pooled[b * 88 + tid];
  if (tid < 40) means[tid] = g_means[b * 40 + tid];
  __syncthreads();
  if (tid < 40) {
    float acc = __ldg(&attno_b[tid]);
    #pragma unroll 4
    for (int c = 0; c < 40; c++) acc = fmaf(__ldg(&attno_w[tid * 40 + c]), means[c], acc);
    pa[tid] = acc;
  }
  __syncthreads();
  if (tid < 100) {
    float acc = __ldg(&fc_b[tid]);
    const float* wp = fc_w + tid * 128;
    #pragma unroll 4
    for (int c = 0; c < 88; c++) acc = fmaf(__ldg(&wp[c]), pooled[c], acc);
    #pragma unroll 4
    for (int c = 0; c < 40; c++) acc = fmaf(__ldg(&wp[88 + c]), pa[c], acc);
    out[b * 100 + tid] = acc;
  }
}

// ---------------- launch ----------------
extern "C" void kernel_launch(void* const* d_in, const int* in_sizes, int n_in,
                              void* d_out, int out_size) {
  const float* x         = (const float*)d_in[0];
  const float* conv1_w   = (const float*)d_in[1];
  const float* conv1_b   = (const float*)d_in[2];
  const float* bn1_g     = (const float*)d_in[3];
  const float* bn1_b     = (const float*)d_in[4];
  const float* convo_w   = (const float*)d_in[5];
  const float* convo_b   = (const float*)d_in[6];
  const float* qkv_w     = (const float*)d_in[7];
  const float* qkv_b     = (const float*)d_in[8];
  const float* attno_w   = (const float*)d_in[9];
  const float* attno_b   = (const float*)d_in[10];
  const float* key_rel_h = (const float*)d_in[11];
  const float* key_rel_w = (const float*)d_in[12];
  const float* fc_w      = (const float*)d_in[13];
  const float* fc_b      = (const float*)d_in[14];
  float* out = (float*)d_out;

  cudaFuncSetAttribute(attn_kernel, cudaFuncAttributeMaxDynamicSharedMemorySize, ATTN_SMEM_BYTES);

  conv1_kernel<<<dim3(64, 16), 256>>>(x, conv1_w, conv1_b);     // #0
  bnrelu_kernel<<<dim3(64, 16), 1024>>>(bn1_g, bn1_b);          // #1
  qkv_kernel<<<dim3(1, 8, 16), 256>>>(qkv_w, qkv_b);            // #2
  attn_kernel<<<dim3(8, 64), 256, ATTN_SMEM_BYTES>>>(key_rel_h, key_rel_w);  // #3 (profiled)
  pool_kernel<<<dim3(4, 16), 1024>>>(convo_w, convo_b);         // #4
  fc_kernel<<<16, 128>>>(attno_w, attno_b, fc_w, fc_b, out);    // #5
}

// round 14
// speedup vs baseline: 1.7181x; 1.0131x over previous
#include <cuda_runtime.h>
#include <cuda_fp16.h>

typedef unsigned long long u64;
typedef unsigned u32;

// ---------------- scratch (device globals; no allocation) ----------------
__device__ float g_pre[16*64*1024];     // conv1 out, then h (in-place)
__device__ float2 g_bstats[64*16];      // per (oc,b) partial {sum, sumsq}
__device__ float g_S[16*64*9];          // 9 shifted window sums per (b, in-ch)
__device__ float g_Q[16*4*1024*10];
__device__ float g_KV[16*4*1024*20];    // interleaved K(10) | V(10) per key
__device__ float g_attn[16*4*1024*10];  // normalized attention output

__device__ __forceinline__ float wred(float v) {
  #pragma unroll
  for (int o = 16; o; o >>= 1) v += __shfl_down_sync(0xffffffffu, v, o);
  return v;
}
__device__ __forceinline__ float ex2f(float x) {
  float y; asm("ex2.approx.f32 %0, %1;" : "=f"(y) : "f"(x)); return y;
}
// pack two f32 -> f16x2 (lo in low half)
__device__ __forceinline__ u32 f16x2(float lo, float hi) {
  u32 r; asm("cvt.rn.f16x2.f32 %0, %1, %2;" : "=r"(r) : "f"(hi), "f"(lo)); return r;
}
// D += A*B (m16n8k16, f16 in, f32 acc), D/C in-place
__device__ __forceinline__ void mma_acc(float& d0, float& d1, float& d2, float& d3,
                                        u32 a0, u32 a1, u32 a2, u32 a3,
                                        u32 b0, u32 b1) {
  asm volatile(
    "mma.sync.aligned.m16n8k16.row.col.f32.f16.f16.f32 "
    "{%0,%1,%2,%3}, {%4,%5,%6,%7}, {%8,%9}, {%0,%1,%2,%3};"
    : "+f"(d0), "+f"(d1), "+f"(d2), "+f"(d3)
    : "r"(a0), "r"(a1), "r"(a2), "r"(a3), "r"(b0), "r"(b1));
}

// ---------------- K0: conv1 3x3 (3->64) SAME + per-block BN partial stats ----------------
__global__ void __launch_bounds__(256) conv1_kernel(const float* __restrict__ x,
                                                    const float* __restrict__ w,
                                                    const float* __restrict__ bias) {
  int t = threadIdx.x;
  int oc = blockIdx.x, b = blockIdx.y;
  int p0 = t * 4;
  int y = p0 >> 5, x0 = p0 & 31;
  float w_[27];
  #pragma unroll
  for (int i = 0; i < 27; i++) w_[i] = __ldg(&w[oc * 27 + i]);
  float bv = __ldg(&bias[oc]);
  float a0 = bv, a1 = bv, a2 = bv, a3 = bv;
  #pragma unroll
  for (int ic = 0; ic < 3; ic++) {
    const float* base = x + (b * 3 + ic) * 1024;
    #pragma unroll
    for (int ky = 0; ky < 3; ky++) {
      int iy = y + ky - 1;
      if (iy < 0 || iy > 31) continue;
      const float* row = base + iy * 32;
      float r[6];
      #pragma unroll
      for (int dx = 0; dx < 6; dx++) {
        int c = x0 - 1 + dx;
        r[dx] = (c >= 0 && c < 32) ? __ldg(&row[c]) : 0.f;
      }
      #pragma unroll
      for (int kx = 0; kx < 3; kx++) {
        float wv = w_[ic * 9 + ky * 3 + kx];
        a0 = fmaf(wv, r[kx],     a0);
        a1 = fmaf(wv, r[kx + 1], a1);
        a2 = fmaf(wv, r[kx + 2], a2);
        a3 = fmaf(wv, r[kx + 3], a3);
      }
    }
  }
  *(float4*)(g_pre + (b * 64 + oc) * 1024 + p0) = make_float4(a0, a1, a2, a3);

  float s  = a0 + a1 + a2 + a3;
  float sq = fmaf(a0, a0, fmaf(a1, a1, fmaf(a2, a2, a3 * a3)));
  s = wred(s); sq = wred(sq);
  __shared__ float ss[8], s2m[8];
  int warp = t >> 5, lane = t & 31;
  if (lane == 0) { ss[warp] = s; s2m[warp] = sq; }
  __syncthreads();
  if (t == 0) {
    float S = 0.f, Q = 0.f;
    #pragma unroll
    for (int i = 0; i < 8; i++) { S += ss[i]; Q += s2m[i]; }
    g_bstats[oc * 16 + b] = make_float2(S, Q);
  }
}

// ---------------- K1: BN finalize + apply + relu + 9 window sums ----------------
__global__ void bnrelu_kernel(const float* __restrict__ gamma,
                              const float* __restrict__ beta) {
  int c = blockIdx.x, b = blockIdx.y;
  int p = threadIdx.x;                  // 1024 threads
  __shared__ float scb[2];
  if (p < 16) {
    float2 v = g_bstats[c * 16 + p];
    float s = v.x, q = v.y;
    #pragma unroll
    for (int o = 8; o; o >>= 1) {
      s += __shfl_down_sync(0xffffu, s, o, 16);
      q += __shfl_down_sync(0xffffu, q, o, 16);
    }
    if (p == 0) {
      float mean = s * (1.f / 16384.f);
      float var  = q * (1.f / 16384.f) - mean * mean;
      float sc = __ldg(&gamma[c]) * rsqrtf(var + 1e-5f);
      scb[0] = sc;
      scb[1] = __ldg(&beta[c]) - mean * sc;
    }
  }
  __syncthreads();

  int y = p >> 5, xx = p & 31;
  int idx = (b * 64 + c) * 1024 + p;
  float v = fmaxf(fmaf(g_pre[idx], scb[0], scb[1]), 0.f);
  g_pre[idx] = v;

  float t = v;
  float r0  = (y == 0)  ? v : 0.f;
  float r31 = (y == 31) ? v : 0.f;
  float c0  = (xx == 0)  ? v : 0.f;
  float c31 = (xx == 31) ? v : 0.f;

  __shared__ float red[32][5];
  __shared__ float corn[4];
  if (p == 0)    corn[0] = v;
  if (p == 31)   corn[1] = v;
  if (p == 992)  corn[2] = v;
  if (p == 1023) corn[3] = v;

  t = wred(t); r0 = wred(r0); r31 = wred(r31); c0 = wred(c0); c31 = wred(c31);
  int warp = p >> 5, lane = p & 31;
  if (lane == 0) { red[warp][0]=t; red[warp][1]=r0; red[warp][2]=r31; red[warp][3]=c0; red[warp][4]=c31; }
  __syncthreads();
  if (p < 32) {
    float a0 = red[p][0], a1 = red[p][1], a2 = red[p][2], a3 = red[p][3], a4 = red[p][4];
    a0 = wred(a0); a1 = wred(a1); a2 = wred(a2); a3 = wred(a3); a4 = wred(a4);
    if (p == 0) {
      float T = a0, R0 = a1, R31 = a2, C0 = a3, C31 = a4;
      float* Sp = g_S + (b * 64 + c) * 9;
      Sp[0] = T - R31 - C31 + corn[3];
      Sp[1] = T - R31;
      Sp[2] = T - R31 - C0 + corn[2];
      Sp[3] = T - C31;
      Sp[4] = T;
      Sp[5] = T - C0;
      Sp[6] = T - R0 - C31 + corn[1];
      Sp[7] = T - R0;
      Sp[8] = T - R0 - C0 + corn[0];
    }
  }
}

// ---------------- K2: qkv 1x1 conv -> Q (scaled), KV interleaved ----------------
__global__ void __launch_bounds__(256) qkv_kernel(const float* __restrict__ w,
                                                  const float* __restrict__ bias) {
  int tid = threadIdx.x;        // 256
  int b = blockIdx.z;
  int o0 = blockIdx.y * 15;     // 8 groups of 15 output channels
  __shared__ float ws[960];
  __shared__ float bs[15];
  for (int i = tid; i < 960; i += 256) ws[i] = w[o0 * 64 + i];
  if (tid < 15) bs[tid] = bias[o0 + tid];
  __syncthreads();
  int n0 = tid * 4;
  float4 acc[15];
  #pragma unroll
  for (int u = 0; u < 15; u++) { float bv = bs[u]; acc[u] = make_float4(bv, bv, bv, bv); }
  const float* hp = g_pre + b * 64 * 1024 + n0;
  #pragma unroll 2
  for (int i = 0; i < 64; i++) {
    float4 hv = *(const float4*)(hp + i * 1024);
    #pragma unroll
    for (int u = 0; u < 15; u++) {
      float wv = ws[u * 64 + i];
      acc[u].x = fmaf(wv, hv.x, acc[u].x);
      acc[u].y = fmaf(wv, hv.y, acc[u].y);
      acc[u].z = fmaf(wv, hv.z, acc[u].z);
      acc[u].w = fmaf(wv, hv.w, acc[u].w);
    }
  }
  const float QMUL = 0.31622776601683794f * 1.4426950408889634f;  // dkh^-.5 * log2e
  #pragma unroll
  for (int u = 0; u < 15; u++) {
    int o = o0 + u;
    int which = o / 40;
    int r = o - which * 40;
    int head = r / 10, d = r - head * 10;
    int bh = b * 4 + head;
    if (which == 0) {
      float* pb = g_Q + (bh * 1024) * 10 + d;
      pb[(n0 + 0) * 10] = acc[u].x * QMUL;
      pb[(n0 + 1) * 10] = acc[u].y * QMUL;
      pb[(n0 + 2) * 10] = acc[u].z * QMUL;
      pb[(n0 + 3) * 10] = acc[u].w * QMUL;
    } else {
      float* pb = g_KV + (bh * 1024) * 20 + ((which == 1) ? d : 10 + d);
      pb[(n0 + 0) * 20] = acc[u].x;
      pb[(n0 + 1) * 20] = acc[u].y;
      pb[(n0 + 2) * 20] = acc[u].z;
      pb[(n0 + 3) * 20] = acc[u].w;
    }
  }
}

// ---------------- K3: HMMA attention (mma.sync m16n8k16 f16) ----------------
// CTA: 128 queries (8 warps x 16 rows) x full 1024 keys, per bh. grid (8, 64).
// KS: [1024][16] f16, per key dims permuted [d0 d1 d8 d9 | d2 d3 0 0 | d4 d5 0 0 | d6 d7 0 0]
//     so each B-fragment pair (b0,b1) is one 8B load.
// VT: [16][1032] f16, keys permuted within 16-groups so (vb0,vb1) is one 8B load.
//     Row 10 = 1.0 (ones): PV MMA col 10 accumulates the softmax denominator for free.
#define KS_OFF  0
#define VT_OFF  32768
#define RH_OFF  65792
#define RW_OFF  82688
#define KRH_OFF 100096
#define KRW_OFF 102616
#define ATTN_SMEM_BYTES 105136

// one 16-key chunk; biases pre-combined per element; denominator via ones-row of VT
#define CHUNK(kb, bl0x, bl0y, bh0x, bh0y, bl1x, bl1y, bh1x, bh1y) do { \
  uint2 kA = *(const uint2*)(KSr + (kb) * 16); \
  uint2 kB = *(const uint2*)(KSr + ((kb) + 8) * 16); \
  float s0 = 0.f, s1 = 0.f, s2 = 0.f, s3 = 0.f; \
  float s4 = 0.f, s5 = 0.f, s6 = 0.f, s7 = 0.f; \
  mma_acc(s0, s1, s2, s3, aq0, aq1, aq2, aq3, kA.x, kA.y); \
  mma_acc(s4, s5, s6, s7, aq0, aq1, aq2, aq3, kB.x, kB.y); \
  float e0 = ex2f(s0 + (bl0x)), e1 = ex2f(s1 + (bl0y)); \
  float e2 = ex2f(s2 + (bh0x)), e3 = ex2f(s3 + (bh0y)); \
  float e4 = ex2f(s4 + (bl1x)), e5 = ex2f(s5 + (bl1y)); \
  float e6 = ex2f(s6 + (bh1x)), e7 = ex2f(s7 + (bh1y)); \
  u32 pa0 = f16x2(e0, e1), pa1 = f16x2(e2, e3); \
  u32 pa2 = f16x2(e4, e5), pa3 = f16x2(e6, e7); \
  uint2 vA = *(const uint2*)(VTlo + (kb)); \
  uint2 vB = *(const uint2*)(VThi + (kb)); \
  mma_acc(D0a, D0b, D0c, D0d, pa0, pa1, pa2, pa3, vA.x, vA.y); \
  mma_acc(D1a, D1b, D1c, D1d, pa0, pa1, pa2, pa3, vB.x, vB.y); \
} while (0)

__global__ void __launch_bounds__(256, 2) attn_kernel(const float* __restrict__ krh,
                                                      const float* __restrict__ krw) {
  extern __shared__ char smem[];
  __half* KS   = (__half*)(smem + KS_OFF);
  __half* VT   = (__half*)(smem + VT_OFF);
  float*  RH   = (float*)(smem + RH_OFF);
  float2* RW2  = (float2*)(smem + RW_OFF);
  float*  KRH  = (float*)(smem + KRH_OFF);
  float*  KRW  = (float*)(smem + KRW_OFF);
  int qt = blockIdx.x, bh = blockIdx.y;
  int tid = threadIdx.x;
  int qbase = qt * 128;

  // stage rel tables + K/V (f16, permuted layouts)
  for (int i = tid; i < 630; i += 256) { KRH[i] = krh[i]; KRW[i] = krw[i]; }
  for (int k = tid; k < 1024; k += 256) {
    const float4* src = (const float4*)(g_KV + (bh * 1024 + k) * 20);
    float4 v0 = src[0], v1 = src[1], v2 = src[2], v3 = src[3], v4 = src[4];
    // K dims permuted: [d0d1][d8d9][d2d3][0][d4d5][0][d6d7][0]
    u32* kw = (u32*)(KS + k * 16);
    kw[0] = f16x2(v0.x, v0.y); kw[1] = f16x2(v2.x, v2.y);
    kw[2] = f16x2(v0.z, v0.w); kw[3] = 0u;
    kw[4] = f16x2(v1.x, v1.y); kw[5] = 0u;
    kw[6] = f16x2(v1.z, v1.w); kw[7] = 0u;
    // V transposed, key-permuted within 16-group; row 10 = ones (denominator)
    int wk = k & 15, p = wk >> 1, e = wk & 1;
    int pk = (k & ~15) + ((((((p & 3) << 1) | (p >> 2)) << 1) | e));
    VT[0 * 1032 + pk] = __float2half_rn(v2.z);
    VT[1 * 1032 + pk] = __float2half_rn(v2.w);
    VT[2 * 1032 + pk] = __float2half_rn(v3.x);
    VT[3 * 1032 + pk] = __float2half_rn(v3.y);
    VT[4 * 1032 + pk] = __float2half_rn(v3.z);
    VT[5 * 1032 + pk] = __float2half_rn(v3.w);
    VT[6 * 1032 + pk] = __float2half_rn(v4.x);
    VT[7 * 1032 + pk] = __float2half_rn(v4.y);
    VT[8 * 1032 + pk] = __float2half_rn(v4.z);
    VT[9 * 1032 + pk] = __float2half_rn(v4.w);
    VT[10 * 1032 + pk] = __float2half_rn(1.0f);
    #pragma unroll
    for (int d = 11; d < 16; d++) VT[d * 1032 + pk] = __ushort_as_half(0);
  }
  __syncthreads();

  // per-query relative-bias tables (log2e domain; q pre-scaled)
  {
    int ql = tid >> 1;
    int n = qbase + ql;
    const float* qp = g_Q + (bh * 1024 + n) * 10;
    float q[10];
    #pragma unroll
    for (int i = 0; i < 10; i++) q[i] = qp[i];
    int yq = n >> 5, xq = n & 31;
    if ((tid & 1) == 0) {
      #pragma unroll 4
      for (int ym = 0; ym < 32; ym++) {
        const float* t = KRH + (ym - yq + 31) * 10;
        float s = q[0] * t[0];
        #pragma unroll
        for (int i = 1; i < 10; i++) s = fmaf(q[i], t[i], s);
        RH[ql * 33 + ym] = s;
      }
    } else {
      #pragma unroll 4
      for (int j = 0; j < 16; j++) {
        const float* t0 = KRW + (2 * j - xq + 31) * 10;
        const float* t1 = t0 + 10;
        float s0 = q[0] * t0[0], s1 = q[0] * t1[0];
        #pragma unroll
        for (int i = 1; i < 10; i++) { s0 = fmaf(q[i], t0[i], s0); s1 = fmaf(q[i], t1[i], s1); }
        RW2[ql * 17 + j] = make_float2(s0, s1);
      }
    }
  }

  // Q fragment (from gmem; dims 10-15 zero)
  int lane = tid & 31, w = tid >> 5;
  int r = lane >> 2, c0 = (lane & 3) * 2;
  int ql_lo = w * 16 + r, ql_hi = ql_lo + 8;
  int n_lo = qbase + ql_lo, n_hi = qbase + ql_hi;
  const float* qlo = g_Q + (bh * 1024 + n_lo) * 10;
  const float* qhi = g_Q + (bh * 1024 + n_hi) * 10;
  u32 aq0 = f16x2(qlo[c0], qlo[c0 + 1]);
  u32 aq1 = f16x2(qhi[c0], qhi[c0 + 1]);
  u32 aq2 = (c0 == 0) ? f16x2(qlo[8], qlo[9]) : 0u;
  u32 aq3 = (c0 == 0) ? f16x2(qhi[8], qhi[9]) : 0u;

  __syncthreads();

  const __half* KSr  = KS + r * 16 + 4 * (lane & 3);
  const __half* VTlo = VT + r * 1032 + 4 * (lane & 3);
  const __half* VThi = VT + (r + 8) * 1032 + 4 * (lane & 3);
  const float*  RHlo = RH + ql_lo * 33;
  const float*  RHhi = RH + ql_hi * 33;

  // hoist this thread's 8 RW2 entries into registers
  int l3 = lane & 3;
  const float2* RWlo = RW2 + ql_lo * 17;
  const float2* RWhi = RW2 + ql_hi * 17;
  float2 wla0 = RWlo[l3],      wla1 = RWlo[l3 + 4];    // even chunk
  float2 wlb0 = RWlo[l3 + 8],  wlb1 = RWlo[l3 + 12];   // odd chunk
  float2 wha0 = RWhi[l3],      wha1 = RWhi[l3 + 4];
  float2 whb0 = RWhi[l3 + 8],  whb1 = RWhi[l3 + 12];

  float D0a = 0.f, D0b = 0.f, D0c = 0.f, D0d = 0.f;
  float D1a = 0.f, D1b = 0.f, D1c = 0.f, D1d = 0.f;

  #pragma unroll 4
  for (int ym = 0; ym < 32; ym++) {
    float rhl = RHlo[ym], rhh = RHhi[ym];
    int kb = ym * 32;
    CHUNK(kb,
          rhl + wla0.x, rhl + wla0.y, rhh + wha0.x, rhh + wha0.y,
          rhl + wla1.x, rhl + wla1.y, rhh + wha1.x, rhh + wha1.y);
    CHUNK(kb + 16,
          rhl + wlb0.x, rhl + wlb0.y, rhh + whb0.x, rhh + whb0.y,
          rhl + wlb1.x, rhl + wlb1.y, rhh + whb1.x, rhh + whb1.y);
  }

  // denominators live in D1 col 10 (tile col 2 -> lanes with lane&3==1)
  float l_lo = __shfl_sync(0xffffffffu, D1a, (lane & ~3) | 1);
  float l_hi = __shfl_sync(0xffffffffu, D1c, (lane & ~3) | 1);
  float il = __frcp_rn(l_lo), ih = __frcp_rn(l_hi);

  float* olo = g_attn + (bh * 1024 + n_lo) * 10;
  float* ohi = g_attn + (bh * 1024 + n_hi) * 10;
  *(float2*)(olo + c0) = make_float2(D0a * il, D0b * il);
  *(float2*)(ohi + c0) = make_float2(D0c * ih, D0d * ih);
  if (c0 == 0) {
    *(float2*)(olo + 8) = make_float2(D1a * il, D1b * il);
    *(float2*)(ohi + 8) = make_float2(D1c * ih, D1d * ih);
  }
}

// ---------------- K4: pool + attno + fc (merged; one block per batch) ----------------
__global__ void __launch_bounds__(1024) poolfc_kernel(const float* __restrict__ convo_w,
                                                      const float* __restrict__ convo_b,
                                                      const float* __restrict__ attno_w,
                                                      const float* __restrict__ attno_b,
                                                      const float* __restrict__ fc_w,
                                                      const float* __restrict__ fc_b,
                                                      float* __restrict__ out) {
  int b = blockIdx.x;
  int tid = threadIdx.x;
  int warp = tid >> 5, lane = tid & 31;
  __shared__ float Ssm[576];
  __shared__ float pooled[88], mean_s[40], pa[40];
  for (int i = tid; i < 576; i += 1024) Ssm[i] = g_S[b * 576 + i];
  __syncthreads();

  #pragma unroll
  for (int i = 0; i < 4; i++) {
    int task = warp + 32 * i;   // 0..127
    if (task < 88) {
      const float* wp = convo_w + task * 576;
      float acc = 0.f;
      #pragma unroll
      for (int j = lane; j < 576; j += 32) acc = fmaf(__ldg(&wp[j]), Ssm[j], acc);
      acc = wred(acc);
      if (lane == 0) pooled[task] = __ldg(&convo_b[task]) + acc * (1.f / 1024.f);
    } else {
      int c = task - 88;
      const float* p = g_attn + b * 40960 + c * 1024;
      float s = 0.f;
      #pragma unroll 8
      for (int j = lane; j < 1024; j += 32) s += p[j];
      s = wred(s);
      if (lane == 0) mean_s[c] = s * (1.f / 1024.f);
    }
  }
  __syncthreads();
  if (tid < 40) {
    float acc = __ldg(&attno_b[tid]);
    #pragma unroll 4
    for (int c = 0; c < 40; c++) acc = fmaf(__ldg(&attno_w[tid * 40 + c]), mean_s[c], acc);
    pa[tid] = acc;
  }
  __syncthreads();
  if (tid < 100) {
    float acc = __ldg(&fc_b[tid]);
    const float* wp = fc_w + tid * 128;
    #pragma unroll 4
    for (int c = 0; c < 88; c++) acc = fmaf(__ldg(&wp[c]), pooled[c], acc);
    #pragma unroll 4
    for (int c = 0; c < 40; c++) acc = fmaf(__ldg(&wp[88 + c]), pa[c], acc);
    out[b * 100 + tid] = acc;
  }
}

// ---------------- launch ----------------
extern "C" void kernel_launch(void* const* d_in, const int* in_sizes, int n_in,
                              void* d_out, int out_size) {
  const float* x         = (const float*)d_in[0];
  const float* conv1_w   = (const float*)d_in[1];
  const float* conv1_b   = (const float*)d_in[2];
  const float* bn1_g     = (const float*)d_in[3];
  const float* bn1_b     = (const float*)d_in[4];
  const float* convo_w   = (const float*)d_in[5];
  const float* convo_b   = (const float*)d_in[6];
  const float* qkv_w     = (const float*)d_in[7];
  const float* qkv_b     = (const float*)d_in[8];
  const float* attno_w   = (const float*)d_in[9];
  const float* attno_b   = (const float*)d_in[10];
  const float* key_rel_h = (const float*)d_in[11];
  const float* key_rel_w = (const float*)d_in[12];
  const float* fc_w      = (const float*)d_in[13];
  const float* fc_b      = (const float*)d_in[14];
  float* out = (float*)d_out;

  cudaFuncSetAttribute(attn_kernel, cudaFuncAttributeMaxDynamicSharedMemorySize, ATTN_SMEM_BYTES);

  conv1_kernel<<<dim3(64, 16), 256>>>(x, conv1_w, conv1_b);     // #0
  bnrelu_kernel<<<dim3(64, 16), 1024>>>(bn1_g, bn1_b);          // #1
  qkv_kernel<<<dim3(1, 8, 16), 256>>>(qkv_w, qkv_b);            // #2
  attn_kernel<<<dim3(8, 64), 256, ATTN_SMEM_BYTES>>>(key_rel_h, key_rel_w);  // #3 (profiled)
  poolfc_kernel<<<16, 1024>>>(convo_w, convo_b, attno_w, attno_b, fc_w, fc_b, out);  // #4
}

// round 15
// speedup vs baseline: 1.7922x; 1.0431x over previous
#include <cuda_runtime.h>
#include <cuda_fp16.h>

typedef unsigned long long u64;
typedef unsigned u32;

// ---------------- scratch (device globals; no allocation) ----------------
__device__ float g_pre[16*64*1024];     // conv1 out, then h (in-place)
__device__ float2 g_bstats[64*16];      // per (oc,b) partial {sum, sumsq}
__device__ float g_S[16*64*9];          // 9 shifted window sums per (b, in-ch)
__device__ float g_Q[16*4*1024*10];
__device__ float g_KV[16*4*1024*20];    // interleaved K(10) | V(10) per key
__device__ float g_attn[16*4*1024*10];  // normalized attention output
__device__ float g_pooled[16*88];

__device__ __forceinline__ float wred(float v) {
  #pragma unroll
  for (int o = 16; o; o >>= 1) v += __shfl_down_sync(0xffffffffu, v, o);
  return v;
}
// pack two f32 -> f16x2 (lo in low half)
__device__ __forceinline__ u32 f16x2(float lo, float hi) {
  u32 r; asm("cvt.rn.f16x2.f32 %0, %1, %2;" : "=r"(r) : "f"(hi), "f"(lo)); return r;
}
// packed f16x2 ex2
__device__ __forceinline__ u32 hex2(u32 x) {
  u32 y; asm("ex2.approx.f16x2 %0, %1;" : "=r"(y) : "r"(x)); return y;
}
// D += A*B (m16n8k16, f16 in, f32 acc), D/C in-place
__device__ __forceinline__ void mma_acc(float& d0, float& d1, float& d2, float& d3,
                                        u32 a0, u32 a1, u32 a2, u32 a3,
                                        u32 b0, u32 b1) {
  asm volatile(
    "mma.sync.aligned.m16n8k16.row.col.f32.f16.f16.f32 "
    "{%0,%1,%2,%3}, {%4,%5,%6,%7}, {%8,%9}, {%0,%1,%2,%3};"
    : "+f"(d0), "+f"(d1), "+f"(d2), "+f"(d3)
    : "r"(a0), "r"(a1), "r"(a2), "r"(a3), "r"(b0), "r"(b1));
}

// ---------------- K0: conv1 3x3 (3->64) SAME + per-block BN partial stats ----------------
__global__ void __launch_bounds__(256) conv1_kernel(const float* __restrict__ x,
                                                    const float* __restrict__ w,
                                                    const float* __restrict__ bias) {
  int t = threadIdx.x;
  int oc = blockIdx.x, b = blockIdx.y;
  int p0 = t * 4;
  int y = p0 >> 5, x0 = p0 & 31;
  float w_[27];
  #pragma unroll
  for (int i = 0; i < 27; i++) w_[i] = __ldg(&w[oc * 27 + i]);
  float bv = __ldg(&bias[oc]);
  float a0 = bv, a1 = bv, a2 = bv, a3 = bv;
  #pragma unroll
  for (int ic = 0; ic < 3; ic++) {
    const float* base = x + (b * 3 + ic) * 1024;
    #pragma unroll
    for (int ky = 0; ky < 3; ky++) {
      int iy = y + ky - 1;
      if (iy < 0 || iy > 31) continue;
      const float* row = base + iy * 32;
      float r[6];
      #pragma unroll
      for (int dx = 0; dx < 6; dx++) {
        int c = x0 - 1 + dx;
        r[dx] = (c >= 0 && c < 32) ? __ldg(&row[c]) : 0.f;
      }
      #pragma unroll
      for (int kx = 0; kx < 3; kx++) {
        float wv = w_[ic * 9 + ky * 3 + kx];
        a0 = fmaf(wv, r[kx],     a0);
        a1 = fmaf(wv, r[kx + 1], a1);
        a2 = fmaf(wv, r[kx + 2], a2);
        a3 = fmaf(wv, r[kx + 3], a3);
      }
    }
  }
  *(float4*)(g_pre + (b * 64 + oc) * 1024 + p0) = make_float4(a0, a1, a2, a3);

  float s  = a0 + a1 + a2 + a3;
  float sq = fmaf(a0, a0, fmaf(a1, a1, fmaf(a2, a2, a3 * a3)));
  s = wred(s); sq = wred(sq);
  __shared__ float ss[8], s2m[8];
  int warp = t >> 5, lane = t & 31;
  if (lane == 0) { ss[warp] = s; s2m[warp] = sq; }
  __syncthreads();
  if (t == 0) {
    float S = 0.f, Q = 0.f;
    #pragma unroll
    for (int i = 0; i < 8; i++) { S += ss[i]; Q += s2m[i]; }
    g_bstats[oc * 16 + b] = make_float2(S, Q);
  }
}

// ---------------- K1: BN finalize + apply + relu + 9 window sums ----------------
__global__ void bnrelu_kernel(const float* __restrict__ gamma,
                              const float* __restrict__ beta) {
  int c = blockIdx.x, b = blockIdx.y;
  int p = threadIdx.x;                  // 1024 threads
  __shared__ float scb[2];
  if (p < 16) {
    float2 v = g_bstats[c * 16 + p];
    float s = v.x, q = v.y;
    #pragma unroll
    for (int o = 8; o; o >>= 1) {
      s += __shfl_down_sync(0xffffu, s, o, 16);
      q += __shfl_down_sync(0xffffu, q, o, 16);
    }
    if (p == 0) {
      float mean = s * (1.f / 16384.f);
      float var  = q * (1.f / 16384.f) - mean * mean;
      float sc = __ldg(&gamma[c]) * rsqrtf(var + 1e-5f);
      scb[0] = sc;
      scb[1] = __ldg(&beta[c]) - mean * sc;
    }
  }
  __syncthreads();

  int y = p >> 5, xx = p & 31;
  int idx = (b * 64 + c) * 1024 + p;
  float v = fmaxf(fmaf(g_pre[idx], scb[0], scb[1]), 0.f);
  g_pre[idx] = v;

  float t = v;
  float r0  = (y == 0)  ? v : 0.f;
  float r31 = (y == 31) ? v : 0.f;
  float c0  = (xx == 0)  ? v : 0.f;
  float c31 = (xx == 31) ? v : 0.f;

  __shared__ float red[32][5];
  __shared__ float corn[4];
  if (p == 0)    corn[0] = v;
  if (p == 31)   corn[1] = v;
  if (p == 992)  corn[2] = v;
  if (p == 1023) corn[3] = v;

  t = wred(t); r0 = wred(r0); r31 = wred(r31); c0 = wred(c0); c31 = wred(c31);
  int warp = p >> 5, lane = p & 31;
  if (lane == 0) { red[warp][0]=t; red[warp][1]=r0; red[warp][2]=r31; red[warp][3]=c0; red[warp][4]=c31; }
  __syncthreads();
  if (p < 32) {
    float a0 = red[p][0], a1 = red[p][1], a2 = red[p][2], a3 = red[p][3], a4 = red[p][4];
    a0 = wred(a0); a1 = wred(a1); a2 = wred(a2); a3 = wred(a3); a4 = wred(a4);
    if (p == 0) {
      float T = a0, R0 = a1, R31 = a2, C0 = a3, C31 = a4;
      float* Sp = g_S + (b * 64 + c) * 9;
      Sp[0] = T - R31 - C31 + corn[3];
      Sp[1] = T - R31;
      Sp[2] = T - R31 - C0 + corn[2];
      Sp[3] = T - C31;
      Sp[4] = T;
      Sp[5] = T - C0;
      Sp[6] = T - R0 - C31 + corn[1];
      Sp[7] = T - R0;
      Sp[8] = T - R0 - C0 + corn[0];
    }
  }
}

// ---------------- K2: pooled conv_out (depends only on g_S) ----------------
__global__ void __launch_bounds__(1024) pool_conv_kernel(const float* __restrict__ convo_w,
                                                         const float* __restrict__ convo_b) {
  int b = blockIdx.y;
  int tid = threadIdx.x;
  int warp = tid >> 5, lane = tid & 31;
  int task = blockIdx.x * 32 + warp;   // 0..95 (88 used)
  __shared__ float Ssm[576];
  for (int i = tid; i < 576; i += 1024) Ssm[i] = g_S[b * 576 + i];
  __syncthreads();
  if (task < 88) {
    const float* wp = convo_w + task * 576;
    float acc = 0.f;
    #pragma unroll
    for (int i = lane; i < 576; i += 32) acc = fmaf(__ldg(&wp[i]), Ssm[i], acc);
    acc = wred(acc);
    if (lane == 0) g_pooled[b * 88 + task] = __ldg(&convo_b[task]) + acc * (1.f / 1024.f);
  }
}

// ---------------- K3: qkv 1x1 conv -> Q (scaled), KV interleaved (PROFILED) ----------------
__global__ void __launch_bounds__(256) qkv_kernel(const float* __restrict__ w,
                                                  const float* __restrict__ bias) {
  int tid = threadIdx.x;        // 256
  int b = blockIdx.z;
  int o0 = blockIdx.y * 15;     // 8 groups of 15 output channels
  __shared__ float ws[960];
  __shared__ float bs[15];
  for (int i = tid; i < 960; i += 256) ws[i] = w[o0 * 64 + i];
  if (tid < 15) bs[tid] = bias[o0 + tid];
  __syncthreads();
  int n0 = tid * 4;
  float4 acc[15];
  #pragma unroll
  for (int u = 0; u < 15; u++) { float bv = bs[u]; acc[u] = make_float4(bv, bv, bv, bv); }
  const float* hp = g_pre + b * 64 * 1024 + n0;
  #pragma unroll 2
  for (int i = 0; i < 64; i++) {
    float4 hv = *(const float4*)(hp + i * 1024);
    #pragma unroll
    for (int u = 0; u < 15; u++) {
      float wv = ws[u * 64 + i];
      acc[u].x = fmaf(wv, hv.x, acc[u].x);
      acc[u].y = fmaf(wv, hv.y, acc[u].y);
      acc[u].z = fmaf(wv, hv.z, acc[u].z);
      acc[u].w = fmaf(wv, hv.w, acc[u].w);
    }
  }
  const float QMUL = 0.31622776601683794f * 1.4426950408889634f;  // dkh^-.5 * log2e
  #pragma unroll
  for (int u = 0; u < 15; u++) {
    int o = o0 + u;
    int which = o / 40;
    int r = o - which * 40;
    int head = r / 10, d = r - head * 10;
    int bh = b * 4 + head;
    if (which == 0) {
      float* pb = g_Q + (bh * 1024) * 10 + d;
      pb[(n0 + 0) * 10] = acc[u].x * QMUL;
      pb[(n0 + 1) * 10] = acc[u].y * QMUL;
      pb[(n0 + 2) * 10] = acc[u].z * QMUL;
      pb[(n0 + 3) * 10] = acc[u].w * QMUL;
    } else {
      float* pb = g_KV + (bh * 1024) * 20 + ((which == 1) ? d : 10 + d);
      pb[(n0 + 0) * 20] = acc[u].x;
      pb[(n0 + 1) * 20] = acc[u].y;
      pb[(n0 + 2) * 20] = acc[u].z;
      pb[(n0 + 3) * 20] = acc[u].w;
    }
  }
}

// ---------------- K4: HMMA attention (mma.sync m16n8k16 f16) ----------------
// CTA: 128 queries (8 warps x 16 rows) x full 1024 keys, per bh. grid (8, 64).
// KS: [1024][16] f16, dims permuted so each B-fragment pair is one 8B load.
// VT: [16][1032] f16, keys permuted within 16-groups; row 10 = ones (denominator).
#define KS_OFF  0
#define VT_OFF  32768
#define RH_OFF  65792
#define RW_OFF  82688
#define KRH_OFF 100096
#define KRW_OFF 102616
#define ATTN_SMEM_BYTES 105136

// one 16-key chunk; f32 bias adds -> f16x2 pack -> packed ex2 (half the MUFU)
#define CHUNK(kb, bl0x, bl0y, bh0x, bh0y, bl1x, bl1y, bh1x, bh1y) do { \
  uint2 kA = *(const uint2*)(KSr + (kb) * 16); \
  uint2 kB = *(const uint2*)(KSr + ((kb) + 8) * 16); \
  float s0 = 0.f, s1 = 0.f, s2 = 0.f, s3 = 0.f; \
  float s4 = 0.f, s5 = 0.f, s6 = 0.f, s7 = 0.f; \
  mma_acc(s0, s1, s2, s3, aq0, aq1, aq2, aq3, kA.x, kA.y); \
  mma_acc(s4, s5, s6, s7, aq0, aq1, aq2, aq3, kB.x, kB.y); \
  u32 pa0 = hex2(f16x2(s0 + (bl0x), s1 + (bl0y))); \
  u32 pa1 = hex2(f16x2(s2 + (bh0x), s3 + (bh0y))); \
  u32 pa2 = hex2(f16x2(s4 + (bl1x), s5 + (bl1y))); \
  u32 pa3 = hex2(f16x2(s6 + (bh1x), s7 + (bh1y))); \
  uint2 vA = *(const uint2*)(VTlo + (kb)); \
  uint2 vB = *(const uint2*)(VThi + (kb)); \
  mma_acc(D0a, D0b, D0c, D0d, pa0, pa1, pa2, pa3, vA.x, vA.y); \
  mma_acc(D1a, D1b, D1c, D1d, pa0, pa1, pa2, pa3, vB.x, vB.y); \
} while (0)

__global__ void __launch_bounds__(256, 2) attn_kernel(const float* __restrict__ krh,
                                                      const float* __restrict__ krw) {
  extern __shared__ char smem[];
  __half* KS   = (__half*)(smem + KS_OFF);
  __half* VT   = (__half*)(smem + VT_OFF);
  float*  RH   = (float*)(smem + RH_OFF);
  float2* RW2  = (float2*)(smem + RW_OFF);
  float*  KRH  = (float*)(smem + KRH_OFF);
  float*  KRW  = (float*)(smem + KRW_OFF);
  int qt = blockIdx.x, bh = blockIdx.y;
  int tid = threadIdx.x;
  int qbase = qt * 128;

  // stage rel tables + K/V (f16, permuted layouts)
  for (int i = tid; i < 630; i += 256) { KRH[i] = krh[i]; KRW[i] = krw[i]; }
  for (int k = tid; k < 1024; k += 256) {
    const float4* src = (const float4*)(g_KV + (bh * 1024 + k) * 20);
    float4 v0 = src[0], v1 = src[1], v2 = src[2], v3 = src[3], v4 = src[4];
    u32* kw = (u32*)(KS + k * 16);
    kw[0] = f16x2(v0.x, v0.y); kw[1] = f16x2(v2.x, v2.y);
    kw[2] = f16x2(v0.z, v0.w); kw[3] = 0u;
    kw[4] = f16x2(v1.x, v1.y); kw[5] = 0u;
    kw[6] = f16x2(v1.z, v1.w); kw[7] = 0u;
    int wk = k & 15, p = wk >> 1, e = wk & 1;
    int pk = (k & ~15) + ((((((p & 3) << 1) | (p >> 2)) << 1) | e));
    VT[0 * 1032 + pk] = __float2half_rn(v2.z);
    VT[1 * 1032 + pk] = __float2half_rn(v2.w);
    VT[2 * 1032 + pk] = __float2half_rn(v3.x);
    VT[3 * 1032 + pk] = __float2half_rn(v3.y);
    VT[4 * 1032 + pk] = __float2half_rn(v3.z);
    VT[5 * 1032 + pk] = __float2half_rn(v3.w);
    VT[6 * 1032 + pk] = __float2half_rn(v4.x);
    VT[7 * 1032 + pk] = __float2half_rn(v4.y);
    VT[8 * 1032 + pk] = __float2half_rn(v4.z);
    VT[9 * 1032 + pk] = __float2half_rn(v4.w);
    VT[10 * 1032 + pk] = __float2half_rn(1.0f);
    #pragma unroll
    for (int d = 11; d < 16; d++) VT[d * 1032 + pk] = __ushort_as_half(0);
  }
  __syncthreads();

  // per-query relative-bias tables (log2e domain; q pre-scaled)
  {
    int ql = tid >> 1;
    int n = qbase + ql;
    const float* qp = g_Q + (bh * 1024 + n) * 10;
    float q[10];
    #pragma unroll
    for (int i = 0; i < 10; i++) q[i] = qp[i];
    int yq = n >> 5, xq = n & 31;
    if ((tid & 1) == 0) {
      #pragma unroll 4
      for (int ym = 0; ym < 32; ym++) {
        const float* t = KRH + (ym - yq + 31) * 10;
        float s = q[0] * t[0];
        #pragma unroll
        for (int i = 1; i < 10; i++) s = fmaf(q[i], t[i], s);
        RH[ql * 33 + ym] = s;
      }
    } else {
      #pragma unroll 4
      for (int j = 0; j < 16; j++) {
        const float* t0 = KRW + (2 * j - xq + 31) * 10;
        const float* t1 = t0 + 10;
        float s0 = q[0] * t0[0], s1 = q[0] * t1[0];
        #pragma unroll
        for (int i = 1; i < 10; i++) { s0 = fmaf(q[i], t0[i], s0); s1 = fmaf(q[i], t1[i], s1); }
        RW2[ql * 17 + j] = make_float2(s0, s1);
      }
    }
  }

  // Q fragment (from gmem; dims 10-15 zero)
  int lane = tid & 31, w = tid >> 5;
  int r = lane >> 2, c0 = (lane & 3) * 2;
  int ql_lo = w * 16 + r, ql_hi = ql_lo + 8;
  int n_lo = qbase + ql_lo, n_hi = qbase + ql_hi;
  const float* qlo = g_Q + (bh * 1024 + n_lo) * 10;
  const float* qhi = g_Q + (bh * 1024 + n_hi) * 10;
  u32 aq0 = f16x2(qlo[c0], qlo[c0 + 1]);
  u32 aq1 = f16x2(qhi[c0], qhi[c0 + 1]);
  u32 aq2 = (c0 == 0) ? f16x2(qlo[8], qlo[9]) : 0u;
  u32 aq3 = (c0 == 0) ? f16x2(qhi[8], qhi[9]) : 0u;

  __syncthreads();

  const __half* KSr  = KS + r * 16 + 4 * (lane & 3);
  const __half* VTlo = VT + r * 1032 + 4 * (lane & 3);
  const __half* VThi = VT + (r + 8) * 1032 + 4 * (lane & 3);
  const float*  RHlo = RH + ql_lo * 33;
  const float*  RHhi = RH + ql_hi * 33;

  // hoist this thread's 8 RW2 entries into registers
  int l3 = lane & 3;
  const float2* RWlo = RW2 + ql_lo * 17;
  const float2* RWhi = RW2 + ql_hi * 17;
  float2 wla0 = RWlo[l3],      wla1 = RWlo[l3 + 4];    // even chunk
  float2 wlb0 = RWlo[l3 + 8],  wlb1 = RWlo[l3 + 12];   // odd chunk
  float2 wha0 = RWhi[l3],      wha1 = RWhi[l3 + 4];
  float2 whb0 = RWhi[l3 + 8],  whb1 = RWhi[l3 + 12];

  float D0a = 0.f, D0b = 0.f, D0c = 0.f, D0d = 0.f;
  float D1a = 0.f, D1b = 0.f, D1c = 0.f, D1d = 0.f;

  #pragma unroll 4
  for (int ym = 0; ym < 32; ym++) {
    float rhl = RHlo[ym], rhh = RHhi[ym];
    int kb = ym * 32;
    CHUNK(kb,
          rhl + wla0.x, rhl + wla0.y, rhh + wha0.x, rhh + wha0.y,
          rhl + wla1.x, rhl + wla1.y, rhh + wha1.x, rhh + wha1.y);
    CHUNK(kb + 16,
          rhl + wlb0.x, rhl + wlb0.y, rhh + whb0.x, rhh + whb0.y,
          rhl + wlb1.x, rhl + wlb1.y, rhh + whb1.x, rhh + whb1.y);
  }

  // denominators live in D1 col 10 (tile col 2 -> lanes with lane&3==1)
  float l_lo = __shfl_sync(0xffffffffu, D1a, (lane & ~3) | 1);
  float l_hi = __shfl_sync(0xffffffffu, D1c, (lane & ~3) | 1);
  float il = __frcp_rn(l_lo), ih = __frcp_rn(l_hi);

  float* olo = g_attn + (bh * 1024 + n_lo) * 10;
  float* ohi = g_attn + (bh * 1024 + n_hi) * 10;
  *(float2*)(olo + c0) = make_float2(D0a * il, D0b * il);
  *(float2*)(ohi + c0) = make_float2(D0c * ih, D0d * ih);
  if (c0 == 0) {
    *(float2*)(olo + 8) = make_float2(D1a * il, D1b * il);
    *(float2*)(ohi + 8) = make_float2(D1c * ih, D1d * ih);
  }
}

// ---------------- K5: attn means + attno + fc ----------------
__global__ void __launch_bounds__(1024) attnpool_fc_kernel(const float* __restrict__ attno_w,
                                                           const float* __restrict__ attno_b,
                                                           const float* __restrict__ fc_w,
                                                           const float* __restrict__ fc_b,
                                                           float* __restrict__ out) {
  int b = blockIdx.x;
  int tid = threadIdx.x;
  int warp = tid >> 5, lane = tid & 31;
  __shared__ float mean_s[40], pa[40], pooled[88];
  if (tid < 88) pooled[tid] = g_pooled[b * 88 + tid];
  for (int c = warp; c < 40; c += 32) {
    const float* p = g_attn + b * 40960 + c * 1024;
    float s = 0.f;
    #pragma unroll 8
    for (int j = lane; j < 1024; j += 32) s += p[j];
    s = wred(s);
    if (lane == 0) mean_s[c] = s * (1.f / 1024.f);
  }
  __syncthreads();
  if (tid < 40) {
    float acc = __ldg(&attno_b[tid]);
    #pragma unroll 4
    for (int c = 0; c < 40; c++) acc = fmaf(__ldg(&attno_w[tid * 40 + c]), mean_s[c], acc);
    pa[tid] = acc;
  }
  __syncthreads();
  if (tid < 100) {
    float acc = __ldg(&fc_b[tid]);
    const float* wp = fc_w + tid * 128;
    #pragma unroll 4
    for (int c = 0; c < 88; c++) acc = fmaf(__ldg(&wp[c]), pooled[c], acc);
    #pragma unroll 4
    for (int c = 0; c < 40; c++) acc = fmaf(__ldg(&wp[88 + c]), pa[c], acc);
    out[b * 100 + tid] = acc;
  }
}

// ---------------- launch ----------------
extern "C" void kernel_launch(void* const* d_in, const int* in_sizes, int n_in,
                              void* d_out, int out_size) {
  const float* x         = (const float*)d_in[0];
  const float* conv1_w   = (const float*)d_in[1];
  const float* conv1_b   = (const float*)d_in[2];
  const float* bn1_g     = (const float*)d_in[3];
  const float* bn1_b     = (const float*)d_in[4];
  const float* convo_w   = (const float*)d_in[5];
  const float* convo_b   = (const float*)d_in[6];
  const float* qkv_w     = (const float*)d_in[7];
  const float* qkv_b     = (const float*)d_in[8];
  const float* attno_w   = (const float*)d_in[9];
  const float* attno_b   = (const float*)d_in[10];
  const float* key_rel_h = (const float*)d_in[11];
  const float* key_rel_w = (const float*)d_in[12];
  const float* fc_w      = (const float*)d_in[13];
  const float* fc_b      = (const float*)d_in[14];
  float* out = (float*)d_out;

  cudaFuncSetAttribute(attn_kernel, cudaFuncAttributeMaxDynamicSharedMemorySize, ATTN_SMEM_BYTES);

  conv1_kernel<<<dim3(64, 16), 256>>>(x, conv1_w, conv1_b);             // #0
  bnrelu_kernel<<<dim3(64, 16), 1024>>>(bn1_g, bn1_b);                  // #1
  pool_conv_kernel<<<dim3(3, 16), 1024>>>(convo_w, convo_b);            // #2
  qkv_kernel<<<dim3(1, 8, 16), 256>>>(qkv_w, qkv_b);                    // #3 (profiled)
  attn_kernel<<<dim3(8, 64), 256, ATTN_SMEM_BYTES>>>(key_rel_h, key_rel_w);  // #4
  attnpool_fc_kernel<<<16, 1024>>>(attno_w, attno_b, fc_w, fc_b, out);  // #5
}

// round 16
// speedup vs baseline: 1.9947x; 1.1130x over previous
#include <cuda_runtime.h>
#include <cuda_fp16.h>

typedef unsigned long long u64;
typedef unsigned u32;

// ---------------- scratch (device globals; no allocation) ----------------
__device__ float g_pre[16*64*1024];     // conv1 out, then h (in-place)
__device__ float2 g_bstats[64*16];      // per (oc,b) partial {sum, sumsq}
__device__ float g_S[16*64*9];          // 9 shifted window sums per (b, in-ch)
__device__ float g_Q[16*4*1024*10];
__device__ float g_KV[16*4*1024*20];    // interleaved K(10) | V(10) per key
__device__ float g_attn[16*4*1024*10];  // normalized attention output
__device__ float g_pooled[16*88];

__device__ __forceinline__ float wred(float v) {
  #pragma unroll
  for (int o = 16; o; o >>= 1) v += __shfl_down_sync(0xffffffffu, v, o);
  return v;
}
// pack two f32 -> f16x2 (lo in low half)
__device__ __forceinline__ u32 f16x2(float lo, float hi) {
  u32 r; asm("cvt.rn.f16x2.f32 %0, %1, %2;" : "=r"(r) : "f"(hi), "f"(lo)); return r;
}
// packed f16x2 ex2
__device__ __forceinline__ u32 hex2(u32 x) {
  u32 y; asm("ex2.approx.f16x2 %0, %1;" : "=r"(y) : "r"(x)); return y;
}
// D += A*B (m16n8k16, f16 in, f32 acc), D/C in-place
__device__ __forceinline__ void mma_acc(float& d0, float& d1, float& d2, float& d3,
                                        u32 a0, u32 a1, u32 a2, u32 a3,
                                        u32 b0, u32 b1) {
  asm volatile(
    "mma.sync.aligned.m16n8k16.row.col.f32.f16.f16.f32 "
    "{%0,%1,%2,%3}, {%4,%5,%6,%7}, {%8,%9}, {%0,%1,%2,%3};"
    : "+f"(d0), "+f"(d1), "+f"(d2), "+f"(d3)
    : "r"(a0), "r"(a1), "r"(a2), "r"(a3), "r"(b0), "r"(b1));
}

// ---------------- K0: conv1 3x3 (3->64) SAME + per-block BN partial stats ----------------
__global__ void __launch_bounds__(256) conv1_kernel(const float* __restrict__ x,
                                                    const float* __restrict__ w,
                                                    const float* __restrict__ bias) {
  int t = threadIdx.x;
  int oc = blockIdx.x, b = blockIdx.y;
  int p0 = t * 4;
  int y = p0 >> 5, x0 = p0 & 31;
  float w_[27];
  #pragma unroll
  for (int i = 0; i < 27; i++) w_[i] = __ldg(&w[oc * 27 + i]);
  float bv = __ldg(&bias[oc]);
  float a0 = bv, a1 = bv, a2 = bv, a3 = bv;
  #pragma unroll
  for (int ic = 0; ic < 3; ic++) {
    const float* base = x + (b * 3 + ic) * 1024;
    #pragma unroll
    for (int ky = 0; ky < 3; ky++) {
      int iy = y + ky - 1;
      if (iy < 0 || iy > 31) continue;
      const float* row = base + iy * 32;
      float r[6];
      #pragma unroll
      for (int dx = 0; dx < 6; dx++) {
        int c = x0 - 1 + dx;
        r[dx] = (c >= 0 && c < 32) ? __ldg(&row[c]) : 0.f;
      }
      #pragma unroll
      for (int kx = 0; kx < 3; kx++) {
        float wv = w_[ic * 9 + ky * 3 + kx];
        a0 = fmaf(wv, r[kx],     a0);
        a1 = fmaf(wv, r[kx + 1], a1);
        a2 = fmaf(wv, r[kx + 2], a2);
        a3 = fmaf(wv, r[kx + 3], a3);
      }
    }
  }
  *(float4*)(g_pre + (b * 64 + oc) * 1024 + p0) = make_float4(a0, a1, a2, a3);

  float s  = a0 + a1 + a2 + a3;
  float sq = fmaf(a0, a0, fmaf(a1, a1, fmaf(a2, a2, a3 * a3)));
  s = wred(s); sq = wred(sq);
  __shared__ float ss[8], s2m[8];
  int warp = t >> 5, lane = t & 31;
  if (lane == 0) { ss[warp] = s; s2m[warp] = sq; }
  __syncthreads();
  if (t == 0) {
    float S = 0.f, Q = 0.f;
    #pragma unroll
    for (int i = 0; i < 8; i++) { S += ss[i]; Q += s2m[i]; }
    g_bstats[oc * 16 + b] = make_float2(S, Q);
  }
}

// ---------------- K1: BN finalize + apply + relu + 9 window sums ----------------
__global__ void bnrelu_kernel(const float* __restrict__ gamma,
                              const float* __restrict__ beta) {
  int c = blockIdx.x, b = blockIdx.y;
  int p = threadIdx.x;                  // 1024 threads
  __shared__ float scb[2];
  if (p < 16) {
    float2 v = g_bstats[c * 16 + p];
    float s = v.x, q = v.y;
    #pragma unroll
    for (int o = 8; o; o >>= 1) {
      s += __shfl_down_sync(0xffffu, s, o, 16);
      q += __shfl_down_sync(0xffffu, q, o, 16);
    }
    if (p == 0) {
      float mean = s * (1.f / 16384.f);
      float var  = q * (1.f / 16384.f) - mean * mean;
      float sc = __ldg(&gamma[c]) * rsqrtf(var + 1e-5f);
      scb[0] = sc;
      scb[1] = __ldg(&beta[c]) - mean * sc;
    }
  }
  __syncthreads();

  int y = p >> 5, xx = p & 31;
  int idx = (b * 64 + c) * 1024 + p;
  float v = fmaxf(fmaf(g_pre[idx], scb[0], scb[1]), 0.f);
  g_pre[idx] = v;

  float t = v;
  float r0  = (y == 0)  ? v : 0.f;
  float r31 = (y == 31) ? v : 0.f;
  float c0  = (xx == 0)  ? v : 0.f;
  float c31 = (xx == 31) ? v : 0.f;

  __shared__ float red[32][5];
  __shared__ float corn[4];
  if (p == 0)    corn[0] = v;
  if (p == 31)   corn[1] = v;
  if (p == 992)  corn[2] = v;
  if (p == 1023) corn[3] = v;

  t = wred(t); r0 = wred(r0); r31 = wred(r31); c0 = wred(c0); c31 = wred(c31);
  int warp = p >> 5, lane = p & 31;
  if (lane == 0) { red[warp][0]=t; red[warp][1]=r0; red[warp][2]=r31; red[warp][3]=c0; red[warp][4]=c31; }
  __syncthreads();
  if (p < 32) {
    float a0 = red[p][0], a1 = red[p][1], a2 = red[p][2], a3 = red[p][3], a4 = red[p][4];
    a0 = wred(a0); a1 = wred(a1); a2 = wred(a2); a3 = wred(a3); a4 = wred(a4);
    if (p == 0) {
      float T = a0, R0 = a1, R31 = a2, C0 = a3, C31 = a4;
      float* Sp = g_S + (b * 64 + c) * 9;
      Sp[0] = T - R31 - C31 + corn[3];
      Sp[1] = T - R31;
      Sp[2] = T - R31 - C0 + corn[2];
      Sp[3] = T - C31;
      Sp[4] = T;
      Sp[5] = T - C0;
      Sp[6] = T - R0 - C31 + corn[1];
      Sp[7] = T - R0;
      Sp[8] = T - R0 - C0 + corn[0];
    }
  }
}

// ---------------- K2: pooled conv_out (depends only on g_S) ----------------
__global__ void __launch_bounds__(1024) pool_conv_kernel(const float* __restrict__ convo_w,
                                                         const float* __restrict__ convo_b) {
  int b = blockIdx.y;
  int tid = threadIdx.x;
  int warp = tid >> 5, lane = tid & 31;
  int task = blockIdx.x * 32 + warp;   // 0..95 (88 used)
  __shared__ float Ssm[576];
  for (int i = tid; i < 576; i += 1024) Ssm[i] = g_S[b * 576 + i];
  __syncthreads();
  if (task < 88) {
    const float* wp = convo_w + task * 576;
    float acc = 0.f;
    #pragma unroll
    for (int i = lane; i < 576; i += 32) acc = fmaf(__ldg(&wp[i]), Ssm[i], acc);
    acc = wred(acc);
    if (lane == 0) g_pooled[b * 88 + task] = __ldg(&convo_b[task]) + acc * (1.f / 1024.f);
  }
}

// ---------------- K3: qkv 1x1 conv, 1 pixel/thread (PROFILED) ----------------
__global__ void __launch_bounds__(256) qkv_kernel(const float* __restrict__ w,
                                                  const float* __restrict__ bias) {
  int tid = threadIdx.x;        // 256
  int n = blockIdx.x * 256 + tid;   // pixel
  int b = blockIdx.z;
  int o0 = blockIdx.y * 15;     // 8 groups of 15 output channels
  __shared__ float ws[960];
  __shared__ float bs[15];
  for (int i = tid; i < 960; i += 256) ws[i] = w[o0 * 64 + i];
  if (tid < 15) bs[tid] = bias[o0 + tid];
  __syncthreads();
  float acc[15];
  #pragma unroll
  for (int u = 0; u < 15; u++) acc[u] = bs[u];
  const float* hp = g_pre + b * 65536 + n;
  #pragma unroll 16
  for (int i = 0; i < 64; i++) {
    float hv = hp[i * 1024];
    #pragma unroll
    for (int u = 0; u < 15; u++) acc[u] = fmaf(ws[u * 64 + i], hv, acc[u]);
  }
  const float QMUL = 0.31622776601683794f * 1.4426950408889634f;  // dkh^-.5 * log2e
  #pragma unroll
  for (int u = 0; u < 15; u++) {
    int o = o0 + u;
    int which = o / 40;
    int r = o - which * 40;
    int head = r / 10, d = r - head * 10;
    int bh = b * 4 + head;
    if (which == 0) {
      g_Q[(bh * 1024 + n) * 10 + d] = acc[u] * QMUL;
    } else {
      g_KV[(bh * 1024 + n) * 20 + ((which == 1) ? d : 10 + d)] = acc[u];
    }
  }
}

// ---------------- K4: HMMA attention (mma.sync m16n8k16 f16) ----------------
// CTA: 128 queries (8 warps x 16 rows) x full 1024 keys, per bh. grid (8, 64).
// KS: [1024][16] f16, dims permuted so each B-fragment pair is one 8B load.
// VT: [16][1032] f16, keys permuted within 16-groups; row 10 = ones (denominator).
#define KS_OFF  0
#define VT_OFF  32768
#define RH_OFF  65792
#define RW_OFF  82688
#define KRH_OFF 100096
#define KRW_OFF 102616
#define ATTN_SMEM_BYTES 105136

// one 16-key chunk; f32 bias adds -> f16x2 pack -> packed ex2
#define CHUNK(kb, bl0x, bl0y, bh0x, bh0y, bl1x, bl1y, bh1x, bh1y) do { \
  uint2 kA = *(const uint2*)(KSr + (kb) * 16); \
  uint2 kB = *(const uint2*)(KSr + ((kb) + 8) * 16); \
  float s0 = 0.f, s1 = 0.f, s2 = 0.f, s3 = 0.f; \
  float s4 = 0.f, s5 = 0.f, s6 = 0.f, s7 = 0.f; \
  mma_acc(s0, s1, s2, s3, aq0, aq1, aq2, aq3, kA.x, kA.y); \
  mma_acc(s4, s5, s6, s7, aq0, aq1, aq2, aq3, kB.x, kB.y); \
  u32 pa0 = hex2(f16x2(s0 + (bl0x), s1 + (bl0y))); \
  u32 pa1 = hex2(f16x2(s2 + (bh0x), s3 + (bh0y))); \
  u32 pa2 = hex2(f16x2(s4 + (bl1x), s5 + (bl1y))); \
  u32 pa3 = hex2(f16x2(s6 + (bh1x), s7 + (bh1y))); \
  uint2 vA = *(const uint2*)(VTlo + (kb)); \
  uint2 vB = *(const uint2*)(VThi + (kb)); \
  mma_acc(D0a, D0b, D0c, D0d, pa0, pa1, pa2, pa3, vA.x, vA.y); \
  mma_acc(D1a, D1b, D1c, D1d, pa0, pa1, pa2, pa3, vB.x, vB.y); \
} while (0)

__global__ void __launch_bounds__(256, 2) attn_kernel(const float* __restrict__ krh,
                                                      const float* __restrict__ krw) {
  extern __shared__ char smem[];
  __half* KS   = (__half*)(smem + KS_OFF);
  __half* VT   = (__half*)(smem + VT_OFF);
  float*  RH   = (float*)(smem + RH_OFF);
  float2* RW2  = (float2*)(smem + RW_OFF);
  float*  KRH  = (float*)(smem + KRH_OFF);
  float*  KRW  = (float*)(smem + KRW_OFF);
  int qt = blockIdx.x, bh = blockIdx.y;
  int tid = threadIdx.x;
  int qbase = qt * 128;

  // stage rel tables + K/V (f16, permuted layouts)
  for (int i = tid; i < 630; i += 256) { KRH[i] = krh[i]; KRW[i] = krw[i]; }
  for (int k = tid; k < 1024; k += 256) {
    const float4* src = (const float4*)(g_KV + (bh * 1024 + k) * 20);
    float4 v0 = src[0], v1 = src[1], v2 = src[2], v3 = src[3], v4 = src[4];
    u32* kw = (u32*)(KS + k * 16);
    kw[0] = f16x2(v0.x, v0.y); kw[1] = f16x2(v2.x, v2.y);
    kw[2] = f16x2(v0.z, v0.w); kw[3] = 0u;
    kw[4] = f16x2(v1.x, v1.y); kw[5] = 0u;
    kw[6] = f16x2(v1.z, v1.w); kw[7] = 0u;
    int wk = k & 15, p = wk >> 1, e = wk & 1;
    int pk = (k & ~15) + ((((((p & 3) << 1) | (p >> 2)) << 1) | e));
    VT[0 * 1032 + pk] = __float2half_rn(v2.z);
    VT[1 * 1032 + pk] = __float2half_rn(v2.w);
    VT[2 * 1032 + pk] = __float2half_rn(v3.x);
    VT[3 * 1032 + pk] = __float2half_rn(v3.y);
    VT[4 * 1032 + pk] = __float2half_rn(v3.z);
    VT[5 * 1032 + pk] = __float2half_rn(v3.w);
    VT[6 * 1032 + pk] = __float2half_rn(v4.x);
    VT[7 * 1032 + pk] = __float2half_rn(v4.y);
    VT[8 * 1032 + pk] = __float2half_rn(v4.z);
    VT[9 * 1032 + pk] = __float2half_rn(v4.w);
    VT[10 * 1032 + pk] = __float2half_rn(1.0f);
    #pragma unroll
    for (int d = 11; d < 16; d++) VT[d * 1032 + pk] = __ushort_as_half(0);
  }
  __syncthreads();

  // per-query relative-bias tables (log2e domain; q pre-scaled)
  {
    int ql = tid >> 1;
    int n = qbase + ql;
    const float* qp = g_Q + (bh * 1024 + n) * 10;
    float q[10];
    #pragma unroll
    for (int i = 0; i < 10; i++) q[i] = qp[i];
    int yq = n >> 5, xq = n & 31;
    if ((tid & 1) == 0) {
      #pragma unroll 4
      for (int ym = 0; ym < 32; ym++) {
        const float* t = KRH + (ym - yq + 31) * 10;
        float s = q[0] * t[0];
        #pragma unroll
        for (int i = 1; i < 10; i++) s = fmaf(q[i], t[i], s);
        RH[ql * 33 + ym] = s;
      }
    } else {
      #pragma unroll 4
      for (int j = 0; j < 16; j++) {
        const float* t0 = KRW + (2 * j - xq + 31) * 10;
        const float* t1 = t0 + 10;
        float s0 = q[0] * t0[0], s1 = q[0] * t1[0];
        #pragma unroll
        for (int i = 1; i < 10; i++) { s0 = fmaf(q[i], t0[i], s0); s1 = fmaf(q[i], t1[i], s1); }
        RW2[ql * 17 + j] = make_float2(s0, s1);
      }
    }
  }

  // Q fragment (from gmem; dims 10-15 zero)
  int lane = tid & 31, w = tid >> 5;
  int r = lane >> 2, c0 = (lane & 3) * 2;
  int ql_lo = w * 16 + r, ql_hi = ql_lo + 8;
  int n_lo = qbase + ql_lo, n_hi = qbase + ql_hi;
  const float* qlo = g_Q + (bh * 1024 + n_lo) * 10;
  const float* qhi = g_Q + (bh * 1024 + n_hi) * 10;
  u32 aq0 = f16x2(qlo[c0], qlo[c0 + 1]);
  u32 aq1 = f16x2(qhi[c0], qhi[c0 + 1]);
  u32 aq2 = (c0 == 0) ? f16x2(qlo[8], qlo[9]) : 0u;
  u32 aq3 = (c0 == 0) ? f16x2(qhi[8], qhi[9]) : 0u;

  __syncthreads();

  const __half* KSr  = KS + r * 16 + 4 * (lane & 3);
  const __half* VTlo = VT + r * 1032 + 4 * (lane & 3);
  const __half* VThi = VT + (r + 8) * 1032 + 4 * (lane & 3);
  const float*  RHlo = RH + ql_lo * 33;
  const float*  RHhi = RH + ql_hi * 33;

  // hoist this thread's 8 RW2 entries into registers
  int l3 = lane & 3;
  const float2* RWlo = RW2 + ql_lo * 17;
  const float2* RWhi = RW2 + ql_hi * 17;
  float2 wla0 = RWlo[l3],      wla1 = RWlo[l3 + 4];    // even chunk
  float2 wlb0 = RWlo[l3 + 8],  wlb1 = RWlo[l3 + 12];   // odd chunk
  float2 wha0 = RWhi[l3],      wha1 = RWhi[l3 + 4];
  float2 whb0 = RWhi[l3 + 8],  whb1 = RWhi[l3 + 12];

  float D0a = 0.f, D0b = 0.f, D0c = 0.f, D0d = 0.f;
  float D1a = 0.f, D1b = 0.f, D1c = 0.f, D1d = 0.f;

  #pragma unroll 4
  for (int ym = 0; ym < 32; ym++) {
    float rhl = RHlo[ym], rhh = RHhi[ym];
    int kb = ym * 32;
    CHUNK(kb,
          rhl + wla0.x, rhl + wla0.y, rhh + wha0.x, rhh + wha0.y,
          rhl + wla1.x, rhl + wla1.y, rhh + wha1.x, rhh + wha1.y);
    CHUNK(kb + 16,
          rhl + wlb0.x, rhl + wlb0.y, rhh + whb0.x, rhh + whb0.y,
          rhl + wlb1.x, rhl + wlb1.y, rhh + whb1.x, rhh + whb1.y);
  }

  // denominators live in D1 col 10 (tile col 2 -> lanes with lane&3==1)
  float l_lo = __shfl_sync(0xffffffffu, D1a, (lane & ~3) | 1);
  float l_hi = __shfl_sync(0xffffffffu, D1c, (lane & ~3) | 1);
  float il = __frcp_rn(l_lo), ih = __frcp_rn(l_hi);

  float* olo = g_attn + (bh * 1024 + n_lo) * 10;
  float* ohi = g_attn + (bh * 1024 + n_hi) * 10;
  *(float2*)(olo + c0) = make_float2(D0a * il, D0b * il);
  *(float2*)(ohi + c0) = make_float2(D0c * ih, D0d * ih);
  if (c0 == 0) {
    *(float2*)(olo + 8) = make_float2(D1a * il, D1b * il);
    *(float2*)(ohi + 8) = make_float2(D1c * ih, D1d * ih);
  }
}

// ---------------- K5: attn means + attno + fc ----------------
__global__ void __launch_bounds__(1024) attnpool_fc_kernel(const float* __restrict__ attno_w,
                                                           const float* __restrict__ attno_b,
                                                           const float* __restrict__ fc_w,
                                                           const float* __restrict__ fc_b,
                                                           float* __restrict__ out) {
  int b = blockIdx.x;
  int tid = threadIdx.x;
  int warp = tid >> 5, lane = tid & 31;
  __shared__ float mean_s[40], pa[40], pooled[88];
  if (tid < 88) pooled[tid] = g_pooled[b * 88 + tid];
  for (int c = warp; c < 40; c += 32) {
    const float* p = g_attn + b * 40960 + c * 1024;
    float s = 0.f;
    #pragma unroll 8
    for (int j = lane; j < 1024; j += 32) s += p[j];
    s = wred(s);
    if (lane == 0) mean_s[c] = s * (1.f / 1024.f);
  }
  __syncthreads();
  if (tid < 40) {
    float acc = __ldg(&attno_b[tid]);
    #pragma unroll 4
    for (int c = 0; c < 40; c++) acc = fmaf(__ldg(&attno_w[tid * 40 + c]), mean_s[c], acc);
    pa[tid] = acc;
  }
  __syncthreads();
  if (tid < 100) {
    float acc = __ldg(&fc_b[tid]);
    const float* wp = fc_w + tid * 128;
    #pragma unroll 4
    for (int c = 0; c < 88; c++) acc = fmaf(__ldg(&wp[c]), pooled[c], acc);
    #pragma unroll 4
    for (int c = 0; c < 40; c++) acc = fmaf(__ldg(&wp[88 + c]), pa[c], acc);
    out[b * 100 + tid] = acc;
  }
}

// ---------------- launch ----------------
extern "C" void kernel_launch(void* const* d_in, const int* in_sizes, int n_in,
                              void* d_out, int out_size) {
  const float* x         = (const float*)d_in[0];
  const float* conv1_w   = (const float*)d_in[1];
  const float* conv1_b   = (const float*)d_in[2];
  const float* bn1_g     = (const float*)d_in[3];
  const float* bn1_b     = (const float*)d_in[4];
  const float* convo_w   = (const float*)d_in[5];
  const float* convo_b   = (const float*)d_in[6];
  const float* qkv_w     = (const float*)d_in[7];
  const float* qkv_b     = (const float*)d_in[8];
  const float* attno_w   = (const float*)d_in[9];
  const float* attno_b   = (const float*)d_in[10];
  const float* key_rel_h = (const float*)d_in[11];
  const float* key_rel_w = (const float*)d_in[12];
  const float* fc_w      = (const float*)d_in[13];
  const float* fc_b      = (const float*)d_in[14];
  float* out = (float*)d_out;

  cudaFuncSetAttribute(attn_kernel, cudaFuncAttributeMaxDynamicSharedMemorySize, ATTN_SMEM_BYTES);

  conv1_kernel<<<dim3(64, 16), 256>>>(x, conv1_w, conv1_b);             // #0
  bnrelu_kernel<<<dim3(64, 16), 1024>>>(bn1_g, bn1_b);                  // #1
  pool_conv_kernel<<<dim3(3, 16), 1024>>>(convo_w, convo_b);            // #2
  qkv_kernel<<<dim3(4, 8, 16), 256>>>(qkv_w, qkv_b);                    // #3 (profiled)
  attn_kernel<<<dim3(8, 64), 256, ATTN_SMEM_BYTES>>>(key_rel_h, key_rel_w);  // #4
  attnpool_fc_kernel<<<16, 1024>>>(attno_w, attno_b, fc_w, fc_b, out);  // #5
}

// round 17
// speedup vs baseline: 2.0512x; 1.0283x over previous
#include <cuda_runtime.h>
#include <cuda_fp16.h>

typedef unsigned long long u64;
typedef unsigned u32;

// ---------------- scratch (device globals; no allocation) ----------------
__device__ float g_pre[16*64*1024];     // conv1 out, then h (in-place)
__device__ float2 g_bstats[64*16];      // per (oc,b) partial {sum, sumsq}
__device__ float g_S[16*64*9];          // 9 shifted window sums per (b, in-ch)
__device__ float g_Q[16*4*1024*10];
__device__ float g_KV[16*4*1024*20];    // interleaved K(10) | V(10) per key
__device__ float g_attn[16*4*1024*10];  // normalized attention output
__device__ float g_pooled[16*88];
__device__ float g_means[16*40];

__device__ __forceinline__ float wred(float v) {
  #pragma unroll
  for (int o = 16; o; o >>= 1) v += __shfl_down_sync(0xffffffffu, v, o);
  return v;
}
// pack two f32 -> f16x2 (lo in low half)
__device__ __forceinline__ u32 f16x2(float lo, float hi) {
  u32 r; asm("cvt.rn.f16x2.f32 %0, %1, %2;" : "=r"(r) : "f"(hi), "f"(lo)); return r;
}
// packed f16x2 ex2
__device__ __forceinline__ u32 hex2(u32 x) {
  u32 y; asm("ex2.approx.f16x2 %0, %1;" : "=r"(y) : "r"(x)); return y;
}
// D += A*B (m16n8k16, f16 in, f32 acc), D/C in-place
__device__ __forceinline__ void mma_acc(float& d0, float& d1, float& d2, float& d3,
                                        u32 a0, u32 a1, u32 a2, u32 a3,
                                        u32 b0, u32 b1) {
  asm volatile(
    "mma.sync.aligned.m16n8k16.row.col.f32.f16.f16.f32 "
    "{%0,%1,%2,%3}, {%4,%5,%6,%7}, {%8,%9}, {%0,%1,%2,%3};"
    : "+f"(d0), "+f"(d1), "+f"(d2), "+f"(d3)
    : "r"(a0), "r"(a1), "r"(a2), "r"(a3), "r"(b0), "r"(b1));
}

// ---------------- K0: conv1 3x3 (3->64) SAME + per-block BN partial stats ----------------
__global__ void __launch_bounds__(256) conv1_kernel(const float* __restrict__ x,
                                                    const float* __restrict__ w,
                                                    const float* __restrict__ bias) {
  int t = threadIdx.x;
  int oc = blockIdx.x, b = blockIdx.y;
  int p0 = t * 4;
  int y = p0 >> 5, x0 = p0 & 31;
  float w_[27];
  #pragma unroll
  for (int i = 0; i < 27; i++) w_[i] = __ldg(&w[oc * 27 + i]);
  float bv = __ldg(&bias[oc]);
  float a0 = bv, a1 = bv, a2 = bv, a3 = bv;
  #pragma unroll
  for (int ic = 0; ic < 3; ic++) {
    const float* base = x + (b * 3 + ic) * 1024;
    #pragma unroll
    for (int ky = 0; ky < 3; ky++) {
      int iy = y + ky - 1;
      if (iy < 0 || iy > 31) continue;
      const float* row = base + iy * 32;
      float r[6];
      #pragma unroll
      for (int dx = 0; dx < 6; dx++) {
        int c = x0 - 1 + dx;
        r[dx] = (c >= 0 && c < 32) ? __ldg(&row[c]) : 0.f;
      }
      #pragma unroll
      for (int kx = 0; kx < 3; kx++) {
        float wv = w_[ic * 9 + ky * 3 + kx];
        a0 = fmaf(wv, r[kx],     a0);
        a1 = fmaf(wv, r[kx + 1], a1);
        a2 = fmaf(wv, r[kx + 2], a2);
        a3 = fmaf(wv, r[kx + 3], a3);
      }
    }
  }
  *(float4*)(g_pre + (b * 64 + oc) * 1024 + p0) = make_float4(a0, a1, a2, a3);

  float s  = a0 + a1 + a2 + a3;
  float sq = fmaf(a0, a0, fmaf(a1, a1, fmaf(a2, a2, a3 * a3)));
  s = wred(s); sq = wred(sq);
  __shared__ float ss[8], s2m[8];
  int warp = t >> 5, lane = t & 31;
  if (lane == 0) { ss[warp] = s; s2m[warp] = sq; }
  __syncthreads();
  if (t == 0) {
    float S = 0.f, Q = 0.f;
    #pragma unroll
    for (int i = 0; i < 8; i++) { S += ss[i]; Q += s2m[i]; }
    g_bstats[oc * 16 + b] = make_float2(S, Q);
  }
}

// ---------------- K1: BN finalize + apply + relu + 9 window sums ----------------
__global__ void bnrelu_kernel(const float* __restrict__ gamma,
                              const float* __restrict__ beta) {
  int c = blockIdx.x, b = blockIdx.y;
  int p = threadIdx.x;                  // 1024 threads
  __shared__ float scb[2];
  if (p < 16) {
    float2 v = g_bstats[c * 16 + p];
    float s = v.x, q = v.y;
    #pragma unroll
    for (int o = 8; o; o >>= 1) {
      s += __shfl_down_sync(0xffffu, s, o, 16);
      q += __shfl_down_sync(0xffffu, q, o, 16);
    }
    if (p == 0) {
      float mean = s * (1.f / 16384.f);
      float var  = q * (1.f / 16384.f) - mean * mean;
      float sc = __ldg(&gamma[c]) * rsqrtf(var + 1e-5f);
      scb[0] = sc;
      scb[1] = __ldg(&beta[c]) - mean * sc;
    }
  }
  __syncthreads();

  int y = p >> 5, xx = p & 31;
  int idx = (b * 64 + c) * 1024 + p;
  float v = fmaxf(fmaf(g_pre[idx], scb[0], scb[1]), 0.f);
  g_pre[idx] = v;

  float t = v;
  float r0  = (y == 0)  ? v : 0.f;
  float r31 = (y == 31) ? v : 0.f;
  float c0  = (xx == 0)  ? v : 0.f;
  float c31 = (xx == 31) ? v : 0.f;

  __shared__ float red[32][5];
  __shared__ float corn[4];
  if (p == 0)    corn[0] = v;
  if (p == 31)   corn[1] = v;
  if (p == 992)  corn[2] = v;
  if (p == 1023) corn[3] = v;

  t = wred(t); r0 = wred(r0); r31 = wred(r31); c0 = wred(c0); c31 = wred(c31);
  int warp = p >> 5, lane = p & 31;
  if (lane == 0) { red[warp][0]=t; red[warp][1]=r0; red[warp][2]=r31; red[warp][3]=c0; red[warp][4]=c31; }
  __syncthreads();
  if (p < 32) {
    float a0 = red[p][0], a1 = red[p][1], a2 = red[p][2], a3 = red[p][3], a4 = red[p][4];
    a0 = wred(a0); a1 = wred(a1); a2 = wred(a2); a3 = wred(a3); a4 = wred(a4);
    if (p == 0) {
      float T = a0, R0 = a1, R31 = a2, C0 = a3, C31 = a4;
      float* Sp = g_S + (b * 64 + c) * 9;
      Sp[0] = T - R31 - C31 + corn[3];
      Sp[1] = T - R31;
      Sp[2] = T - R31 - C0 + corn[2];
      Sp[3] = T - C31;
      Sp[4] = T;
      Sp[5] = T - C0;
      Sp[6] = T - R0 - C31 + corn[1];
      Sp[7] = T - R0;
      Sp[8] = T - R0 - C0 + corn[0];
    }
  }
}

// ---------------- K2: pooled conv_out (depends only on g_S) ----------------
__global__ void __launch_bounds__(1024) pool_conv_kernel(const float* __restrict__ convo_w,
                                                         const float* __restrict__ convo_b) {
  int b = blockIdx.y;
  int tid = threadIdx.x;
  int warp = tid >> 5, lane = tid & 31;
  int task = blockIdx.x * 32 + warp;   // 0..95 (88 used)
  __shared__ float Ssm[576];
  for (int i = tid; i < 576; i += 1024) Ssm[i] = g_S[b * 576 + i];
  __syncthreads();
  if (task < 88) {
    const float* wp = convo_w + task * 576;
    float acc = 0.f;
    #pragma unroll
    for (int i = lane; i < 576; i += 32) acc = fmaf(__ldg(&wp[i]), Ssm[i], acc);
    acc = wred(acc);
    if (lane == 0) g_pooled[b * 88 + task] = __ldg(&convo_b[task]) + acc * (1.f / 1024.f);
  }
}

// ---------------- K3: qkv 1x1 conv, 1 pixel/thread, 128-thr blocks (PROFILED) ----------------
__global__ void __launch_bounds__(128) qkv_kernel(const float* __restrict__ w,
                                                  const float* __restrict__ bias) {
  int tid = threadIdx.x;        // 128
  int n = blockIdx.x * 128 + tid;   // pixel 0..1023
  int b = blockIdx.z;
  int o0 = blockIdx.y * 15;     // 8 groups of 15 output channels
  __shared__ float ws[960];
  __shared__ float bs[15];
  for (int i = tid; i < 960; i += 128) ws[i] = w[o0 * 64 + i];
  if (tid < 15) bs[tid] = bias[o0 + tid];
  __syncthreads();
  float acc[15];
  #pragma unroll
  for (int u = 0; u < 15; u++) acc[u] = bs[u];
  const float* hp = g_pre + b * 65536 + n;
  #pragma unroll 16
  for (int i = 0; i < 64; i++) {
    float hv = hp[i * 1024];
    #pragma unroll
    for (int u = 0; u < 15; u++) acc[u] = fmaf(ws[u * 64 + i], hv, acc[u]);
  }
  const float QMUL = 0.31622776601683794f * 1.4426950408889634f;  // dkh^-.5 * log2e
  #pragma unroll
  for (int u = 0; u < 15; u++) {
    int o = o0 + u;
    int which = o / 40;
    int r = o - which * 40;
    int head = r / 10, d = r - head * 10;
    int bh = b * 4 + head;
    if (which == 0) {
      g_Q[(bh * 1024 + n) * 10 + d] = acc[u] * QMUL;
    } else {
      g_KV[(bh * 1024 + n) * 20 + ((which == 1) ? d : 10 + d)] = acc[u];
    }
  }
}

// ---------------- K4: HMMA attention (mma.sync m16n8k16 f16) ----------------
// CTA: 128 queries (8 warps x 16 rows) x full 1024 keys, per bh. grid (8, 64).
// KS: [1024][16] f16, dims permuted so each B-fragment pair is one 8B load.
// VT: [16][1032] f16, keys permuted within 16-groups; row 10 = ones (denominator).
#define KS_OFF  0
#define VT_OFF  32768
#define RH_OFF  65792
#define RW_OFF  82688
#define KRH_OFF 100096
#define KRW_OFF 102616
#define ATTN_SMEM_BYTES 105136

// one 16-key chunk; f32 bias adds -> f16x2 pack -> packed ex2
#define CHUNK(kb, bl0x, bl0y, bh0x, bh0y, bl1x, bl1y, bh1x, bh1y) do { \
  uint2 kA = *(const uint2*)(KSr + (kb) * 16); \
  uint2 kB = *(const uint2*)(KSr + ((kb) + 8) * 16); \
  float s0 = 0.f, s1 = 0.f, s2 = 0.f, s3 = 0.f; \
  float s4 = 0.f, s5 = 0.f, s6 = 0.f, s7 = 0.f; \
  mma_acc(s0, s1, s2, s3, aq0, aq1, aq2, aq3, kA.x, kA.y); \
  mma_acc(s4, s5, s6, s7, aq0, aq1, aq2, aq3, kB.x, kB.y); \
  u32 pa0 = hex2(f16x2(s0 + (bl0x), s1 + (bl0y))); \
  u32 pa1 = hex2(f16x2(s2 + (bh0x), s3 + (bh0y))); \
  u32 pa2 = hex2(f16x2(s4 + (bl1x), s5 + (bl1y))); \
  u32 pa3 = hex2(f16x2(s6 + (bh1x), s7 + (bh1y))); \
  uint2 vA = *(const uint2*)(VTlo + (kb)); \
  uint2 vB = *(const uint2*)(VThi + (kb)); \
  mma_acc(D0a, D0b, D0c, D0d, pa0, pa1, pa2, pa3, vA.x, vA.y); \
  mma_acc(D1a, D1b, D1c, D1d, pa0, pa1, pa2, pa3, vB.x, vB.y); \
} while (0)

__global__ void __launch_bounds__(256, 2) attn_kernel(const float* __restrict__ krh,
                                                      const float* __restrict__ krw) {
  extern __shared__ char smem[];
  __half* KS   = (__half*)(smem + KS_OFF);
  __half* VT   = (__half*)(smem + VT_OFF);
  float*  RH   = (float*)(smem + RH_OFF);
  float2* RW2  = (float2*)(smem + RW_OFF);
  float*  KRH  = (float*)(smem + KRH_OFF);
  float*  KRW  = (float*)(smem + KRW_OFF);
  int qt = blockIdx.x, bh = blockIdx.y;
  int tid = threadIdx.x;
  int qbase = qt * 128;

  // stage rel tables + K/V (f16, permuted layouts)
  for (int i = tid; i < 630; i += 256) { KRH[i] = krh[i]; KRW[i] = krw[i]; }
  for (int k = tid; k < 1024; k += 256) {
    const float4* src = (const float4*)(g_KV + (bh * 1024 + k) * 20);
    float4 v0 = src[0], v1 = src[1], v2 = src[2], v3 = src[3], v4 = src[4];
    u32* kw = (u32*)(KS + k * 16);
    kw[0] = f16x2(v0.x, v0.y); kw[1] = f16x2(v2.x, v2.y);
    kw[2] = f16x2(v0.z, v0.w); kw[3] = 0u;
    kw[4] = f16x2(v1.x, v1.y); kw[5] = 0u;
    kw[6] = f16x2(v1.z, v1.w); kw[7] = 0u;
    int wk = k & 15, p = wk >> 1, e = wk & 1;
    int pk = (k & ~15) + ((((((p & 3) << 1) | (p >> 2)) << 1) | e));
    VT[0 * 1032 + pk] = __float2half_rn(v2.z);
    VT[1 * 1032 + pk] = __float2half_rn(v2.w);
    VT[2 * 1032 + pk] = __float2half_rn(v3.x);
    VT[3 * 1032 + pk] = __float2half_rn(v3.y);
    VT[4 * 1032 + pk] = __float2half_rn(v3.z);
    VT[5 * 1032 + pk] = __float2half_rn(v3.w);
    VT[6 * 1032 + pk] = __float2half_rn(v4.x);
    VT[7 * 1032 + pk] = __float2half_rn(v4.y);
    VT[8 * 1032 + pk] = __float2half_rn(v4.z);
    VT[9 * 1032 + pk] = __float2half_rn(v4.w);
    VT[10 * 1032 + pk] = __float2half_rn(1.0f);
    #pragma unroll
    for (int d = 11; d < 16; d++) VT[d * 1032 + pk] = __ushort_as_half(0);
  }
  __syncthreads();

  // per-query relative-bias tables (log2e domain; q pre-scaled)
  {
    int ql = tid >> 1;
    int n = qbase + ql;
    const float* qp = g_Q + (bh * 1024 + n) * 10;
    float q[10];
    #pragma unroll
    for (int i = 0; i < 10; i++) q[i] = qp[i];
    int yq = n >> 5, xq = n & 31;
    if ((tid & 1) == 0) {
      #pragma unroll 4
      for (int ym = 0; ym < 32; ym++) {
        const float* t = KRH + (ym - yq + 31) * 10;
        float s = q[0] * t[0];
        #pragma unroll
        for (int i = 1; i < 10; i++) s = fmaf(q[i], t[i], s);
        RH[ql * 33 + ym] = s;
      }
    } else {
      #pragma unroll 4
      for (int j = 0; j < 16; j++) {
        const float* t0 = KRW + (2 * j - xq + 31) * 10;
        const float* t1 = t0 + 10;
        float s0 = q[0] * t0[0], s1 = q[0] * t1[0];
        #pragma unroll
        for (int i = 1; i < 10; i++) { s0 = fmaf(q[i], t0[i], s0); s1 = fmaf(q[i], t1[i], s1); }
        RW2[ql * 17 + j] = make_float2(s0, s1);
      }
    }
  }

  // Q fragment (from gmem; dims 10-15 zero)
  int lane = tid & 31, w = tid >> 5;
  int r = lane >> 2, c0 = (lane & 3) * 2;
  int ql_lo = w * 16 + r, ql_hi = ql_lo + 8;
  int n_lo = qbase + ql_lo, n_hi = qbase + ql_hi;
  const float* qlo = g_Q + (bh * 1024 + n_lo) * 10;
  const float* qhi = g_Q + (bh * 1024 + n_hi) * 10;
  u32 aq0 = f16x2(qlo[c0], qlo[c0 + 1]);
  u32 aq1 = f16x2(qhi[c0], qhi[c0 + 1]);
  u32 aq2 = (c0 == 0) ? f16x2(qlo[8], qlo[9]) : 0u;
  u32 aq3 = (c0 == 0) ? f16x2(qhi[8], qhi[9]) : 0u;

  __syncthreads();

  const __half* KSr  = KS + r * 16 + 4 * (lane & 3);
  const __half* VTlo = VT + r * 1032 + 4 * (lane & 3);
  const __half* VThi = VT + (r + 8) * 1032 + 4 * (lane & 3);
  const float*  RHlo = RH + ql_lo * 33;
  const float*  RHhi = RH + ql_hi * 33;

  // hoist this thread's 8 RW2 entries into registers
  int l3 = lane & 3;
  const float2* RWlo = RW2 + ql_lo * 17;
  const float2* RWhi = RW2 + ql_hi * 17;
  float2 wla0 = RWlo[l3],      wla1 = RWlo[l3 + 4];    // even chunk
  float2 wlb0 = RWlo[l3 + 8],  wlb1 = RWlo[l3 + 12];   // odd chunk
  float2 wha0 = RWhi[l3],      wha1 = RWhi[l3 + 4];
  float2 whb0 = RWhi[l3 + 8],  whb1 = RWhi[l3 + 12];

  float D0a = 0.f, D0b = 0.f, D0c = 0.f, D0d = 0.f;
  float D1a = 0.f, D1b = 0.f, D1c = 0.f, D1d = 0.f;

  #pragma unroll 4
  for (int ym = 0; ym < 32; ym++) {
    float rhl = RHlo[ym], rhh = RHhi[ym];
    int kb = ym * 32;
    CHUNK(kb,
          rhl + wla0.x, rhl + wla0.y, rhh + wha0.x, rhh + wha0.y,
          rhl + wla1.x, rhl + wla1.y, rhh + wha1.x, rhh + wha1.y);
    CHUNK(kb + 16,
          rhl + wlb0.x, rhl + wlb0.y, rhh + whb0.x, rhh + whb0.y,
          rhl + wlb1.x, rhl + wlb1.y, rhh + whb1.x, rhh + whb1.y);
  }

  // denominators live in D1 col 10 (tile col 2 -> lanes with lane&3==1)
  float l_lo = __shfl_sync(0xffffffffu, D1a, (lane & ~3) | 1);
  float l_hi = __shfl_sync(0xffffffffu, D1c, (lane & ~3) | 1);
  float il = __frcp_rn(l_lo), ih = __frcp_rn(l_hi);

  float* olo = g_attn + (bh * 1024 + n_lo) * 10;
  float* ohi = g_attn + (bh * 1024 + n_hi) * 10;
  *(float2*)(olo + c0) = make_float2(D0a * il, D0b * il);
  *(float2*)(ohi + c0) = make_float2(D0c * ih, D0d * ih);
  if (c0 == 0) {
    *(float2*)(olo + 8) = make_float2(D1a * il, D1b * il);
    *(float2*)(ohi + 8) = make_float2(D1c * ih, D1d * ih);
  }
}

// ---------------- K5: attn channel means (block per (c, b)) ----------------
__global__ void __launch_bounds__(256) mean_kernel() {
  int c = blockIdx.x, b = blockIdx.y;
  int tid = threadIdx.x;
  const float* p = g_attn + b * 40960 + c * 1024;
  float s = 0.f;
  #pragma unroll 4
  for (int j = tid; j < 1024; j += 256) s += p[j];
  s = wred(s);
  __shared__ float ps[8];
  int warp = tid >> 5, lane = tid & 31;
  if (lane == 0) ps[warp] = s;
  __syncthreads();
  if (tid == 0) {
    float t = 0.f;
    #pragma unroll
    for (int i = 0; i < 8; i++) t += ps[i];
    g_means[b * 40 + c] = t * (1.f / 1024.f);
  }
}

// ---------------- K6: attno + fc ----------------
__global__ void __launch_bounds__(128) fc_kernel(const float* __restrict__ attno_w,
                                                 const float* __restrict__ attno_b,
                                                 const float* __restrict__ fc_w,
                                                 const float* __restrict__ fc_b,
                                                 float* __restrict__ out) {
  int b = blockIdx.x, tid = threadIdx.x;  // 128
  __shared__ float pooled[88], means[40], pa[40];
  if (tid < 88) pooled[tid] = g_pooled[b * 88 + tid];
  if (tid < 40) means[tid] = g_means[b * 40 + tid];
  __syncthreads();
  if (tid < 40) {
    float acc = __ldg(&attno_b[tid]);
    #pragma unroll 4
    for (int c = 0; c < 40; c++) acc = fmaf(__ldg(&attno_w[tid * 40 + c]), means[c], acc);
    pa[tid] = acc;
  }
  __syncthreads();
  if (tid < 100) {
    float acc = __ldg(&fc_b[tid]);
    const float* wp = fc_w + tid * 128;
    #pragma unroll 4
    for (int c = 0; c < 88; c++) acc = fmaf(__ldg(&wp[c]), pooled[c], acc);
    #pragma unroll 4
    for (int c = 0; c < 40; c++) acc = fmaf(__ldg(&wp[88 + c]), pa[c], acc);
    out[b * 100 + tid] = acc;
  }
}

// ---------------- launch ----------------
extern "C" void kernel_launch(void* const* d_in, const int* in_sizes, int n_in,
                              void* d_out, int out_size) {
  const float* x         = (const float*)d_in[0];
  const float* conv1_w   = (const float*)d_in[1];
  const float* conv1_b   = (const float*)d_in[2];
  const float* bn1_g     = (const float*)d_in[3];
  const float* bn1_b     = (const float*)d_in[4];
  const float* convo_w   = (const float*)d_in[5];
  const float* convo_b   = (const float*)d_in[6];
  const float* qkv_w     = (const float*)d_in[7];
  const float* qkv_b     = (const float*)d_in[8];
  const float* attno_w   = (const float*)d_in[9];
  const float* attno_b   = (const float*)d_in[10];
  const float* key_rel_h = (const float*)d_in[11];
  const float* key_rel_w = (const float*)d_in[12];
  const float* fc_w      = (const float*)d_in[13];
  const float* fc_b      = (const float*)d_in[14];
  float* out = (float*)d_out;

  cudaFuncSetAttribute(attn_kernel, cudaFuncAttributeMaxDynamicSharedMemorySize, ATTN_SMEM_BYTES);

  conv1_kernel<<<dim3(64, 16), 256>>>(x, conv1_w, conv1_b);             // #0
  bnrelu_kernel<<<dim3(64, 16), 1024>>>(bn1_g, bn1_b);                  // #1
  pool_conv_kernel<<<dim3(3, 16), 1024>>>(convo_w, convo_b);            // #2
  qkv_kernel<<<dim3(8, 8, 16), 128>>>(qkv_w, qkv_b);                    // #3 (profiled)
  attn_kernel<<<dim3(8, 64), 256, ATTN_SMEM_BYTES>>>(key_rel_h, key_rel_w);  // #4
  mean_kernel<<<dim3(40, 16), 256>>>();                                 // #5
  fc_kernel<<<16, 128>>>(attno_w, attno_b, fc_w, fc_b, out);            // #6
}